// round 1
// baseline (speedup 1.0000x reference)
#include <cuda_runtime.h>

// Problem constants
#define BATCH 16
#define CCH   512      // C
#define CIN   256      // CI = C/2
#define NUM   1024     // H*W

// ---------------------------------------------------------------------------
// Static device scratch (allocation-free rule: __device__ globals)
// ---------------------------------------------------------------------------
__device__ float d_Abn1[BATCH * CCH * NUM];   // bnrelu1(rgb)   [B, C, num]
__device__ float d_Pbn1[BATCH * CCH * NUM];   // bnrelu1(flow)
__device__ float d_Abn2[BATCH * CCH * NUM];   // bnrelu2(flow)
__device__ float d_Pbn2[BATCH * CCH * NUM];   // bnrelu2(rgb)
__device__ float d_TH[BATCH * CIN * NUM];     // theta  [B, CI, num]
__device__ float d_PH[BATCH * CIN * NUM];     // phi
__device__ float d_G [BATCH * CIN * NUM];     // g
__device__ float d_Y [BATCH * CIN * NUM];     // y
__device__ float d_S [BATCH * NUM * NUM];     // attention logits/probs [B, num, num]

__device__ __forceinline__ float* scratch_ptr(int sel) {
    switch (sel) {
        case 0: return d_Abn1;
        case 1: return d_Pbn1;
        case 2: return d_Abn2;
        case 3: return d_Pbn2;
        case 4: return d_TH;
        case 5: return d_PH;
        case 6: return d_G;
        case 7: return d_Y;
        case 8: return d_S;
    }
    return nullptr;
}

// ---------------------------------------------------------------------------
// BN(eval) + ReLU for both parameter sets, both inputs, in one pass.
// Inputs are [B, C, H, W] with HW=1024 contiguous -> 256 float4 per channel.
// ---------------------------------------------------------------------------
__global__ void bnrelu_kernel(const float4* __restrict__ rgb,
                              const float4* __restrict__ flow,
                              const float* __restrict__ g1, const float* __restrict__ b1,
                              const float* __restrict__ m1, const float* __restrict__ v1,
                              const float* __restrict__ g2, const float* __restrict__ b2,
                              const float* __restrict__ m2, const float* __restrict__ v2)
{
    int i = blockIdx.x * blockDim.x + threadIdx.x;
    if (i >= BATCH * CCH * (NUM / 4)) return;
    int c = (i >> 8) & (CCH - 1);   // (i / 256) % 512

    float s1 = g1[c] / sqrtf(v1[c] + 1e-5f);
    float h1 = b1[c] - m1[c] * s1;
    float s2 = g2[c] / sqrtf(v2[c] + 1e-5f);
    float h2 = b2[c] - m2[c] * s2;

    float4 r = rgb[i];
    float4 f = flow[i];
    float4 o;

    // set 1 applied to rgb -> Abn1
    o.x = fmaxf(fmaf(r.x, s1, h1), 0.f);
    o.y = fmaxf(fmaf(r.y, s1, h1), 0.f);
    o.z = fmaxf(fmaf(r.z, s1, h1), 0.f);
    o.w = fmaxf(fmaf(r.w, s1, h1), 0.f);
    reinterpret_cast<float4*>(d_Abn1)[i] = o;

    // set 1 applied to flow -> Pbn1
    o.x = fmaxf(fmaf(f.x, s1, h1), 0.f);
    o.y = fmaxf(fmaf(f.y, s1, h1), 0.f);
    o.z = fmaxf(fmaf(f.z, s1, h1), 0.f);
    o.w = fmaxf(fmaf(f.w, s1, h1), 0.f);
    reinterpret_cast<float4*>(d_Pbn1)[i] = o;

    // set 2 applied to flow -> Abn2
    o.x = fmaxf(fmaf(f.x, s2, h2), 0.f);
    o.y = fmaxf(fmaf(f.y, s2, h2), 0.f);
    o.z = fmaxf(fmaf(f.z, s2, h2), 0.f);
    o.w = fmaxf(fmaf(f.w, s2, h2), 0.f);
    reinterpret_cast<float4*>(d_Abn2)[i] = o;

    // set 2 applied to rgb -> Pbn2
    o.x = fmaxf(fmaf(r.x, s2, h2), 0.f);
    o.y = fmaxf(fmaf(r.y, s2, h2), 0.f);
    o.z = fmaxf(fmaf(r.z, s2, h2), 0.f);
    o.w = fmaxf(fmaf(r.w, s2, h2), 0.f);
    reinterpret_cast<float4*>(d_Pbn2)[i] = o;
}

// ---------------------------------------------------------------------------
// Generic batched SGEMM:  C[m,n] = sum_k A(k,m) * B(k,n)  (+ bias[m]) (+ res[m,n])
//   TA=false : A stored [K, M] row-major (direct)
//   TA=true  : A stored [M, K] row-major (transpose-load into smem)
//   TB=false : B stored [K, N] row-major (direct)
//   TB=true  : B stored [N, K] row-major (transpose-load into smem)
// Tiles: 128x128x16, 256 threads, 8x8 micro-tile. All dims are multiples of
// tile sizes for this problem -> no bounds checks.
// ---------------------------------------------------------------------------
template <bool TA, bool TB, bool HAS_BIAS, bool HAS_RES>
__global__ __launch_bounds__(256, 2)
void gemm_kernel(const float* Ap, int aSel, const float* Bp, int bSel,
                 const float* __restrict__ bias,
                 const float* resP, int resSel,
                 float* Cp, int cSel,
                 int M, int N, int K,
                 long long sA, long long sB, long long sC, long long sRes)
{
    const float* Ag = (aSel >= 0) ? scratch_ptr(aSel) : Ap;
    const float* Bg = (bSel >= 0) ? scratch_ptr(bSel) : Bp;
    float*       Cg = (cSel >= 0) ? scratch_ptr(cSel) : Cp;
    const float* Rg = nullptr;
    if (HAS_RES) Rg = (resSel >= 0) ? scratch_ptr(resSel) : resP;

    const long long z = blockIdx.z;
    Ag += z * sA;
    Bg += z * sB;
    Cg += z * sC;
    if (HAS_RES) Rg += z * sRes;

    __shared__ float As[16][132];   // row stride 132 floats = 528B (16B aligned)
    __shared__ float Bs[16][132];

    const int m0  = blockIdx.y * 128;
    const int n0  = blockIdx.x * 128;
    const int tid = threadIdx.x;
    const int tx  = tid & 15;
    const int ty  = tid >> 4;

    float acc[8][8];
#pragma unroll
    for (int i = 0; i < 8; i++)
#pragma unroll
        for (int j = 0; j < 8; j++) acc[i][j] = 0.f;

    for (int k0 = 0; k0 < K; k0 += 16) {
        if (!TA) {
            const int kr = tid >> 5;          // 0..7
            const int mc = (tid & 31) << 2;   // 0..124
#pragma unroll
            for (int p = 0; p < 2; p++) {
                const float4 v = *reinterpret_cast<const float4*>(
                    Ag + (long long)(k0 + kr + p * 8) * M + m0 + mc);
                *reinterpret_cast<float4*>(&As[kr + p * 8][mc]) = v;
            }
        } else {
            const int kc = (tid & 3) << 2;    // 0,4,8,12
#pragma unroll
            for (int p = 0; p < 2; p++) {
                const int mr = (tid >> 2) + p * 64;   // 0..127
                const float4 v = *reinterpret_cast<const float4*>(
                    Ag + (long long)(m0 + mr) * K + k0 + kc);
                As[kc + 0][mr] = v.x;
                As[kc + 1][mr] = v.y;
                As[kc + 2][mr] = v.z;
                As[kc + 3][mr] = v.w;
            }
        }
        if (!TB) {
            const int kr = tid >> 5;
            const int nc = (tid & 31) << 2;
#pragma unroll
            for (int p = 0; p < 2; p++) {
                const float4 v = *reinterpret_cast<const float4*>(
                    Bg + (long long)(k0 + kr + p * 8) * N + n0 + nc);
                *reinterpret_cast<float4*>(&Bs[kr + p * 8][nc]) = v;
            }
        } else {
            const int kc = (tid & 3) << 2;
#pragma unroll
            for (int p = 0; p < 2; p++) {
                const int nr = (tid >> 2) + p * 64;
                const float4 v = *reinterpret_cast<const float4*>(
                    Bg + (long long)(n0 + nr) * K + k0 + kc);
                Bs[kc + 0][nr] = v.x;
                Bs[kc + 1][nr] = v.y;
                Bs[kc + 2][nr] = v.z;
                Bs[kc + 3][nr] = v.w;
            }
        }
        __syncthreads();

#pragma unroll
        for (int k = 0; k < 16; k++) {
            float ra[8], rb[8];
#pragma unroll
            for (int i = 0; i < 8; i++) ra[i] = As[k][ty * 8 + i];
#pragma unroll
            for (int j = 0; j < 8; j++) rb[j] = Bs[k][tx * 8 + j];
#pragma unroll
            for (int i = 0; i < 8; i++)
#pragma unroll
                for (int j = 0; j < 8; j++)
                    acc[i][j] = fmaf(ra[i], rb[j], acc[i][j]);
        }
        __syncthreads();
    }

#pragma unroll
    for (int i = 0; i < 8; i++) {
        const int m = m0 + ty * 8 + i;
        const float bv = HAS_BIAS ? bias[m] : 0.f;
#pragma unroll
        for (int j = 0; j < 8; j += 4) {
            const int n = n0 + tx * 8 + j;
            float4 v;
            v.x = acc[i][j + 0] + bv;
            v.y = acc[i][j + 1] + bv;
            v.z = acc[i][j + 2] + bv;
            v.w = acc[i][j + 3] + bv;
            if (HAS_RES) {
                const float4 r = *reinterpret_cast<const float4*>(
                    Rg + (long long)m * N + n);
                v.x += r.x; v.y += r.y; v.z += r.z; v.w += r.w;
            }
            *reinterpret_cast<float4*>(Cg + (long long)m * N + n) = v;
        }
    }
}

// ---------------------------------------------------------------------------
// Row softmax over d_S: 16384 rows of 1024. One 128-thread block per row,
// 8 elements per thread held in registers.
// ---------------------------------------------------------------------------
__global__ void softmax_kernel()
{
    float* row = d_S + (long long)blockIdx.x * NUM;
    const int t = threadIdx.x;

    float v[8];
    float mx = -1e30f;
#pragma unroll
    for (int i = 0; i < 8; i++) {
        v[i] = row[t + i * 128];
        mx = fmaxf(mx, v[i]);
    }

    __shared__ float red[128];
    red[t] = mx;
    __syncthreads();
#pragma unroll
    for (int s = 64; s > 0; s >>= 1) {
        if (t < s) red[t] = fmaxf(red[t], red[t + s]);
        __syncthreads();
    }
    mx = red[0];
    __syncthreads();

    float sum = 0.f;
#pragma unroll
    for (int i = 0; i < 8; i++) {
        v[i] = expf(v[i] - mx);
        sum += v[i];
    }
    red[t] = sum;
    __syncthreads();
#pragma unroll
    for (int s = 64; s > 0; s >>= 1) {
        if (t < s) red[t] += red[t + s];
        __syncthreads();
    }
    const float inv = 1.0f / red[0];
#pragma unroll
    for (int i = 0; i < 8; i++) row[t + i * 128] = v[i] * inv;
}

// ---------------------------------------------------------------------------
// Launcher. Input order (metadata):
//  0 rgb_cm, 1 flow_cm,
//  2..13  : bn1_g,b,m,v, th1_w,th1_b, ph1_w,ph1_b, g1_w,g1_b, w1_w,w1_b
// 14..25  : same for set 2
// Output: att_rgb [16,512,32,32] then att_flow [16,512,32,32]
// ---------------------------------------------------------------------------
extern "C" void kernel_launch(void* const* d_in, const int* in_sizes, int n_in,
                              void* d_out, int out_size)
{
    const float4* rgb  = reinterpret_cast<const float4*>(d_in[0]);
    const float4* flow = reinterpret_cast<const float4*>(d_in[1]);

    bnrelu_kernel<<<(BATCH * CCH * (NUM / 4)) / 256, 256>>>(
        rgb, flow,
        (const float*)d_in[2],  (const float*)d_in[3],
        (const float*)d_in[4],  (const float*)d_in[5],
        (const float*)d_in[14], (const float*)d_in[15],
        (const float*)d_in[16], (const float*)d_in[17]);

    const long long sX  = (long long)CCH * NUM;   // 512*1024  per-batch stride of bnrelu'd input
    const long long sP  = (long long)CIN * NUM;   // 256*1024  per-batch stride of projections
    const long long sS  = (long long)NUM * NUM;   // 1024*1024 per-batch stride of attention
    const long long sO  = (long long)CCH * NUM;   // output per-batch stride

    for (int blk = 0; blk < 2; blk++) {
        const int o = blk ? 14 : 2;
        const float* thw = (const float*)d_in[o + 4];
        const float* thb = (const float*)d_in[o + 5];
        const float* phw = (const float*)d_in[o + 6];
        const float* phb = (const float*)d_in[o + 7];
        const float* gw  = (const float*)d_in[o + 8];
        const float* gb  = (const float*)d_in[o + 9];
        const float* ww  = (const float*)d_in[o + 10];
        const float* wb  = (const float*)d_in[o + 11];

        const int ABN = blk ? 2 : 0;   // bnrelu'd "A" stream (residual source too)
        const int PBN = blk ? 3 : 1;   // bnrelu'd "B" stream

        // theta = th_w @ Abn + th_b      [CI, num] = [256,512] @ [512,1024]
        gemm_kernel<true, false, true, false><<<dim3(8, 2, BATCH), 256>>>(
            thw, -1, nullptr, ABN, thb, nullptr, -1, nullptr, 4,
            CIN, NUM, CCH, 0, sX, sP, 0);
        // phi = ph_w @ Pbn + ph_b
        gemm_kernel<true, false, true, false><<<dim3(8, 2, BATCH), 256>>>(
            phw, -1, nullptr, PBN, phb, nullptr, -1, nullptr, 5,
            CIN, NUM, CCH, 0, sX, sP, 0);
        // g = g_w @ Abn + g_b
        gemm_kernel<true, false, true, false><<<dim3(8, 2, BATCH), 256>>>(
            gw, -1, nullptr, ABN, gb, nullptr, -1, nullptr, 6,
            CIN, NUM, CCH, 0, sX, sP, 0);

        // S[n,m] = sum_ci TH[ci,n] * PH[ci,m]   (both operands direct [K,*])
        gemm_kernel<false, false, false, false><<<dim3(8, 8, BATCH), 256>>>(
            nullptr, 4, nullptr, 5, nullptr, nullptr, -1, nullptr, 8,
            NUM, NUM, CIN, sP, sP, sS, 0);

        softmax_kernel<<<BATCH * NUM, 128>>>();

        // Y[ci,n] = sum_m G[ci,m] * S[n,m]   (A trans [M,K], B trans [N,K])
        gemm_kernel<true, true, false, false><<<dim3(8, 2, BATCH), 256>>>(
            nullptr, 6, nullptr, 8, nullptr, nullptr, -1, nullptr, 7,
            CIN, NUM, NUM, sP, sS, sP, 0);

        // out[c,n] = Abn[c,n] + w_b[c] + sum_ci w_w[c,ci] * Y[ci,n]
        float* outp = (float*)d_out + (long long)blk * BATCH * CCH * NUM;
        gemm_kernel<true, false, true, true><<<dim3(8, 4, BATCH), 256>>>(
            ww, -1, nullptr, 7, wb, nullptr, ABN, outp, -1,
            CCH, NUM, CIN, 0, sP, sO, sO);
    }
}

// round 2
// speedup vs baseline: 1.5265x; 1.5265x over previous
#include <cuda_runtime.h>
#include <cstdint>

// Problem constants
#define BATCH 16
#define CCH   512      // C
#define CIN   256      // CI = C/2
#define NUM   1024     // H*W

// ---------------------------------------------------------------------------
// Static device scratch (allocation-free rule: __device__ globals)
// ---------------------------------------------------------------------------
__device__ float d_Abn1[BATCH * CCH * NUM];
__device__ float d_Pbn1[BATCH * CCH * NUM];
__device__ float d_Abn2[BATCH * CCH * NUM];
__device__ float d_Pbn2[BATCH * CCH * NUM];
__device__ float d_TH[BATCH * CIN * NUM];
__device__ float d_PH[BATCH * CIN * NUM];
__device__ float d_G [BATCH * CIN * NUM];
__device__ float d_Y [BATCH * CIN * NUM];
__device__ float d_S [BATCH * NUM * NUM];

__device__ __forceinline__ float* scratch_ptr(int sel) {
    switch (sel) {
        case 0: return d_Abn1;
        case 1: return d_Pbn1;
        case 2: return d_Abn2;
        case 3: return d_Pbn2;
        case 4: return d_TH;
        case 5: return d_PH;
        case 6: return d_G;
        case 7: return d_Y;
        case 8: return d_S;
    }
    return nullptr;
}

// ---------------------------------------------------------------------------
// BN(eval) + ReLU, both parameter sets, both inputs, one pass.
// ---------------------------------------------------------------------------
__global__ void bnrelu_kernel(const float4* __restrict__ rgb,
                              const float4* __restrict__ flow,
                              const float* __restrict__ g1, const float* __restrict__ b1,
                              const float* __restrict__ m1, const float* __restrict__ v1,
                              const float* __restrict__ g2, const float* __restrict__ b2,
                              const float* __restrict__ m2, const float* __restrict__ v2)
{
    int i = blockIdx.x * blockDim.x + threadIdx.x;
    if (i >= BATCH * CCH * (NUM / 4)) return;
    int c = (i >> 8) & (CCH - 1);

    float s1 = g1[c] / sqrtf(v1[c] + 1e-5f);
    float h1 = b1[c] - m1[c] * s1;
    float s2 = g2[c] / sqrtf(v2[c] + 1e-5f);
    float h2 = b2[c] - m2[c] * s2;

    float4 r = rgb[i];
    float4 f = flow[i];
    float4 o;

    o.x = fmaxf(fmaf(r.x, s1, h1), 0.f);
    o.y = fmaxf(fmaf(r.y, s1, h1), 0.f);
    o.z = fmaxf(fmaf(r.z, s1, h1), 0.f);
    o.w = fmaxf(fmaf(r.w, s1, h1), 0.f);
    reinterpret_cast<float4*>(d_Abn1)[i] = o;

    o.x = fmaxf(fmaf(f.x, s1, h1), 0.f);
    o.y = fmaxf(fmaf(f.y, s1, h1), 0.f);
    o.z = fmaxf(fmaf(f.z, s1, h1), 0.f);
    o.w = fmaxf(fmaf(f.w, s1, h1), 0.f);
    reinterpret_cast<float4*>(d_Pbn1)[i] = o;

    o.x = fmaxf(fmaf(f.x, s2, h2), 0.f);
    o.y = fmaxf(fmaf(f.y, s2, h2), 0.f);
    o.z = fmaxf(fmaf(f.z, s2, h2), 0.f);
    o.w = fmaxf(fmaf(f.w, s2, h2), 0.f);
    reinterpret_cast<float4*>(d_Abn2)[i] = o;

    o.x = fmaxf(fmaf(r.x, s2, h2), 0.f);
    o.y = fmaxf(fmaf(r.y, s2, h2), 0.f);
    o.z = fmaxf(fmaf(r.z, s2, h2), 0.f);
    o.w = fmaxf(fmaf(r.w, s2, h2), 0.f);
    reinterpret_cast<float4*>(d_Pbn2)[i] = o;
}

// ---------------------------------------------------------------------------
// tf32 mma helpers
// ---------------------------------------------------------------------------
__device__ __forceinline__ uint32_t cvt_tf32(float x) {
    uint32_t r;
    asm("cvt.rna.tf32.f32 %0, %1;" : "=r"(r) : "f"(x));
    return r;
}

__device__ __forceinline__ void mma_tf32(float c[4], const uint32_t a[4],
                                         uint32_t b0, uint32_t b1) {
    asm volatile(
        "mma.sync.aligned.m16n8k8.row.col.f32.tf32.tf32.f32 "
        "{%0,%1,%2,%3}, {%4,%5,%6,%7}, {%8,%9}, {%0,%1,%2,%3};"
        : "+f"(c[0]), "+f"(c[1]), "+f"(c[2]), "+f"(c[3])
        : "r"(a[0]), "r"(a[1]), "r"(a[2]), "r"(a[3]), "r"(b0), "r"(b1));
}

// ---------------------------------------------------------------------------
// Batched tf32-MMA GEMM:  C[m,n] = sum_k A(k,m) * B(k,n)  (+bias[m]) (+res)
//   TA=false: A stored [K,M] (direct)    TA=true: A stored [M,K] (transpose-load)
//   TB=false: B stored [K,N] (direct)    TB=true: B stored [N,K] (transpose-load)
// NSPLIT=1: plain tf32.  NSPLIT=3: hi/lo split (~fp32 accuracy).
// CTA tile 128x128x16, 8 warps, warp tile 32(m) x 64(n), mma m16n8k8.
// Double-buffered smem with register prefetch. Dims multiples of tile sizes.
// ---------------------------------------------------------------------------
#define SMS 136   // smem row stride in floats (k-major rows): 136 % 32 == 8

template <bool TA, bool TB, bool HAS_BIAS, bool HAS_RES, int NSPLIT>
__global__ __launch_bounds__(256)
void mma_gemm(const float* Ap, int aSel, const float* Bp, int bSel,
              const float* __restrict__ bias,
              const float* resP, int resSel,
              float* Cp, int cSel,
              int M, int N, int K,
              long long sA, long long sB, long long sC, long long sRes)
{
    const float* Ag = (aSel >= 0) ? scratch_ptr(aSel) : Ap;
    const float* Bg = (bSel >= 0) ? scratch_ptr(bSel) : Bp;
    float*       Cg = (cSel >= 0) ? scratch_ptr(cSel) : Cp;
    const float* Rg = nullptr;
    if (HAS_RES) Rg = (resSel >= 0) ? scratch_ptr(resSel) : resP;

    const long long z = blockIdx.z;
    Ag += z * sA;  Bg += z * sB;  Cg += z * sC;
    if (HAS_RES) Rg += z * sRes;

    __shared__ float As[2][16][SMS];
    __shared__ float Bs[2][16][SMS];

    const int m0   = blockIdx.y * 128;
    const int n0   = blockIdx.x * 128;
    const int tid  = threadIdx.x;
    const int lane = tid & 31;
    const int warp = tid >> 5;
    const int grp  = lane >> 2;   // 0..7
    const int tig  = lane & 3;    // 0..3
    const int wm   = warp & 3;    // 4 m-tiles of 32
    const int wn   = warp >> 2;   // 2 n-tiles of 64

    float acc[2][8][4];
#pragma unroll
    for (int i = 0; i < 2; i++)
#pragma unroll
        for (int j = 0; j < 8; j++)
#pragma unroll
            for (int q = 0; q < 4; q++) acc[i][j][q] = 0.f;

    float4 pa[2], pb[2];

    auto ldgA = [&](int k0) {
        if (!TA) {
            const int kr = tid >> 5;
            const int mc = (tid & 31) << 2;
            pa[0] = *reinterpret_cast<const float4*>(Ag + (long long)(k0 + kr) * M + m0 + mc);
            pa[1] = *reinterpret_cast<const float4*>(Ag + (long long)(k0 + kr + 8) * M + m0 + mc);
        } else {
            const int kc = (tid & 3) << 2;
            const int mr = tid >> 2;
            pa[0] = *reinterpret_cast<const float4*>(Ag + (long long)(m0 + mr) * K + k0 + kc);
            pa[1] = *reinterpret_cast<const float4*>(Ag + (long long)(m0 + mr + 64) * K + k0 + kc);
        }
    };
    auto ldgB = [&](int k0) {
        if (!TB) {
            const int kr = tid >> 5;
            const int nc = (tid & 31) << 2;
            pb[0] = *reinterpret_cast<const float4*>(Bg + (long long)(k0 + kr) * N + n0 + nc);
            pb[1] = *reinterpret_cast<const float4*>(Bg + (long long)(k0 + kr + 8) * N + n0 + nc);
        } else {
            const int kc = (tid & 3) << 2;
            const int nr = tid >> 2;
            pb[0] = *reinterpret_cast<const float4*>(Bg + (long long)(n0 + nr) * K + k0 + kc);
            pb[1] = *reinterpret_cast<const float4*>(Bg + (long long)(n0 + nr + 64) * K + k0 + kc);
        }
    };
    auto stsA = [&](int buf) {
        if (!TA) {
            const int kr = tid >> 5;
            const int mc = (tid & 31) << 2;
            *reinterpret_cast<float4*>(&As[buf][kr][mc])     = pa[0];
            *reinterpret_cast<float4*>(&As[buf][kr + 8][mc]) = pa[1];
        } else {
            const int kc = (tid & 3) << 2;
            const int mr = tid >> 2;
            As[buf][kc + 0][mr] = pa[0].x;  As[buf][kc + 1][mr] = pa[0].y;
            As[buf][kc + 2][mr] = pa[0].z;  As[buf][kc + 3][mr] = pa[0].w;
            As[buf][kc + 0][mr + 64] = pa[1].x;  As[buf][kc + 1][mr + 64] = pa[1].y;
            As[buf][kc + 2][mr + 64] = pa[1].z;  As[buf][kc + 3][mr + 64] = pa[1].w;
        }
    };
    auto stsB = [&](int buf) {
        if (!TB) {
            const int kr = tid >> 5;
            const int nc = (tid & 31) << 2;
            *reinterpret_cast<float4*>(&Bs[buf][kr][nc])     = pb[0];
            *reinterpret_cast<float4*>(&Bs[buf][kr + 8][nc]) = pb[1];
        } else {
            const int kc = (tid & 3) << 2;
            const int nr = tid >> 2;
            Bs[buf][kc + 0][nr] = pb[0].x;  Bs[buf][kc + 1][nr] = pb[0].y;
            Bs[buf][kc + 2][nr] = pb[0].z;  Bs[buf][kc + 3][nr] = pb[0].w;
            Bs[buf][kc + 0][nr + 64] = pb[1].x;  Bs[buf][kc + 1][nr + 64] = pb[1].y;
            Bs[buf][kc + 2][nr + 64] = pb[1].z;  Bs[buf][kc + 3][nr + 64] = pb[1].w;
        }
    };

    // Prologue
    ldgA(0); ldgB(0);
    stsA(0); stsB(0);
    __syncthreads();

    const int nstage = K >> 4;
    for (int ks = 0; ks < nstage; ks++) {
        const int buf = ks & 1;
        const bool more = (ks + 1 < nstage);
        if (more) { ldgA((ks + 1) << 4); ldgB((ks + 1) << 4); }

#pragma unroll
        for (int kk = 0; kk < 2; kk++) {
            const int kA = kk * 8 + tig;     // rows k and k+4 used
            // A fragments (2 m-subtiles of 16)
            uint32_t ah[2][4], al[2][4];
#pragma unroll
            for (int i = 0; i < 2; i++) {
                const int mb = wm * 32 + i * 16 + grp;
                float f0 = As[buf][kA][mb];
                float f1 = As[buf][kA][mb + 8];
                float f2 = As[buf][kA + 4][mb];
                float f3 = As[buf][kA + 4][mb + 8];
                ah[i][0] = cvt_tf32(f0);
                ah[i][1] = cvt_tf32(f1);
                ah[i][2] = cvt_tf32(f2);
                ah[i][3] = cvt_tf32(f3);
                if (NSPLIT == 3) {
                    al[i][0] = cvt_tf32(f0 - __uint_as_float(ah[i][0]));
                    al[i][1] = cvt_tf32(f1 - __uint_as_float(ah[i][1]));
                    al[i][2] = cvt_tf32(f2 - __uint_as_float(ah[i][2]));
                    al[i][3] = cvt_tf32(f3 - __uint_as_float(ah[i][3]));
                }
            }
#pragma unroll
            for (int j = 0; j < 8; j++) {
                const int nb = wn * 64 + j * 8 + grp;
                float fb0 = Bs[buf][kA][nb];
                float fb1 = Bs[buf][kA + 4][nb];
                uint32_t bh0 = cvt_tf32(fb0);
                uint32_t bh1 = cvt_tf32(fb1);
#pragma unroll
                for (int i = 0; i < 2; i++)
                    mma_tf32(acc[i][j], ah[i], bh0, bh1);
                if (NSPLIT == 3) {
                    uint32_t bl0 = cvt_tf32(fb0 - __uint_as_float(bh0));
                    uint32_t bl1 = cvt_tf32(fb1 - __uint_as_float(bh1));
#pragma unroll
                    for (int i = 0; i < 2; i++) {
                        mma_tf32(acc[i][j], ah[i], bl0, bl1);
                        mma_tf32(acc[i][j], al[i], bh0, bh1);
                    }
                }
            }
        }

        if (more) { stsA(buf ^ 1); stsB(buf ^ 1); }
        __syncthreads();
    }

    // Epilogue: c0:(grp, tig*2) c1:(grp, tig*2+1) c2:(grp+8, ...) c3
#pragma unroll
    for (int i = 0; i < 2; i++) {
#pragma unroll
        for (int h = 0; h < 2; h++) {
            const int m = m0 + wm * 32 + i * 16 + grp + h * 8;
            const float bv = HAS_BIAS ? bias[m] : 0.f;
#pragma unroll
            for (int j = 0; j < 8; j++) {
                const int n = n0 + wn * 64 + j * 8 + tig * 2;
                float2 v;
                v.x = acc[i][j][h * 2 + 0] + bv;
                v.y = acc[i][j][h * 2 + 1] + bv;
                if (HAS_RES) {
                    const float2 r = *reinterpret_cast<const float2*>(
                        Rg + (long long)m * N + n);
                    v.x += r.x;  v.y += r.y;
                }
                *reinterpret_cast<float2*>(Cg + (long long)m * N + n) = v;
            }
        }
    }
}

// ---------------------------------------------------------------------------
// Row softmax over d_S: 16384 rows of 1024.
// ---------------------------------------------------------------------------
__global__ void softmax_kernel()
{
    float* row = d_S + (long long)blockIdx.x * NUM;
    const int t = threadIdx.x;

    float v[8];
    float mx = -1e30f;
#pragma unroll
    for (int i = 0; i < 8; i++) {
        v[i] = row[t + i * 128];
        mx = fmaxf(mx, v[i]);
    }

    __shared__ float red[128];
    red[t] = mx;
    __syncthreads();
#pragma unroll
    for (int s = 64; s > 0; s >>= 1) {
        if (t < s) red[t] = fmaxf(red[t], red[t + s]);
        __syncthreads();
    }
    mx = red[0];
    __syncthreads();

    float sum = 0.f;
#pragma unroll
    for (int i = 0; i < 8; i++) {
        v[i] = expf(v[i] - mx);
        sum += v[i];
    }
    red[t] = sum;
    __syncthreads();
#pragma unroll
    for (int s = 64; s > 0; s >>= 1) {
        if (t < s) red[t] += red[t + s];
        __syncthreads();
    }
    const float inv = 1.0f / red[0];
#pragma unroll
    for (int i = 0; i < 8; i++) row[t + i * 128] = v[i] * inv;
}

// ---------------------------------------------------------------------------
// Launcher
// ---------------------------------------------------------------------------
extern "C" void kernel_launch(void* const* d_in, const int* in_sizes, int n_in,
                              void* d_out, int out_size)
{
    const float4* rgb  = reinterpret_cast<const float4*>(d_in[0]);
    const float4* flow = reinterpret_cast<const float4*>(d_in[1]);

    bnrelu_kernel<<<(BATCH * CCH * (NUM / 4)) / 256, 256>>>(
        rgb, flow,
        (const float*)d_in[2],  (const float*)d_in[3],
        (const float*)d_in[4],  (const float*)d_in[5],
        (const float*)d_in[14], (const float*)d_in[15],
        (const float*)d_in[16], (const float*)d_in[17]);

    const long long sX = (long long)CCH * NUM;
    const long long sP = (long long)CIN * NUM;
    const long long sS = (long long)NUM * NUM;
    const long long sO = (long long)CCH * NUM;

    for (int blk = 0; blk < 2; blk++) {
        const int o = blk ? 14 : 2;
        const float* thw = (const float*)d_in[o + 4];
        const float* thb = (const float*)d_in[o + 5];
        const float* phw = (const float*)d_in[o + 6];
        const float* phb = (const float*)d_in[o + 7];
        const float* gw  = (const float*)d_in[o + 8];
        const float* gb  = (const float*)d_in[o + 9];
        const float* ww  = (const float*)d_in[o + 10];
        const float* wb  = (const float*)d_in[o + 11];

        const int ABN = blk ? 2 : 0;
        const int PBN = blk ? 3 : 1;

        // theta = th_w @ Abn + th_b   [256,1024], K=512  (3x split: pre-softmax)
        mma_gemm<true, false, true, false, 3><<<dim3(8, 2, BATCH), 256>>>(
            thw, -1, nullptr, ABN, thb, nullptr, -1, nullptr, 4,
            CIN, NUM, CCH, 0, sX, sP, 0);
        // phi = ph_w @ Pbn + ph_b   (3x split)
        mma_gemm<true, false, true, false, 3><<<dim3(8, 2, BATCH), 256>>>(
            phw, -1, nullptr, PBN, phb, nullptr, -1, nullptr, 5,
            CIN, NUM, CCH, 0, sX, sP, 0);
        // g = g_w @ Abn + g_b   (1x: post-softmax linear path)
        mma_gemm<true, false, true, false, 1><<<dim3(8, 2, BATCH), 256>>>(
            gw, -1, nullptr, ABN, gb, nullptr, -1, nullptr, 6,
            CIN, NUM, CCH, 0, sX, sP, 0);

        // S[n,m] = sum_ci TH[ci,n] * PH[ci,m]   (3x split: logits)
        mma_gemm<false, false, false, false, 3><<<dim3(8, 8, BATCH), 256>>>(
            nullptr, 4, nullptr, 5, nullptr, nullptr, -1, nullptr, 8,
            NUM, NUM, CIN, sP, sP, sS, 0);

        softmax_kernel<<<BATCH * NUM, 128>>>();

        // Y[ci,n] = sum_m G[ci,m] * P[n,m]   (1x)
        mma_gemm<true, true, false, false, 1><<<dim3(8, 2, BATCH), 256>>>(
            nullptr, 6, nullptr, 8, nullptr, nullptr, -1, nullptr, 7,
            CIN, NUM, NUM, sP, sS, sP, 0);

        // out[c,n] = Abn[c,n] + w_b[c] + w_w @ Y   (1x)
        float* outp = (float*)d_out + (long long)blk * BATCH * CCH * NUM;
        mma_gemm<true, false, true, true, 1><<<dim3(8, 4, BATCH), 256>>>(
            ww, -1, nullptr, 7, wb, nullptr, ABN, outp, -1,
            CCH, NUM, CIN, 0, sP, sO, sO);
    }
}

// round 3
// speedup vs baseline: 2.0322x; 1.3313x over previous
#include <cuda_runtime.h>
#include <cuda_bf16.h>
#include <cstdint>

// Problem constants
#define BATCH 16
#define CCH   512      // C
#define CIN   256      // CI = C/2
#define NUM   1024     // H*W

// ---------------------------------------------------------------------------
// Static device scratch
// ---------------------------------------------------------------------------
__device__ float d_Abn1[BATCH * CCH * NUM];
__device__ float d_Pbn1[BATCH * CCH * NUM];
__device__ float d_Abn2[BATCH * CCH * NUM];
__device__ float d_Pbn2[BATCH * CCH * NUM];
__device__ float d_TH[BATCH * CIN * NUM];
__device__ float d_PH[BATCH * CIN * NUM];
__device__ float d_G [BATCH * CIN * NUM];
__device__ float d_Y [BATCH * CIN * NUM];
__device__ float d_S [BATCH * NUM * NUM];

__device__ __forceinline__ float* scratch_ptr(int sel) {
    switch (sel) {
        case 0: return d_Abn1;
        case 1: return d_Pbn1;
        case 2: return d_Abn2;
        case 3: return d_Pbn2;
        case 4: return d_TH;
        case 5: return d_PH;
        case 6: return d_G;
        case 7: return d_Y;
        case 8: return d_S;
    }
    return nullptr;
}

// ---------------------------------------------------------------------------
// BN(eval) + ReLU, both parameter sets, both inputs, one pass.
// ---------------------------------------------------------------------------
__global__ void bnrelu_kernel(const float4* __restrict__ rgb,
                              const float4* __restrict__ flow,
                              const float* __restrict__ g1, const float* __restrict__ b1,
                              const float* __restrict__ m1, const float* __restrict__ v1,
                              const float* __restrict__ g2, const float* __restrict__ b2,
                              const float* __restrict__ m2, const float* __restrict__ v2)
{
    int i = blockIdx.x * blockDim.x + threadIdx.x;
    if (i >= BATCH * CCH * (NUM / 4)) return;
    int c = (i >> 8) & (CCH - 1);

    float s1 = g1[c] / sqrtf(v1[c] + 1e-5f);
    float h1 = b1[c] - m1[c] * s1;
    float s2 = g2[c] / sqrtf(v2[c] + 1e-5f);
    float h2 = b2[c] - m2[c] * s2;

    float4 r = rgb[i];
    float4 f = flow[i];
    float4 o;

    o.x = fmaxf(fmaf(r.x, s1, h1), 0.f);
    o.y = fmaxf(fmaf(r.y, s1, h1), 0.f);
    o.z = fmaxf(fmaf(r.z, s1, h1), 0.f);
    o.w = fmaxf(fmaf(r.w, s1, h1), 0.f);
    reinterpret_cast<float4*>(d_Abn1)[i] = o;

    o.x = fmaxf(fmaf(f.x, s1, h1), 0.f);
    o.y = fmaxf(fmaf(f.y, s1, h1), 0.f);
    o.z = fmaxf(fmaf(f.z, s1, h1), 0.f);
    o.w = fmaxf(fmaf(f.w, s1, h1), 0.f);
    reinterpret_cast<float4*>(d_Pbn1)[i] = o;

    o.x = fmaxf(fmaf(f.x, s2, h2), 0.f);
    o.y = fmaxf(fmaf(f.y, s2, h2), 0.f);
    o.z = fmaxf(fmaf(f.z, s2, h2), 0.f);
    o.w = fmaxf(fmaf(f.w, s2, h2), 0.f);
    reinterpret_cast<float4*>(d_Abn2)[i] = o;

    o.x = fmaxf(fmaf(r.x, s2, h2), 0.f);
    o.y = fmaxf(fmaf(r.y, s2, h2), 0.f);
    o.z = fmaxf(fmaf(r.z, s2, h2), 0.f);
    o.w = fmaxf(fmaf(r.w, s2, h2), 0.f);
    reinterpret_cast<float4*>(d_Pbn2)[i] = o;
}

// ---------------------------------------------------------------------------
// bf16 split helpers: x = hi + lo (+ O(2^-18)); pack (even_k, odd_k) pairs.
// ---------------------------------------------------------------------------
__device__ __forceinline__ void split_pack(float a, float b,
                                           uint32_t& hi, uint32_t& lo)
{
    __nv_bfloat16 ha = __float2bfloat16_rn(a);
    __nv_bfloat16 hb = __float2bfloat16_rn(b);
    float ra = a - __bfloat162float(ha);
    float rb = b - __bfloat162float(hb);
    __nv_bfloat16 la = __float2bfloat16_rn(ra);
    __nv_bfloat16 lb = __float2bfloat16_rn(rb);
    __nv_bfloat162 hp; hp.x = ha; hp.y = hb;   // .x = low 16 bits = even k
    __nv_bfloat162 lp; lp.x = la; lp.y = lb;
    hi = *reinterpret_cast<uint32_t*>(&hp);
    lo = *reinterpret_cast<uint32_t*>(&lp);
}

__device__ __forceinline__ void mma16816(float c[4], const uint32_t a[4],
                                         uint32_t b0, uint32_t b1)
{
    asm volatile(
        "mma.sync.aligned.m16n8k16.row.col.f32.bf16.bf16.f32 "
        "{%0,%1,%2,%3}, {%4,%5,%6,%7}, {%8,%9}, {%0,%1,%2,%3};"
        : "+f"(c[0]), "+f"(c[1]), "+f"(c[2]), "+f"(c[3])
        : "r"(a[0]), "r"(a[1]), "r"(a[2]), "r"(a[3]), "r"(b0), "r"(b1));
}

// ---------------------------------------------------------------------------
// Batched bf16-split MMA GEMM:  C[m,n] = sum_k A(k,m)*B(k,n) (+bias[m]) (+res)
//   TA/TB flag the stored layout as in previous rounds.
// CTA tile 128x128x16, 8 warps (wm 4 x wn 2 -> warp tile 32m x 64n),
// mma m16n8k16, 3-term hi/lo split (hh + hl + lh), split done at STS.
// smem: [buf][split][k2 (8 rows)][136 uint32], fragment loads conflict-free.
// Double-buffered. All dims multiples of tile sizes.
// ---------------------------------------------------------------------------
template <bool TA, bool TB, bool HAS_BIAS, bool HAS_RES>
__global__ __launch_bounds__(256)
void bmma_gemm(const float* Ap, int aSel, const float* Bp, int bSel,
               const float* __restrict__ bias,
               const float* resP, int resSel,
               float* Cp, int cSel,
               int M, int N, int K,
               long long sA, long long sB, long long sC, long long sRes)
{
    const float* Ag = (aSel >= 0) ? scratch_ptr(aSel) : Ap;
    const float* Bg = (bSel >= 0) ? scratch_ptr(bSel) : Bp;
    float*       Cg = (cSel >= 0) ? scratch_ptr(cSel) : Cp;
    const float* Rg = nullptr;
    if (HAS_RES) Rg = (resSel >= 0) ? scratch_ptr(resSel) : resP;

    const long long z = blockIdx.z;
    Ag += z * sA;  Bg += z * sB;  Cg += z * sC;
    if (HAS_RES) Rg += z * sRes;

    __shared__ uint32_t As[2][2][8][136];   // [buf][hi/lo][k2][m]
    __shared__ uint32_t Bs[2][2][8][136];   // [buf][hi/lo][k2][n]

    const int m0   = blockIdx.y * 128;
    const int n0   = blockIdx.x * 128;
    const int tid  = threadIdx.x;
    const int lane = tid & 31;
    const int warp = tid >> 5;
    const int grp  = lane >> 2;   // 0..7
    const int tig  = lane & 3;    // 0..3
    const int wm   = warp & 3;    // 4 m-tiles of 32
    const int wn   = warp >> 2;   // 2 n-tiles of 64

    float acc[2][8][4];
#pragma unroll
    for (int i = 0; i < 2; i++)
#pragma unroll
        for (int j = 0; j < 8; j++)
#pragma unroll
            for (int q = 0; q < 4; q++) acc[i][j][q] = 0.f;

    float4 pa[2], pb[2];

    auto ldgA = [&](int k0) {
        if (!TA) {                              // A [K, M]
            const int kr2 = tid >> 5;           // k2 row 0..7
            const int mc  = (tid & 31) << 2;
            pa[0] = *reinterpret_cast<const float4*>(
                Ag + (long long)(k0 + 2 * kr2) * M + m0 + mc);
            pa[1] = *reinterpret_cast<const float4*>(
                Ag + (long long)(k0 + 2 * kr2 + 1) * M + m0 + mc);
        } else {                                // A [M, K]
            const int kc = (tid & 3) << 2;
            const int mr = tid >> 2;
            pa[0] = *reinterpret_cast<const float4*>(
                Ag + (long long)(m0 + mr) * K + k0 + kc);
            pa[1] = *reinterpret_cast<const float4*>(
                Ag + (long long)(m0 + mr + 64) * K + k0 + kc);
        }
    };
    auto ldgB = [&](int k0) {
        if (!TB) {                              // B [K, N]
            const int kr2 = tid >> 5;
            const int nc  = (tid & 31) << 2;
            pb[0] = *reinterpret_cast<const float4*>(
                Bg + (long long)(k0 + 2 * kr2) * N + n0 + nc);
            pb[1] = *reinterpret_cast<const float4*>(
                Bg + (long long)(k0 + 2 * kr2 + 1) * N + n0 + nc);
        } else {                                // B [N, K]
            const int kc = (tid & 3) << 2;
            const int nr = tid >> 2;
            pb[0] = *reinterpret_cast<const float4*>(
                Bg + (long long)(n0 + nr) * K + k0 + kc);
            pb[1] = *reinterpret_cast<const float4*>(
                Bg + (long long)(n0 + nr + 64) * K + k0 + kc);
        }
    };
    auto stsA = [&](int buf) {
        if (!TA) {
            const int kr2 = tid >> 5;
            const int mc  = (tid & 31) << 2;
            uint32_t h[4], l[4];
            split_pack(pa[0].x, pa[1].x, h[0], l[0]);
            split_pack(pa[0].y, pa[1].y, h[1], l[1]);
            split_pack(pa[0].z, pa[1].z, h[2], l[2]);
            split_pack(pa[0].w, pa[1].w, h[3], l[3]);
            *reinterpret_cast<uint4*>(&As[buf][0][kr2][mc]) = make_uint4(h[0], h[1], h[2], h[3]);
            *reinterpret_cast<uint4*>(&As[buf][1][kr2][mc]) = make_uint4(l[0], l[1], l[2], l[3]);
        } else {
            const int kc = (tid & 3) << 2;      // k2 rows kc/2, kc/2+1
            const int mr = tid >> 2;
#pragma unroll
            for (int p = 0; p < 2; p++) {
                const float4 v = pa[p];
                const int mm = mr + p * 64;
                uint32_t h0, l0, h1, l1;
                split_pack(v.x, v.y, h0, l0);
                split_pack(v.z, v.w, h1, l1);
                As[buf][0][(kc >> 1)][mm]     = h0;
                As[buf][0][(kc >> 1) + 1][mm] = h1;
                As[buf][1][(kc >> 1)][mm]     = l0;
                As[buf][1][(kc >> 1) + 1][mm] = l1;
            }
        }
    };
    auto stsB = [&](int buf) {
        if (!TB) {
            const int kr2 = tid >> 5;
            const int nc  = (tid & 31) << 2;
            uint32_t h[4], l[4];
            split_pack(pb[0].x, pb[1].x, h[0], l[0]);
            split_pack(pb[0].y, pb[1].y, h[1], l[1]);
            split_pack(pb[0].z, pb[1].z, h[2], l[2]);
            split_pack(pb[0].w, pb[1].w, h[3], l[3]);
            *reinterpret_cast<uint4*>(&Bs[buf][0][kr2][nc]) = make_uint4(h[0], h[1], h[2], h[3]);
            *reinterpret_cast<uint4*>(&Bs[buf][1][kr2][nc]) = make_uint4(l[0], l[1], l[2], l[3]);
        } else {
            const int kc = (tid & 3) << 2;
            const int nr = tid >> 2;
#pragma unroll
            for (int p = 0; p < 2; p++) {
                const float4 v = pb[p];
                const int nn = nr + p * 64;
                uint32_t h0, l0, h1, l1;
                split_pack(v.x, v.y, h0, l0);
                split_pack(v.z, v.w, h1, l1);
                Bs[buf][0][(kc >> 1)][nn]     = h0;
                Bs[buf][0][(kc >> 1) + 1][nn] = h1;
                Bs[buf][1][(kc >> 1)][nn]     = l0;
                Bs[buf][1][(kc >> 1) + 1][nn] = l1;
            }
        }
    };

    // Prologue
    ldgA(0); ldgB(0);
    stsA(0); stsB(0);
    __syncthreads();

    const int nstage = K >> 4;
    for (int ks = 0; ks < nstage; ks++) {
        const int buf = ks & 1;
        const bool more = (ks + 1 < nstage);
        if (more) { ldgA((ks + 1) << 4); ldgB((ks + 1) << 4); }

        // A fragments (hi + lo), 2 m16 subtiles
        uint32_t ah[2][4], al[2][4];
#pragma unroll
        for (int i = 0; i < 2; i++) {
            const int mb = wm * 32 + i * 16 + grp;
            ah[i][0] = As[buf][0][tig][mb];
            ah[i][1] = As[buf][0][tig][mb + 8];
            ah[i][2] = As[buf][0][tig + 4][mb];
            ah[i][3] = As[buf][0][tig + 4][mb + 8];
            al[i][0] = As[buf][1][tig][mb];
            al[i][1] = As[buf][1][tig][mb + 8];
            al[i][2] = As[buf][1][tig + 4][mb];
            al[i][3] = As[buf][1][tig + 4][mb + 8];
        }
#pragma unroll
        for (int j = 0; j < 8; j++) {
            const int nb = wn * 64 + j * 8 + grp;
            const uint32_t bh0 = Bs[buf][0][tig][nb];
            const uint32_t bh1 = Bs[buf][0][tig + 4][nb];
            const uint32_t bl0 = Bs[buf][1][tig][nb];
            const uint32_t bl1 = Bs[buf][1][tig + 4][nb];
#pragma unroll
            for (int i = 0; i < 2; i++) mma16816(acc[i][j], ah[i], bh0, bh1);
#pragma unroll
            for (int i = 0; i < 2; i++) mma16816(acc[i][j], ah[i], bl0, bl1);
#pragma unroll
            for (int i = 0; i < 2; i++) mma16816(acc[i][j], al[i], bh0, bh1);
        }

        if (more) { stsA(buf ^ 1); stsB(buf ^ 1); }
        __syncthreads();
    }

    // Epilogue (c0,c1 -> row grp; c2,c3 -> row grp+8; cols tig*2, tig*2+1)
#pragma unroll
    for (int i = 0; i < 2; i++) {
#pragma unroll
        for (int h = 0; h < 2; h++) {
            const int m = m0 + wm * 32 + i * 16 + grp + h * 8;
            const float bv = HAS_BIAS ? bias[m] : 0.f;
#pragma unroll
            for (int j = 0; j < 8; j++) {
                const int n = n0 + wn * 64 + j * 8 + tig * 2;
                float2 v;
                v.x = acc[i][j][h * 2 + 0] + bv;
                v.y = acc[i][j][h * 2 + 1] + bv;
                if (HAS_RES) {
                    const float2 r = *reinterpret_cast<const float2*>(
                        Rg + (long long)m * N + n);
                    v.x += r.x;  v.y += r.y;
                }
                *reinterpret_cast<float2*>(Cg + (long long)m * N + n) = v;
            }
        }
    }
}

// ---------------------------------------------------------------------------
// Row softmax over d_S: 16384 rows of 1024.
// ---------------------------------------------------------------------------
__global__ void softmax_kernel()
{
    float* row = d_S + (long long)blockIdx.x * NUM;
    const int t = threadIdx.x;

    float v[8];
    float mx = -1e30f;
#pragma unroll
    for (int i = 0; i < 8; i++) {
        v[i] = row[t + i * 128];
        mx = fmaxf(mx, v[i]);
    }

    __shared__ float red[128];
    red[t] = mx;
    __syncthreads();
#pragma unroll
    for (int s = 64; s > 0; s >>= 1) {
        if (t < s) red[t] = fmaxf(red[t], red[t + s]);
        __syncthreads();
    }
    mx = red[0];
    __syncthreads();

    float sum = 0.f;
#pragma unroll
    for (int i = 0; i < 8; i++) {
        v[i] = expf(v[i] - mx);
        sum += v[i];
    }
    red[t] = sum;
    __syncthreads();
#pragma unroll
    for (int s = 64; s > 0; s >>= 1) {
        if (t < s) red[t] += red[t + s];
        __syncthreads();
    }
    const float inv = 1.0f / red[0];
#pragma unroll
    for (int i = 0; i < 8; i++) row[t + i * 128] = v[i] * inv;
}

// ---------------------------------------------------------------------------
// Launcher
// ---------------------------------------------------------------------------
extern "C" void kernel_launch(void* const* d_in, const int* in_sizes, int n_in,
                              void* d_out, int out_size)
{
    const float4* rgb  = reinterpret_cast<const float4*>(d_in[0]);
    const float4* flow = reinterpret_cast<const float4*>(d_in[1]);

    bnrelu_kernel<<<(BATCH * CCH * (NUM / 4)) / 256, 256>>>(
        rgb, flow,
        (const float*)d_in[2],  (const float*)d_in[3],
        (const float*)d_in[4],  (const float*)d_in[5],
        (const float*)d_in[14], (const float*)d_in[15],
        (const float*)d_in[16], (const float*)d_in[17]);

    const long long sX = (long long)CCH * NUM;
    const long long sP = (long long)CIN * NUM;
    const long long sS = (long long)NUM * NUM;
    const long long sO = (long long)CCH * NUM;

    for (int blk = 0; blk < 2; blk++) {
        const int o = blk ? 14 : 2;
        const float* thw = (const float*)d_in[o + 4];
        const float* thb = (const float*)d_in[o + 5];
        const float* phw = (const float*)d_in[o + 6];
        const float* phb = (const float*)d_in[o + 7];
        const float* gw  = (const float*)d_in[o + 8];
        const float* gb  = (const float*)d_in[o + 9];
        const float* ww  = (const float*)d_in[o + 10];
        const float* wb  = (const float*)d_in[o + 11];

        const int ABN = blk ? 2 : 0;
        const int PBN = blk ? 3 : 1;

        // theta = th_w @ Abn + th_b   [256,1024], K=512
        bmma_gemm<true, false, true, false><<<dim3(8, 2, BATCH), 256>>>(
            thw, -1, nullptr, ABN, thb, nullptr, -1, nullptr, 4,
            CIN, NUM, CCH, 0, sX, sP, 0);
        // phi = ph_w @ Pbn + ph_b
        bmma_gemm<true, false, true, false><<<dim3(8, 2, BATCH), 256>>>(
            phw, -1, nullptr, PBN, phb, nullptr, -1, nullptr, 5,
            CIN, NUM, CCH, 0, sX, sP, 0);
        // g = g_w @ Abn + g_b
        bmma_gemm<true, false, true, false><<<dim3(8, 2, BATCH), 256>>>(
            gw, -1, nullptr, ABN, gb, nullptr, -1, nullptr, 6,
            CIN, NUM, CCH, 0, sX, sP, 0);

        // S[n,m] = sum_ci TH[ci,n] * PH[ci,m]
        bmma_gemm<false, false, false, false><<<dim3(8, 8, BATCH), 256>>>(
            nullptr, 4, nullptr, 5, nullptr, nullptr, -1, nullptr, 8,
            NUM, NUM, CIN, sP, sP, sS, 0);

        softmax_kernel<<<BATCH * NUM, 128>>>();

        // Y[ci,n] = sum_m G[ci,m] * P[n,m]
        bmma_gemm<true, true, false, false><<<dim3(8, 2, BATCH), 256>>>(
            nullptr, 6, nullptr, 8, nullptr, nullptr, -1, nullptr, 7,
            CIN, NUM, NUM, sP, sS, sP, 0);

        // out[c,n] = Abn[c,n] + w_b[c] + w_w @ Y
        float* outp = (float*)d_out + (long long)blk * BATCH * CCH * NUM;
        bmma_gemm<true, false, true, true><<<dim3(8, 4, BATCH), 256>>>(
            ww, -1, nullptr, 7, wb, nullptr, ABN, outp, -1,
            CCH, NUM, CIN, 0, sP, sO, sO);
    }
}

// round 4
// speedup vs baseline: 2.0412x; 1.0044x over previous
#include <cuda_runtime.h>
#include <cuda_bf16.h>
#include <cstdint>

// Problem constants
#define BATCH 16
#define CCH   512      // C
#define CIN   256      // CI = C/2
#define NUM   1024     // H*W

// ---------------------------------------------------------------------------
// Static device scratch
// ---------------------------------------------------------------------------
__device__ float d_Abn1[BATCH * CCH * NUM];
__device__ float d_Pbn1[BATCH * CCH * NUM];
__device__ float d_Abn2[BATCH * CCH * NUM];
__device__ float d_Pbn2[BATCH * CCH * NUM];
__device__ float d_TH[BATCH * CIN * NUM];
__device__ float d_PH[BATCH * CIN * NUM];
__device__ float d_G [BATCH * CIN * NUM];
__device__ float d_Y [BATCH * CIN * NUM];
__device__ float d_S [BATCH * NUM * NUM];

__device__ __forceinline__ float* scratch_ptr(int sel) {
    switch (sel) {
        case 0: return d_Abn1;
        case 1: return d_Pbn1;
        case 2: return d_Abn2;
        case 3: return d_Pbn2;
        case 4: return d_TH;
        case 5: return d_PH;
        case 6: return d_G;
        case 7: return d_Y;
        case 8: return d_S;
    }
    return nullptr;
}

// ---------------------------------------------------------------------------
// BN(eval) + ReLU, both parameter sets, both inputs, one pass.
// ---------------------------------------------------------------------------
__global__ void bnrelu_kernel(const float4* __restrict__ rgb,
                              const float4* __restrict__ flow,
                              const float* __restrict__ g1, const float* __restrict__ b1,
                              const float* __restrict__ m1, const float* __restrict__ v1,
                              const float* __restrict__ g2, const float* __restrict__ b2,
                              const float* __restrict__ m2, const float* __restrict__ v2)
{
    int i = blockIdx.x * blockDim.x + threadIdx.x;
    if (i >= BATCH * CCH * (NUM / 4)) return;
    int c = (i >> 8) & (CCH - 1);

    float s1 = g1[c] / sqrtf(v1[c] + 1e-5f);
    float h1 = b1[c] - m1[c] * s1;
    float s2 = g2[c] / sqrtf(v2[c] + 1e-5f);
    float h2 = b2[c] - m2[c] * s2;

    float4 r = rgb[i];
    float4 f = flow[i];
    float4 o;

    o.x = fmaxf(fmaf(r.x, s1, h1), 0.f);
    o.y = fmaxf(fmaf(r.y, s1, h1), 0.f);
    o.z = fmaxf(fmaf(r.z, s1, h1), 0.f);
    o.w = fmaxf(fmaf(r.w, s1, h1), 0.f);
    reinterpret_cast<float4*>(d_Abn1)[i] = o;

    o.x = fmaxf(fmaf(f.x, s1, h1), 0.f);
    o.y = fmaxf(fmaf(f.y, s1, h1), 0.f);
    o.z = fmaxf(fmaf(f.z, s1, h1), 0.f);
    o.w = fmaxf(fmaf(f.w, s1, h1), 0.f);
    reinterpret_cast<float4*>(d_Pbn1)[i] = o;

    o.x = fmaxf(fmaf(f.x, s2, h2), 0.f);
    o.y = fmaxf(fmaf(f.y, s2, h2), 0.f);
    o.z = fmaxf(fmaf(f.z, s2, h2), 0.f);
    o.w = fmaxf(fmaf(f.w, s2, h2), 0.f);
    reinterpret_cast<float4*>(d_Abn2)[i] = o;

    o.x = fmaxf(fmaf(r.x, s2, h2), 0.f);
    o.y = fmaxf(fmaf(r.y, s2, h2), 0.f);
    o.z = fmaxf(fmaf(r.z, s2, h2), 0.f);
    o.w = fmaxf(fmaf(r.w, s2, h2), 0.f);
    reinterpret_cast<float4*>(d_Pbn2)[i] = o;
}

// ---------------------------------------------------------------------------
// bf16 split helpers: x = hi + lo (+ O(2^-18)); pack (even_k, odd_k) pairs.
// ---------------------------------------------------------------------------
__device__ __forceinline__ void split_pack(float a, float b,
                                           uint32_t& hi, uint32_t& lo)
{
    __nv_bfloat16 ha = __float2bfloat16_rn(a);
    __nv_bfloat16 hb = __float2bfloat16_rn(b);
    float ra = a - __bfloat162float(ha);
    float rb = b - __bfloat162float(hb);
    __nv_bfloat16 la = __float2bfloat16_rn(ra);
    __nv_bfloat16 lb = __float2bfloat16_rn(rb);
    __nv_bfloat162 hp; hp.x = ha; hp.y = hb;   // .x = low 16 bits = even k
    __nv_bfloat162 lp; lp.x = la; lp.y = lb;
    hi = *reinterpret_cast<uint32_t*>(&hp);
    lo = *reinterpret_cast<uint32_t*>(&lp);
}

__device__ __forceinline__ void mma16816(float c[4], const uint32_t a[4],
                                         uint32_t b0, uint32_t b1)
{
    asm volatile(
        "mma.sync.aligned.m16n8k16.row.col.f32.bf16.bf16.f32 "
        "{%0,%1,%2,%3}, {%4,%5,%6,%7}, {%8,%9}, {%0,%1,%2,%3};"
        : "+f"(c[0]), "+f"(c[1]), "+f"(c[2]), "+f"(c[3])
        : "r"(a[0]), "r"(a[1]), "r"(a[2]), "r"(a[3]), "r"(b0), "r"(b1));
}

// ---------------------------------------------------------------------------
// Batched bf16-split MMA GEMM:  C[m,n] = sum_k A(k,m)*B(k,n) (+bias[m]) (+res)
//   TA/TB flag the stored layout as in previous rounds.
// CTA tile 128x128x16, 8 warps (wm 4 x wn 2 -> warp tile 32m x 64n),
// mma m16n8k16, 3-term hi/lo split (hh + hl + lh), split done at STS.
// smem: [buf][split][k2 (8 rows)][136 uint32], fragment loads conflict-free.
// Double-buffered. All dims multiples of tile sizes.
// ---------------------------------------------------------------------------
template <bool TA, bool TB, bool HAS_BIAS, bool HAS_RES>
__global__ __launch_bounds__(256)
void bmma_gemm(const float* Ap, int aSel, const float* Bp, int bSel,
               const float* __restrict__ bias,
               const float* resP, int resSel,
               float* Cp, int cSel,
               int M, int N, int K,
               long long sA, long long sB, long long sC, long long sRes)
{
    const float* Ag = (aSel >= 0) ? scratch_ptr(aSel) : Ap;
    const float* Bg = (bSel >= 0) ? scratch_ptr(bSel) : Bp;
    float*       Cg = (cSel >= 0) ? scratch_ptr(cSel) : Cp;
    const float* Rg = nullptr;
    if (HAS_RES) Rg = (resSel >= 0) ? scratch_ptr(resSel) : resP;

    const long long z = blockIdx.z;
    Ag += z * sA;  Bg += z * sB;  Cg += z * sC;
    if (HAS_RES) Rg += z * sRes;

    __shared__ uint32_t As[2][2][8][136];   // [buf][hi/lo][k2][m]
    __shared__ uint32_t Bs[2][2][8][136];   // [buf][hi/lo][k2][n]

    const int m0   = blockIdx.y * 128;
    const int n0   = blockIdx.x * 128;
    const int tid  = threadIdx.x;
    const int lane = tid & 31;
    const int warp = tid >> 5;
    const int grp  = lane >> 2;   // 0..7
    const int tig  = lane & 3;    // 0..3
    const int wm   = warp & 3;    // 4 m-tiles of 32
    const int wn   = warp >> 2;   // 2 n-tiles of 64

    float acc[2][8][4];
#pragma unroll
    for (int i = 0; i < 2; i++)
#pragma unroll
        for (int j = 0; j < 8; j++)
#pragma unroll
            for (int q = 0; q < 4; q++) acc[i][j][q] = 0.f;

    float4 pa[2], pb[2];

    auto ldgA = [&](int k0) {
        if (!TA) {                              // A [K, M]
            const int kr2 = tid >> 5;           // k2 row 0..7
            const int mc  = (tid & 31) << 2;
            pa[0] = *reinterpret_cast<const float4*>(
                Ag + (long long)(k0 + 2 * kr2) * M + m0 + mc);
            pa[1] = *reinterpret_cast<const float4*>(
                Ag + (long long)(k0 + 2 * kr2 + 1) * M + m0 + mc);
        } else {                                // A [M, K]
            const int kc = (tid & 3) << 2;
            const int mr = tid >> 2;
            pa[0] = *reinterpret_cast<const float4*>(
                Ag + (long long)(m0 + mr) * K + k0 + kc);
            pa[1] = *reinterpret_cast<const float4*>(
                Ag + (long long)(m0 + mr + 64) * K + k0 + kc);
        }
    };
    auto ldgB = [&](int k0) {
        if (!TB) {                              // B [K, N]
            const int kr2 = tid >> 5;
            const int nc  = (tid & 31) << 2;
            pb[0] = *reinterpret_cast<const float4*>(
                Bg + (long long)(k0 + 2 * kr2) * N + n0 + nc);
            pb[1] = *reinterpret_cast<const float4*>(
                Bg + (long long)(k0 + 2 * kr2 + 1) * N + n0 + nc);
        } else {                                // B [N, K]
            const int kc = (tid & 3) << 2;
            const int nr = tid >> 2;
            pb[0] = *reinterpret_cast<const float4*>(
                Bg + (long long)(n0 + nr) * K + k0 + kc);
            pb[1] = *reinterpret_cast<const float4*>(
                Bg + (long long)(n0 + nr + 64) * K + k0 + kc);
        }
    };
    auto stsA = [&](int buf) {
        if (!TA) {
            const int kr2 = tid >> 5;
            const int mc  = (tid & 31) << 2;
            uint32_t h[4], l[4];
            split_pack(pa[0].x, pa[1].x, h[0], l[0]);
            split_pack(pa[0].y, pa[1].y, h[1], l[1]);
            split_pack(pa[0].z, pa[1].z, h[2], l[2]);
            split_pack(pa[0].w, pa[1].w, h[3], l[3]);
            *reinterpret_cast<uint4*>(&As[buf][0][kr2][mc]) = make_uint4(h[0], h[1], h[2], h[3]);
            *reinterpret_cast<uint4*>(&As[buf][1][kr2][mc]) = make_uint4(l[0], l[1], l[2], l[3]);
        } else {
            const int kc = (tid & 3) << 2;      // k2 rows kc/2, kc/2+1
            const int mr = tid >> 2;
#pragma unroll
            for (int p = 0; p < 2; p++) {
                const float4 v = pa[p];
                const int mm = mr + p * 64;
                uint32_t h0, l0, h1, l1;
                split_pack(v.x, v.y, h0, l0);
                split_pack(v.z, v.w, h1, l1);
                As[buf][0][(kc >> 1)][mm]     = h0;
                As[buf][0][(kc >> 1) + 1][mm] = h1;
                As[buf][1][(kc >> 1)][mm]     = l0;
                As[buf][1][(kc >> 1) + 1][mm] = l1;
            }
        }
    };
    auto stsB = [&](int buf) {
        if (!TB) {
            const int kr2 = tid >> 5;
            const int nc  = (tid & 31) << 2;
            uint32_t h[4], l[4];
            split_pack(pb[0].x, pb[1].x, h[0], l[0]);
            split_pack(pb[0].y, pb[1].y, h[1], l[1]);
            split_pack(pb[0].z, pb[1].z, h[2], l[2]);
            split_pack(pb[0].w, pb[1].w, h[3], l[3]);
            *reinterpret_cast<uint4*>(&Bs[buf][0][kr2][nc]) = make_uint4(h[0], h[1], h[2], h[3]);
            *reinterpret_cast<uint4*>(&Bs[buf][1][kr2][nc]) = make_uint4(l[0], l[1], l[2], l[3]);
        } else {
            const int kc = (tid & 3) << 2;
            const int nr = tid >> 2;
#pragma unroll
            for (int p = 0; p < 2; p++) {
                const float4 v = pb[p];
                const int nn = nr + p * 64;
                uint32_t h0, l0, h1, l1;
                split_pack(v.x, v.y, h0, l0);
                split_pack(v.z, v.w, h1, l1);
                Bs[buf][0][(kc >> 1)][nn]     = h0;
                Bs[buf][0][(kc >> 1) + 1][nn] = h1;
                Bs[buf][1][(kc >> 1)][nn]     = l0;
                Bs[buf][1][(kc >> 1) + 1][nn] = l1;
            }
        }
    };

    // Prologue
    ldgA(0); ldgB(0);
    stsA(0); stsB(0);
    __syncthreads();

    const int nstage = K >> 4;
    for (int ks = 0; ks < nstage; ks++) {
        const int buf = ks & 1;
        const bool more = (ks + 1 < nstage);
        if (more) { ldgA((ks + 1) << 4); ldgB((ks + 1) << 4); }

        // A fragments (hi + lo), 2 m16 subtiles
        uint32_t ah[2][4], al[2][4];
#pragma unroll
        for (int i = 0; i < 2; i++) {
            const int mb = wm * 32 + i * 16 + grp;
            ah[i][0] = As[buf][0][tig][mb];
            ah[i][1] = As[buf][0][tig][mb + 8];
            ah[i][2] = As[buf][0][tig + 4][mb];
            ah[i][3] = As[buf][0][tig + 4][mb + 8];
            al[i][0] = As[buf][1][tig][mb];
            al[i][1] = As[buf][1][tig][mb + 8];
            al[i][2] = As[buf][1][tig + 4][mb];
            al[i][3] = As[buf][1][tig + 4][mb + 8];
        }
#pragma unroll
        for (int j = 0; j < 8; j++) {
            const int nb = wn * 64 + j * 8 + grp;
            const uint32_t bh0 = Bs[buf][0][tig][nb];
            const uint32_t bh1 = Bs[buf][0][tig + 4][nb];
            const uint32_t bl0 = Bs[buf][1][tig][nb];
            const uint32_t bl1 = Bs[buf][1][tig + 4][nb];
#pragma unroll
            for (int i = 0; i < 2; i++) mma16816(acc[i][j], ah[i], bh0, bh1);
#pragma unroll
            for (int i = 0; i < 2; i++) mma16816(acc[i][j], ah[i], bl0, bl1);
#pragma unroll
            for (int i = 0; i < 2; i++) mma16816(acc[i][j], al[i], bh0, bh1);
        }

        if (more) { stsA(buf ^ 1); stsB(buf ^ 1); }
        __syncthreads();
    }

    // Epilogue (c0,c1 -> row grp; c2,c3 -> row grp+8; cols tig*2, tig*2+1)
#pragma unroll
    for (int i = 0; i < 2; i++) {
#pragma unroll
        for (int h = 0; h < 2; h++) {
            const int m = m0 + wm * 32 + i * 16 + grp + h * 8;
            const float bv = HAS_BIAS ? bias[m] : 0.f;
#pragma unroll
            for (int j = 0; j < 8; j++) {
                const int n = n0 + wn * 64 + j * 8 + tig * 2;
                float2 v;
                v.x = acc[i][j][h * 2 + 0] + bv;
                v.y = acc[i][j][h * 2 + 1] + bv;
                if (HAS_RES) {
                    const float2 r = *reinterpret_cast<const float2*>(
                        Rg + (long long)m * N + n);
                    v.x += r.x;  v.y += r.y;
                }
                *reinterpret_cast<float2*>(Cg + (long long)m * N + n) = v;
            }
        }
    }
}

// ---------------------------------------------------------------------------
// Row softmax over d_S: 16384 rows of 1024.
// ---------------------------------------------------------------------------
__global__ void softmax_kernel()
{
    float* row = d_S + (long long)blockIdx.x * NUM;
    const int t = threadIdx.x;

    float v[8];
    float mx = -1e30f;
#pragma unroll
    for (int i = 0; i < 8; i++) {
        v[i] = row[t + i * 128];
        mx = fmaxf(mx, v[i]);
    }

    __shared__ float red[128];
    red[t] = mx;
    __syncthreads();
#pragma unroll
    for (int s = 64; s > 0; s >>= 1) {
        if (t < s) red[t] = fmaxf(red[t], red[t + s]);
        __syncthreads();
    }
    mx = red[0];
    __syncthreads();

    float sum = 0.f;
#pragma unroll
    for (int i = 0; i < 8; i++) {
        v[i] = expf(v[i] - mx);
        sum += v[i];
    }
    red[t] = sum;
    __syncthreads();
#pragma unroll
    for (int s = 64; s > 0; s >>= 1) {
        if (t < s) red[t] += red[t + s];
        __syncthreads();
    }
    const float inv = 1.0f / red[0];
#pragma unroll
    for (int i = 0; i < 8; i++) row[t + i * 128] = v[i] * inv;
}

// ---------------------------------------------------------------------------
// Launcher
// ---------------------------------------------------------------------------
extern "C" void kernel_launch(void* const* d_in, const int* in_sizes, int n_in,
                              void* d_out, int out_size)
{
    const float4* rgb  = reinterpret_cast<const float4*>(d_in[0]);
    const float4* flow = reinterpret_cast<const float4*>(d_in[1]);

    bnrelu_kernel<<<(BATCH * CCH * (NUM / 4)) / 256, 256>>>(
        rgb, flow,
        (const float*)d_in[2],  (const float*)d_in[3],
        (const float*)d_in[4],  (const float*)d_in[5],
        (const float*)d_in[14], (const float*)d_in[15],
        (const float*)d_in[16], (const float*)d_in[17]);

    const long long sX = (long long)CCH * NUM;
    const long long sP = (long long)CIN * NUM;
    const long long sS = (long long)NUM * NUM;
    const long long sO = (long long)CCH * NUM;

    for (int blk = 0; blk < 2; blk++) {
        const int o = blk ? 14 : 2;
        const float* thw = (const float*)d_in[o + 4];
        const float* thb = (const float*)d_in[o + 5];
        const float* phw = (const float*)d_in[o + 6];
        const float* phb = (const float*)d_in[o + 7];
        const float* gw  = (const float*)d_in[o + 8];
        const float* gb  = (const float*)d_in[o + 9];
        const float* ww  = (const float*)d_in[o + 10];
        const float* wb  = (const float*)d_in[o + 11];

        const int ABN = blk ? 2 : 0;
        const int PBN = blk ? 3 : 1;

        // theta = th_w @ Abn + th_b   [256,1024], K=512
        bmma_gemm<true, false, true, false><<<dim3(8, 2, BATCH), 256>>>(
            thw, -1, nullptr, ABN, thb, nullptr, -1, nullptr, 4,
            CIN, NUM, CCH, 0, sX, sP, 0);
        // phi = ph_w @ Pbn + ph_b
        bmma_gemm<true, false, true, false><<<dim3(8, 2, BATCH), 256>>>(
            phw, -1, nullptr, PBN, phb, nullptr, -1, nullptr, 5,
            CIN, NUM, CCH, 0, sX, sP, 0);
        // g = g_w @ Abn + g_b
        bmma_gemm<true, false, true, false><<<dim3(8, 2, BATCH), 256>>>(
            gw, -1, nullptr, ABN, gb, nullptr, -1, nullptr, 6,
            CIN, NUM, CCH, 0, sX, sP, 0);

        // S[n,m] = sum_ci TH[ci,n] * PH[ci,m]
        bmma_gemm<false, false, false, false><<<dim3(8, 8, BATCH), 256>>>(
            nullptr, 4, nullptr, 5, nullptr, nullptr, -1, nullptr, 8,
            NUM, NUM, CIN, sP, sP, sS, 0);

        softmax_kernel<<<BATCH * NUM, 128>>>();

        // Y[ci,n] = sum_m G[ci,m] * P[n,m]
        bmma_gemm<true, true, false, false><<<dim3(8, 2, BATCH), 256>>>(
            nullptr, 6, nullptr, 8, nullptr, nullptr, -1, nullptr, 7,
            CIN, NUM, NUM, sP, sS, sP, 0);

        // out[c,n] = Abn[c,n] + w_b[c] + w_w @ Y
        float* outp = (float*)d_out + (long long)blk * BATCH * CCH * NUM;
        bmma_gemm<true, false, true, true><<<dim3(8, 4, BATCH), 256>>>(
            ww, -1, nullptr, 7, wb, nullptr, ABN, outp, -1,
            CCH, NUM, CIN, 0, sP, sO, sO);
    }
}

// round 6
// speedup vs baseline: 2.1959x; 1.0758x over previous
#include <cuda_runtime.h>
#include <cuda_bf16.h>
#include <cstdint>

#define BATCH 16
#define CCH   512
#define CIN   256
#define NUM   1024

// ---------------------------------------------------------------------------
// Scratch: packed bf16-pair (uint32) buffers, hi plane then lo plane.
// Layouts are k-major in the consuming GEMM's order: [K/2][width].
// ---------------------------------------------------------------------------
__device__ uint32_t u_X1[8388608];   // bn1(rgb)  [c2][num]  (+4194304 = lo plane)
__device__ uint32_t u_P1[8388608];   // bn1(flow) [c2][num]
__device__ uint32_t u_X2[8388608];   // bn2(flow) [c2][num]
__device__ uint32_t u_P2[8388608];   // bn2(rgb)  [c2][num]
__device__ uint32_t u_TH[4194304];   // theta^T   [ci2][num] (+2097152 lo)
__device__ uint32_t u_PH[4194304];   // phi^T     [ci2][num]
__device__ uint32_t u_G [4194304];   // g-values  [nk2][ci]
__device__ uint32_t u_Y [4194304];   // y^T       [ci2][num]
__device__ uint32_t u_W [1048576];   // 8 W^T mats [din2][dout], 65536 u32 each (+524288 lo)
__device__ uint32_t u_P [16777216];  // softmax probs bf16 rows [n_q][m] (+8388608 lo)
__device__ float    g_S [16777216];  // logits fp32 [b][n_q][m]
__device__ float    g_R1[8388608];   // bn1(rgb)  fp32 c-major (residual blk0)
__device__ float    g_R2[8388608];   // bn2(flow) fp32 c-major (residual blk1)

__device__ __forceinline__ uint32_t* scratch_u32(int s) {
    switch (s) {
        case 0: return u_X1;  case 1: return u_P1;
        case 2: return u_X2;  case 3: return u_P2;
        case 4: return u_TH;  case 5: return u_PH;
        case 6: return u_G;   case 7: return u_Y;
        case 8: return u_W;   case 9: return u_P;
    }
    return nullptr;
}

// ---------------------------------------------------------------------------
// Helpers
// ---------------------------------------------------------------------------
__device__ __forceinline__ uint32_t smem_u32(const void* p) {
    uint32_t a;
    asm("{ .reg .u64 t; cvta.to.shared.u64 t, %1; cvt.u32.u64 %0, t; }" : "=r"(a) : "l"(p));
    return a;
}
__device__ __forceinline__ void cp16(uint32_t dst, const void* src) {
    asm volatile("cp.async.cg.shared.global [%0], [%1], 16;" :: "r"(dst), "l"(src));
}
#define CP_COMMIT() asm volatile("cp.async.commit_group;")
template <int N>
__device__ __forceinline__ void cp_wait() {
    asm volatile("cp.async.wait_group %0;" :: "n"(N));
}

__device__ __forceinline__ uint32_t packf2(float x, float y, uint32_t& lo) {
    __nv_bfloat16 hx = __float2bfloat16_rn(x);
    __nv_bfloat16 hy = __float2bfloat16_rn(y);
    __nv_bfloat16 lx = __float2bfloat16_rn(x - __bfloat162float(hx));
    __nv_bfloat16 ly = __float2bfloat16_rn(y - __bfloat162float(hy));
    __nv_bfloat162 H; H.x = hx; H.y = hy;
    __nv_bfloat162 L; L.x = lx; L.y = ly;
    lo = *reinterpret_cast<uint32_t*>(&L);
    return *reinterpret_cast<uint32_t*>(&H);
}

__device__ __forceinline__ void mma16816(float c[4], const uint32_t a[4],
                                         uint32_t b0, uint32_t b1) {
    asm volatile(
        "mma.sync.aligned.m16n8k16.row.col.f32.bf16.bf16.f32 "
        "{%0,%1,%2,%3}, {%4,%5,%6,%7}, {%8,%9}, {%0,%1,%2,%3};"
        : "+f"(c[0]), "+f"(c[1]), "+f"(c[2]), "+f"(c[3])
        : "r"(a[0]), "r"(a[1]), "r"(a[2]), "r"(a[3]), "r"(b0), "r"(b1));
}

// ---------------------------------------------------------------------------
// BN+ReLU + channel-pair pack (hi/lo) + fp32 residual copies.
// grid (c2=256, z=16), 256 threads: thread t covers 4 n values (float4).
// ---------------------------------------------------------------------------
__global__ void bnrelu_pack(const float4* __restrict__ rgb, const float4* __restrict__ flow,
                            const float* __restrict__ g1, const float* __restrict__ b1,
                            const float* __restrict__ m1, const float* __restrict__ v1,
                            const float* __restrict__ g2, const float* __restrict__ b2,
                            const float* __restrict__ m2, const float* __restrict__ v2)
{
    const int z = blockIdx.y, c2 = blockIdx.x, t = threadIdx.x;
    const int c0 = 2 * c2, c1 = c0 + 1;

    const float s1a = g1[c0] * rsqrtf(v1[c0] + 1e-5f), h1a = b1[c0] - m1[c0] * s1a;
    const float s1b = g1[c1] * rsqrtf(v1[c1] + 1e-5f), h1b = b1[c1] - m1[c1] * s1b;
    const float s2a = g2[c0] * rsqrtf(v2[c0] + 1e-5f), h2a = b2[c0] - m2[c0] * s2a;
    const float s2b = g2[c1] * rsqrtf(v2[c1] + 1e-5f), h2b = b2[c1] - m2[c1] * s2b;

    const int rbase = (z * CCH + c0) * 256 + t;
    const float4 r0 = rgb[rbase],  r1 = rgb[rbase + 256];
    const float4 f0 = flow[rbase], f1 = flow[rbase + 256];

    auto bnr = [](float x, float s, float h) { return fmaxf(fmaf(x, s, h), 0.f); };
    float a1r[8] = { bnr(r0.x,s1a,h1a), bnr(r0.y,s1a,h1a), bnr(r0.z,s1a,h1a), bnr(r0.w,s1a,h1a),
                     bnr(r1.x,s1b,h1b), bnr(r1.y,s1b,h1b), bnr(r1.z,s1b,h1b), bnr(r1.w,s1b,h1b) };
    float a2r[8] = { bnr(r0.x,s2a,h2a), bnr(r0.y,s2a,h2a), bnr(r0.z,s2a,h2a), bnr(r0.w,s2a,h2a),
                     bnr(r1.x,s2b,h2b), bnr(r1.y,s2b,h2b), bnr(r1.z,s2b,h2b), bnr(r1.w,s2b,h2b) };
    float a1f[8] = { bnr(f0.x,s1a,h1a), bnr(f0.y,s1a,h1a), bnr(f0.z,s1a,h1a), bnr(f0.w,s1a,h1a),
                     bnr(f1.x,s1b,h1b), bnr(f1.y,s1b,h1b), bnr(f1.z,s1b,h1b), bnr(f1.w,s1b,h1b) };
    float a2f[8] = { bnr(f0.x,s2a,h2a), bnr(f0.y,s2a,h2a), bnr(f0.z,s2a,h2a), bnr(f0.w,s2a,h2a),
                     bnr(f1.x,s2b,h2b), bnr(f1.y,s2b,h2b), bnr(f1.z,s2b,h2b), bnr(f1.w,s2b,h2b) };

    const long long ob = (long long)z * 262144 + (long long)c2 * 1024 + t * 4;
    auto emit = [&](uint32_t* buf, const float* a) {
        uint32_t H[4], L[4];
#pragma unroll
        for (int q = 0; q < 4; q++) H[q] = packf2(a[q], a[q + 4], L[q]);
        *reinterpret_cast<uint4*>(buf + ob)           = make_uint4(H[0], H[1], H[2], H[3]);
        *reinterpret_cast<uint4*>(buf + 4194304 + ob) = make_uint4(L[0], L[1], L[2], L[3]);
    };
    emit(u_X1, a1r);   // bn1(rgb)
    emit(u_P1, a1f);   // bn1(flow)
    emit(u_X2, a2f);   // bn2(flow)
    emit(u_P2, a2r);   // bn2(rgb)

    reinterpret_cast<float4*>(g_R1)[rbase]       = make_float4(a1r[0], a1r[1], a1r[2], a1r[3]);
    reinterpret_cast<float4*>(g_R1)[rbase + 256] = make_float4(a1r[4], a1r[5], a1r[6], a1r[7]);
    reinterpret_cast<float4*>(g_R2)[rbase]       = make_float4(a2f[0], a2f[1], a2f[2], a2f[3]);
    reinterpret_cast<float4*>(g_R2)[rbase + 256] = make_float4(a2f[4], a2f[5], a2f[6], a2f[7]);
}

// ---------------------------------------------------------------------------
// Weight prep: src fp32 [dout][din] -> W^T packed [din/2][dout] hi/lo.
// grid (din/64, dout/64), 256 threads, smem transpose.
// ---------------------------------------------------------------------------
__global__ void prep_w(const float* __restrict__ src, long long dOfs, int dout, int din)
{
    __shared__ float s[64][65];
    const int bx = blockIdx.x, by = blockIdx.y, t = threadIdx.x;
    const int r0 = t >> 4, c4 = (t & 15) * 4;
#pragma unroll
    for (int rr = 0; rr < 4; rr++) {
        const int row = r0 + rr * 16;
        const float4 v = *reinterpret_cast<const float4*>(
            src + (long long)(by * 64 + row) * din + bx * 64 + c4);
        s[row][c4] = v.x; s[row][c4 + 1] = v.y; s[row][c4 + 2] = v.z; s[row][c4 + 3] = v.w;
    }
    __syncthreads();
    const int k2l = t >> 3, d0 = (t & 7) * 8;
    uint32_t H[8], L[8];
#pragma unroll
    for (int dd = 0; dd < 8; dd++)
        H[dd] = packf2(s[d0 + dd][2 * k2l], s[d0 + dd][2 * k2l + 1], L[dd]);
    const long long dst = dOfs + (long long)(bx * 32 + k2l) * dout + by * 64 + d0;
    *reinterpret_cast<uint4*>(u_W + dst)              = make_uint4(H[0], H[1], H[2], H[3]);
    *reinterpret_cast<uint4*>(u_W + dst + 4)          = make_uint4(H[4], H[5], H[6], H[7]);
    *reinterpret_cast<uint4*>(u_W + 524288 + dst)     = make_uint4(L[0], L[1], L[2], L[3]);
    *reinterpret_cast<uint4*>(u_W + 524288 + dst + 4) = make_uint4(L[4], L[5], L[6], L[7]);
}

// ---------------------------------------------------------------------------
// GEMM: C[m,n] = sum_k A(k,m)*B(k,n), 3-term bf16 split (hh+hl+lh).
// Operands: packed u32 k-pair planes [K/2][M] / [K/2][N] (cp.async path).
// TRA: A is bf16 rows [m][K] (P probs) -> LDG+STS transpose staging.
// CTA 128x128xk16, 4-stage cp.async pipeline, 8 warps (wm4 x wn2).
// MODE: 0 = PACK out [n2][m] (+bias[n] if given), 1 = PACK out (+bias[m]),
//       2 = fp32 logits to g_S, 3 = fp32 out + bias[m] + residual.
// ---------------------------------------------------------------------------
#define STG   4352          // u32 per stage: 2 ops x 2 planes x 8 rows x 136
#define SMEMB (4 * STG * 4) // 69632 bytes

template <int MODE, bool TRA>
__global__ __launch_bounds__(256, 2)
void tc_gemm(int aSel, long long aOfs, long long aPl, long long aBt,
             int bSel, long long bOfs, long long bPl, long long bBt,
             int M, int N, int K,
             const float* __restrict__ bias,
             int oSel, long long oPl, long long oBt,
             float* outF, int rSel)
{
    extern __shared__ uint32_t sm[];
    const uint32_t smb = smem_u32(sm);
    const int tid  = threadIdx.x;
    const int lane = tid & 31;
    const int warp = tid >> 5;
    const int grp  = lane >> 2;
    const int tig  = lane & 3;
    const int wm   = warp & 3;
    const int wn   = warp >> 2;
    const int z    = blockIdx.z;
    const int m0   = blockIdx.y * 128;
    const int n0   = blockIdx.x * 128;

    const uint32_t* Au = scratch_u32(aSel) + aOfs + (long long)z * aBt;
    const uint32_t* Bu = scratch_u32(bSel) + bOfs + (long long)z * bBt;

    const int ldr = tid >> 5, ldc = tid & 31;           // cp.async chunk coords
    const int ml  = tid >> 1, half = tid & 1;           // TRA coords

    auto issueB = [&](int s) {
        const uint32_t base = smb + ((s & 3) * STG + 2176) * 4;
#pragma unroll
        for (int p = 0; p < 2; p++)
            cp16(base + (p * 1088 + ldr * 136 + ldc * 4) * 4,
                 Bu + p * bPl + (long long)(s * 8 + ldr) * N + n0 + ldc * 4);
    };
    auto issueA = [&](int s) {
        const uint32_t base = smb + ((s & 3) * STG) * 4;
#pragma unroll
        for (int p = 0; p < 2; p++)
            cp16(base + (p * 1088 + ldr * 136 + ldc * 4) * 4,
                 Au + p * aPl + (long long)(s * 8 + ldr) * M + m0 + ldc * 4);
    };

    uint4 pre[2];
    auto ldgA = [&](int s) {     // TRA: A rows bf16 [m][K]
#pragma unroll
        for (int p = 0; p < 2; p++)
            pre[p] = *reinterpret_cast<const uint4*>(
                Au + p * aPl + (long long)(m0 + ml) * (K >> 1) + s * 8 + half * 4);
    };
    auto stsA = [&](int s) {
        uint32_t* base = sm + (s & 3) * STG;
#pragma unroll
        for (int p = 0; p < 2; p++) {
            const uint32_t v[4] = {pre[p].x, pre[p].y, pre[p].z, pre[p].w};
#pragma unroll
            for (int j = 0; j < 4; j++)
                base[p * 1088 + (half * 4 + j) * 136 + ml] = v[j];
        }
    };

    float acc[2][8][4];
#pragma unroll
    for (int i = 0; i < 2; i++)
#pragma unroll
        for (int j = 0; j < 8; j++)
#pragma unroll
            for (int q = 0; q < 4; q++) acc[i][j][q] = 0.f;

    const int S = K >> 4;

    // Prologue: 3 stages in flight
    if (TRA) {
        ldgA(0);
        issueB(0); CP_COMMIT();
        issueB(1); CP_COMMIT();
        issueB(2); CP_COMMIT();
        stsA(0); ldgA(1);
    } else {
        issueA(0); issueB(0); CP_COMMIT();
        issueA(1); issueB(1); CP_COMMIT();
        issueA(2); issueB(2); CP_COMMIT();
    }
    cp_wait<2>();
    __syncthreads();

    for (int s = 0; s < S; s++) {
        if (s + 3 < S) {
            if (TRA) { issueB(s + 3); CP_COMMIT(); }
            else     { issueA(s + 3); issueB(s + 3); CP_COMMIT(); }
        }

        // compute stage s
        {
            const uint32_t* bs = sm + (s & 3) * STG;
            uint32_t ah[2][4], al[2][4];
#pragma unroll
            for (int i = 0; i < 2; i++) {
                const int mb = wm * 32 + i * 16 + grp;
                ah[i][0] = bs[tig * 136 + mb];
                ah[i][1] = bs[tig * 136 + mb + 8];
                ah[i][2] = bs[(tig + 4) * 136 + mb];
                ah[i][3] = bs[(tig + 4) * 136 + mb + 8];
                al[i][0] = bs[1088 + tig * 136 + mb];
                al[i][1] = bs[1088 + tig * 136 + mb + 8];
                al[i][2] = bs[1088 + (tig + 4) * 136 + mb];
                al[i][3] = bs[1088 + (tig + 4) * 136 + mb + 8];
            }
#pragma unroll
            for (int j = 0; j < 8; j++) {
                const int nb = wn * 64 + j * 8 + grp;
                const uint32_t bh0 = bs[2176 + tig * 136 + nb];
                const uint32_t bh1 = bs[2176 + (tig + 4) * 136 + nb];
                const uint32_t bl0 = bs[2176 + 1088 + tig * 136 + nb];
                const uint32_t bl1 = bs[2176 + 1088 + (tig + 4) * 136 + nb];
                mma16816(acc[0][j], ah[0], bh0, bh1);
                mma16816(acc[1][j], ah[1], bh0, bh1);
                mma16816(acc[0][j], ah[0], bl0, bl1);
                mma16816(acc[1][j], ah[1], bl0, bl1);
                mma16816(acc[0][j], al[0], bh0, bh1);
                mma16816(acc[1][j], al[1], bh0, bh1);
            }
        }

        if (s + 1 < S) {
            if (TRA) {
                stsA(s + 1);
                if (s + 2 < S) ldgA(s + 2);
            }
            if (s + 3 < S) cp_wait<2>();
            else if (s + 2 < S) cp_wait<1>();
            else cp_wait<0>();
            __syncthreads();
        }
    }

    // ------------------------- epilogue -------------------------
#pragma unroll
    for (int i = 0; i < 2; i++) {
#pragma unroll
        for (int h = 0; h < 2; h++) {
            const int m = m0 + wm * 32 + i * 16 + grp + h * 8;
            float bm = 0.f;
            if (MODE == 1 || MODE == 3) bm = bias[m];
#pragma unroll
            for (int j = 0; j < 8; j++) {
                const int np = n0 + wn * 64 + j * 8 + tig * 2;
                float v0 = acc[i][j][h * 2];
                float v1 = acc[i][j][h * 2 + 1];
                if (MODE == 0 && bias) { v0 += bias[np]; v1 += bias[np + 1]; }
                if (MODE == 1 || MODE == 3) { v0 += bm; v1 += bm; }
                if (MODE <= 1) {
                    uint32_t lo;
                    const uint32_t hi = packf2(v0, v1, lo);
                    uint32_t* O = scratch_u32(oSel) + (long long)z * oBt
                                + (long long)(np >> 1) * M + m;
                    O[0] = hi;
                    O[oPl] = lo;
                } else if (MODE == 2) {
                    float2* O = reinterpret_cast<float2*>(
                        g_S + (long long)z * 1048576 + (long long)m * 1024 + np);
                    *O = make_float2(v0, v1);
                } else {
                    const float* R = (rSel ? g_R2 : g_R1)
                                   + (long long)z * 524288 + (long long)m * 1024 + np;
                    const float2 r2 = *reinterpret_cast<const float2*>(R);
                    float2* O = reinterpret_cast<float2*>(
                        outF + (long long)z * 524288 + (long long)m * 1024 + np);
                    *O = make_float2(v0 + r2.x, v1 + r2.y);
                }
            }
        }
    }
}

// ---------------------------------------------------------------------------
// Softmax row -> packed bf16 m-pair hi/lo rows of u_P. 16384 rows x 1024.
// ---------------------------------------------------------------------------
__global__ void softmax_pack()
{
    const long long row = blockIdx.x;
    const float4* s4 = reinterpret_cast<const float4*>(g_S + row * NUM);
    const int t = threadIdx.x;

    const float4 a = s4[t * 2], b = s4[t * 2 + 1];
    float v[8] = {a.x, a.y, a.z, a.w, b.x, b.y, b.z, b.w};

    float mx = v[0];
#pragma unroll
    for (int i = 1; i < 8; i++) mx = fmaxf(mx, v[i]);

    __shared__ float red[128];
    red[t] = mx;
    __syncthreads();
#pragma unroll
    for (int st = 64; st > 0; st >>= 1) {
        if (t < st) red[t] = fmaxf(red[t], red[t + st]);
        __syncthreads();
    }
    mx = red[0];
    __syncthreads();

    float sum = 0.f;
#pragma unroll
    for (int i = 0; i < 8; i++) { v[i] = expf(v[i] - mx); sum += v[i]; }
    red[t] = sum;
    __syncthreads();
#pragma unroll
    for (int st = 64; st > 0; st >>= 1) {
        if (t < st) red[t] += red[t + st];
        __syncthreads();
    }
    const float inv = 1.0f / red[0];

    uint32_t H[4], L[4];
#pragma unroll
    for (int q = 0; q < 4; q++)
        H[q] = packf2(v[q * 2] * inv, v[q * 2 + 1] * inv, L[q]);
    *reinterpret_cast<uint4*>(u_P + row * 512 + t * 4)           = make_uint4(H[0], H[1], H[2], H[3]);
    *reinterpret_cast<uint4*>(u_P + 8388608 + row * 512 + t * 4) = make_uint4(L[0], L[1], L[2], L[3]);
}

// ---------------------------------------------------------------------------
// Launcher
// ---------------------------------------------------------------------------
extern "C" void kernel_launch(void* const* d_in, const int* in_sizes, int n_in,
                              void* d_out, int out_size)
{
    cudaFuncSetAttribute(tc_gemm<0, false>, cudaFuncAttributeMaxDynamicSharedMemorySize, SMEMB);
    cudaFuncSetAttribute(tc_gemm<1, false>, cudaFuncAttributeMaxDynamicSharedMemorySize, SMEMB);
    cudaFuncSetAttribute(tc_gemm<2, false>, cudaFuncAttributeMaxDynamicSharedMemorySize, SMEMB);
    cudaFuncSetAttribute(tc_gemm<3, false>, cudaFuncAttributeMaxDynamicSharedMemorySize, SMEMB);
    cudaFuncSetAttribute(tc_gemm<0, true>,  cudaFuncAttributeMaxDynamicSharedMemorySize, SMEMB);

    bnrelu_pack<<<dim3(256, 16), 256>>>(
        (const float4*)d_in[0], (const float4*)d_in[1],
        (const float*)d_in[2],  (const float*)d_in[3],
        (const float*)d_in[4],  (const float*)d_in[5],
        (const float*)d_in[14], (const float*)d_in[15],
        (const float*)d_in[16], (const float*)d_in[17]);

    // Weight transpose+split: th/ph/g are [256,512] (grid 8x4), ww is [512,256] (grid 4x8)
    prep_w<<<dim3(8, 4), 256>>>((const float*)d_in[6],  0 * 65536LL, 256, 512);
    prep_w<<<dim3(8, 4), 256>>>((const float*)d_in[8],  1 * 65536LL, 256, 512);
    prep_w<<<dim3(8, 4), 256>>>((const float*)d_in[10], 2 * 65536LL, 256, 512);
    prep_w<<<dim3(4, 8), 256>>>((const float*)d_in[12], 3 * 65536LL, 512, 256);
    prep_w<<<dim3(8, 4), 256>>>((const float*)d_in[18], 4 * 65536LL, 256, 512);
    prep_w<<<dim3(8, 4), 256>>>((const float*)d_in[20], 5 * 65536LL, 256, 512);
    prep_w<<<dim3(8, 4), 256>>>((const float*)d_in[22], 6 * 65536LL, 256, 512);
    prep_w<<<dim3(4, 8), 256>>>((const float*)d_in[24], 7 * 65536LL, 512, 256);

    const long long PLX = 4194304, BTX = 262144;   // activations [c2][num]
    const long long PLQ = 2097152, BTQ = 131072;   // projections [k2][1024 or 256]
    const long long PLW = 524288;                  // weights

    for (int blk = 0; blk < 2; blk++) {
        const int o = blk ? 14 : 2;
        const float* thb = (const float*)d_in[o + 5];
        const float* phb = (const float*)d_in[o + 7];
        const float* gb  = (const float*)d_in[o + 9];
        const float* wb  = (const float*)d_in[o + 11];
        const int Xs = blk ? 2 : 0;
        const int Ps = blk ? 3 : 1;
        const long long mof = (long long)blk * 4 * 65536;

        // theta^T: C[m=num][n=ci] -> u_TH [ci2][num]   (M=1024,N=256,K=512)
        tc_gemm<0, false><<<dim3(2, 8, 16), 256, SMEMB>>>(
            Xs, 0, PLX, BTX,  8, mof, PLW, 0,
            1024, 256, 512, thb, 4, PLQ, BTQ, nullptr, 0);
        // phi^T -> u_PH
        tc_gemm<0, false><<<dim3(2, 8, 16), 256, SMEMB>>>(
            Ps, 0, PLX, BTX,  8, mof + 65536, PLW, 0,
            1024, 256, 512, phb, 5, PLQ, BTQ, nullptr, 0);
        // g-values: C[m=ci][n=num] -> u_G [nk2][ci]    (M=256,N=1024,K=512)
        tc_gemm<1, false><<<dim3(8, 2, 16), 256, SMEMB>>>(
            8, mof + 131072, PLW, 0,  Xs, 0, PLX, BTX,
            256, 1024, 512, gb, 6, PLQ, BTQ, nullptr, 0);

        // logits S[n_q][m] fp32                         (M=1024,N=1024,K=256)
        tc_gemm<2, false><<<dim3(8, 8, 16), 256, SMEMB>>>(
            4, 0, PLQ, BTQ,  5, 0, PLQ, BTQ,
            1024, 1024, 256, nullptr, 0, 0, 0, nullptr, 0);

        softmax_pack<<<BATCH * NUM, 128>>>();

        // AV: C[m=n_q][n=ci] -> u_Y [ci2][num]          (M=1024,N=256,K=1024)
        tc_gemm<0, true><<<dim3(2, 8, 16), 256, SMEMB>>>(
            9, 0, 8388608, 524288,  6, 0, PLQ, BTQ,
            1024, 256, 1024, nullptr, 7, PLQ, BTQ, nullptr, 0);

        // final: out[c][n_q] = W@Y + wb[c] + residual   (M=512,N=1024,K=256)
        float* outp = (float*)d_out + (long long)blk * 8388608;
        tc_gemm<3, false><<<dim3(8, 4, 16), 256, SMEMB>>>(
            8, mof + 196608, PLW, 0,  7, 0, PLQ, BTQ,
            512, 1024, 256, wb, 0, 0, 0, outp, blk);
    }
}

// round 7
// speedup vs baseline: 2.8524x; 1.2990x over previous
#include <cuda_runtime.h>
#include <cuda_fp16.h>
#include <cstdint>

#define BATCH 16
#define CCH   512
#define CIN   256
#define NUM   1024

// ---------------------------------------------------------------------------
// Scratch: packed fp16-pair (uint32) buffers, hi plane then lo plane.
// Layouts are k-major in the consuming GEMM's order: [K/2][width].
// ---------------------------------------------------------------------------
__device__ uint32_t u_X1[8388608];   // bn1(rgb)  [c2][num]  (+4194304 = lo plane)
__device__ uint32_t u_P1[8388608];   // bn1(flow) [c2][num]
__device__ uint32_t u_X2[8388608];   // bn2(flow) [c2][num]
__device__ uint32_t u_P2[8388608];   // bn2(rgb)  [c2][num]
__device__ uint32_t u_TH[4194304];   // theta^T   [ci2][num] (+2097152 lo)
__device__ uint32_t u_PH[4194304];   // phi^T     [ci2][num]
__device__ uint32_t u_G [4194304];   // g-values  [nk2][ci]  (hi used only)
__device__ uint32_t u_Y [4194304];   // y^T       [ci2][num] (hi used only)
__device__ uint32_t u_W [1048576];   // 8 W^T mats [din2][dout], 65536 u32 each (+524288 lo)
__device__ uint32_t u_P [8388608];   // softmax probs fp16 rows [n_q][m2] (hi only)
__device__ float    g_S [16777216];  // logits fp32 [b][n_q][m]
__device__ float    g_R1[8388608];   // bn1(rgb)  fp32 c-major (residual blk0)
__device__ float    g_R2[8388608];   // bn2(flow) fp32 c-major (residual blk1)

__device__ __forceinline__ uint32_t* scratch_u32(int s) {
    switch (s) {
        case 0: return u_X1;  case 1: return u_P1;
        case 2: return u_X2;  case 3: return u_P2;
        case 4: return u_TH;  case 5: return u_PH;
        case 6: return u_G;   case 7: return u_Y;
        case 8: return u_W;   case 9: return u_P;
    }
    return nullptr;
}

// ---------------------------------------------------------------------------
// Helpers
// ---------------------------------------------------------------------------
__device__ __forceinline__ uint32_t smem_u32(const void* p) {
    uint32_t a;
    asm("{ .reg .u64 t; cvta.to.shared.u64 t, %1; cvt.u32.u64 %0, t; }" : "=r"(a) : "l"(p));
    return a;
}
__device__ __forceinline__ void cp16(uint32_t dst, const void* src) {
    asm volatile("cp.async.cg.shared.global [%0], [%1], 16;" :: "r"(dst), "l"(src));
}
#define CP_COMMIT() asm volatile("cp.async.commit_group;")
template <int N>
__device__ __forceinline__ void cp_wait() {
    asm volatile("cp.async.wait_group %0;" :: "n"(N));
}

__device__ __forceinline__ uint32_t packh2(float x, float y, uint32_t& lo) {
    __half hx = __float2half_rn(x), hy = __float2half_rn(y);
    __half lx = __float2half_rn(x - __half2float(hx));
    __half ly = __float2half_rn(y - __half2float(hy));
    __half2 H = __halves2half2(hx, hy);
    __half2 L = __halves2half2(lx, ly);
    lo = *reinterpret_cast<uint32_t*>(&L);
    return *reinterpret_cast<uint32_t*>(&H);
}
__device__ __forceinline__ uint32_t packh1(float x, float y) {
    __half2 H = __halves2half2(__float2half_rn(x), __float2half_rn(y));
    return *reinterpret_cast<uint32_t*>(&H);
}

__device__ __forceinline__ void mma16816(float c[4], const uint32_t a[4],
                                         uint32_t b0, uint32_t b1) {
    asm volatile(
        "mma.sync.aligned.m16n8k16.row.col.f32.f16.f16.f32 "
        "{%0,%1,%2,%3}, {%4,%5,%6,%7}, {%8,%9}, {%0,%1,%2,%3};"
        : "+f"(c[0]), "+f"(c[1]), "+f"(c[2]), "+f"(c[3])
        : "r"(a[0]), "r"(a[1]), "r"(a[2]), "r"(a[3]), "r"(b0), "r"(b1));
}

// ---------------------------------------------------------------------------
// BN+ReLU + channel-pair pack (hi/lo) + fp32 residual copies.
// ---------------------------------------------------------------------------
__global__ void bnrelu_pack(const float4* __restrict__ rgb, const float4* __restrict__ flow,
                            const float* __restrict__ g1, const float* __restrict__ b1,
                            const float* __restrict__ m1, const float* __restrict__ v1,
                            const float* __restrict__ g2, const float* __restrict__ b2,
                            const float* __restrict__ m2, const float* __restrict__ v2)
{
    const int z = blockIdx.y, c2 = blockIdx.x, t = threadIdx.x;
    const int c0 = 2 * c2, c1 = c0 + 1;

    const float s1a = g1[c0] * rsqrtf(v1[c0] + 1e-5f), h1a = b1[c0] - m1[c0] * s1a;
    const float s1b = g1[c1] * rsqrtf(v1[c1] + 1e-5f), h1b = b1[c1] - m1[c1] * s1b;
    const float s2a = g2[c0] * rsqrtf(v2[c0] + 1e-5f), h2a = b2[c0] - m2[c0] * s2a;
    const float s2b = g2[c1] * rsqrtf(v2[c1] + 1e-5f), h2b = b2[c1] - m2[c1] * s2b;

    const int rbase = (z * CCH + c0) * 256 + t;
    const float4 r0 = rgb[rbase],  r1 = rgb[rbase + 256];
    const float4 f0 = flow[rbase], f1 = flow[rbase + 256];

    auto bnr = [](float x, float s, float h) { return fmaxf(fmaf(x, s, h), 0.f); };
    float a1r[8] = { bnr(r0.x,s1a,h1a), bnr(r0.y,s1a,h1a), bnr(r0.z,s1a,h1a), bnr(r0.w,s1a,h1a),
                     bnr(r1.x,s1b,h1b), bnr(r1.y,s1b,h1b), bnr(r1.z,s1b,h1b), bnr(r1.w,s1b,h1b) };
    float a2r[8] = { bnr(r0.x,s2a,h2a), bnr(r0.y,s2a,h2a), bnr(r0.z,s2a,h2a), bnr(r0.w,s2a,h2a),
                     bnr(r1.x,s2b,h2b), bnr(r1.y,s2b,h2b), bnr(r1.z,s2b,h2b), bnr(r1.w,s2b,h2b) };
    float a1f[8] = { bnr(f0.x,s1a,h1a), bnr(f0.y,s1a,h1a), bnr(f0.z,s1a,h1a), bnr(f0.w,s1a,h1a),
                     bnr(f1.x,s1b,h1b), bnr(f1.y,s1b,h1b), bnr(f1.z,s1b,h1b), bnr(f1.w,s1b,h1b) };
    float a2f[8] = { bnr(f0.x,s2a,h2a), bnr(f0.y,s2a,h2a), bnr(f0.z,s2a,h2a), bnr(f0.w,s2a,h2a),
                     bnr(f1.x,s2b,h2b), bnr(f1.y,s2b,h2b), bnr(f1.z,s2b,h2b), bnr(f1.w,s2b,h2b) };

    const long long ob = (long long)z * 262144 + (long long)c2 * 1024 + t * 4;
    auto emit = [&](uint32_t* buf, const float* a) {
        uint32_t H[4], L[4];
#pragma unroll
        for (int q = 0; q < 4; q++) H[q] = packh2(a[q], a[q + 4], L[q]);
        *reinterpret_cast<uint4*>(buf + ob)           = make_uint4(H[0], H[1], H[2], H[3]);
        *reinterpret_cast<uint4*>(buf + 4194304 + ob) = make_uint4(L[0], L[1], L[2], L[3]);
    };
    emit(u_X1, a1r);   // bn1(rgb)
    emit(u_P1, a1f);   // bn1(flow)
    emit(u_X2, a2f);   // bn2(flow)
    emit(u_P2, a2r);   // bn2(rgb)

    reinterpret_cast<float4*>(g_R1)[rbase]       = make_float4(a1r[0], a1r[1], a1r[2], a1r[3]);
    reinterpret_cast<float4*>(g_R1)[rbase + 256] = make_float4(a1r[4], a1r[5], a1r[6], a1r[7]);
    reinterpret_cast<float4*>(g_R2)[rbase]       = make_float4(a2f[0], a2f[1], a2f[2], a2f[3]);
    reinterpret_cast<float4*>(g_R2)[rbase + 256] = make_float4(a2f[4], a2f[5], a2f[6], a2f[7]);
}

// ---------------------------------------------------------------------------
// Weight prep: src fp32 [dout][din] -> W^T packed [din/2][dout] hi/lo.
// ---------------------------------------------------------------------------
__global__ void prep_w(const float* __restrict__ src, long long dOfs, int dout, int din)
{
    __shared__ float s[64][65];
    const int bx = blockIdx.x, by = blockIdx.y, t = threadIdx.x;
    const int r0 = t >> 4, c4 = (t & 15) * 4;
#pragma unroll
    for (int rr = 0; rr < 4; rr++) {
        const int row = r0 + rr * 16;
        const float4 v = *reinterpret_cast<const float4*>(
            src + (long long)(by * 64 + row) * din + bx * 64 + c4);
        s[row][c4] = v.x; s[row][c4 + 1] = v.y; s[row][c4 + 2] = v.z; s[row][c4 + 3] = v.w;
    }
    __syncthreads();
    const int k2l = t >> 3, d0 = (t & 7) * 8;
    uint32_t H[8], L[8];
#pragma unroll
    for (int dd = 0; dd < 8; dd++)
        H[dd] = packh2(s[d0 + dd][2 * k2l], s[d0 + dd][2 * k2l + 1], L[dd]);
    const long long dst = dOfs + (long long)(bx * 32 + k2l) * dout + by * 64 + d0;
    *reinterpret_cast<uint4*>(u_W + dst)              = make_uint4(H[0], H[1], H[2], H[3]);
    *reinterpret_cast<uint4*>(u_W + dst + 4)          = make_uint4(H[4], H[5], H[6], H[7]);
    *reinterpret_cast<uint4*>(u_W + 524288 + dst)     = make_uint4(L[0], L[1], L[2], L[3]);
    *reinterpret_cast<uint4*>(u_W + 524288 + dst + 4) = make_uint4(L[4], L[5], L[6], L[7]);
}

// ---------------------------------------------------------------------------
// GEMM: C[m,n] = sum_k A(k,m)*B(k,n).
// NT=3: fp16 3-term split (hh+lh+hl), term-major order (acc chains broken).
// NT=1: single fp16 mma (hi planes only; half the smem/traffic).
// TRA: A is fp16-pair rows [m][K/2] (P probs) -> LDG+STS transpose staging.
// CTA 128x128xk16, 4-stage cp.async pipeline, 8 warps (wm4 x wn2).
// MODE: 0 = PACK out [n2][m] (+bias[n] if given), 1 = PACK out (+bias[m]),
//       2 = fp32 logits to g_S, 3 = fp32 out + bias[m] + residual.
// OUTLO: MODE 0/1 epilogue also writes the lo plane.
// ---------------------------------------------------------------------------
template <int MODE, bool TRA, int NT, bool OUTLO>
__global__ __launch_bounds__(256, 2)
void tc_gemm(int aSel, long long aOfs, long long aPl, long long aBt,
             int bSel, long long bOfs, long long bPl, long long bBt,
             int M, int N, int K,
             const float* __restrict__ bias,
             int oSel, long long oPl, long long oBt,
             float* outF, int rSel)
{
    constexpr int NPLA = (NT == 3) ? 2 : 1;       // planes per operand
    constexpr int BBASE = NPLA * 1088;            // B offset within stage (u32)
    constexpr int STGU = 2 * NPLA * 1088;         // u32 per stage

    extern __shared__ uint32_t sm[];
    const uint32_t smb = smem_u32(sm);
    const int tid  = threadIdx.x;
    const int lane = tid & 31;
    const int warp = tid >> 5;
    const int grp  = lane >> 2;
    const int tig  = lane & 3;
    const int wm   = warp & 3;
    const int wn   = warp >> 2;
    const int z    = blockIdx.z;
    const int m0   = blockIdx.y * 128;
    const int n0   = blockIdx.x * 128;

    const uint32_t* Au = scratch_u32(aSel) + aOfs + (long long)z * aBt;
    const uint32_t* Bu = scratch_u32(bSel) + bOfs + (long long)z * bBt;

    const int ldr = tid >> 5, ldc = tid & 31;
    const int ml  = tid >> 1, half = tid & 1;

    auto issueB = [&](int s) {
        const uint32_t base = smb + ((s & 3) * STGU + BBASE) * 4;
#pragma unroll
        for (int p = 0; p < NPLA; p++)
            cp16(base + (p * 1088 + ldr * 136 + ldc * 4) * 4,
                 Bu + p * bPl + (long long)(s * 8 + ldr) * N + n0 + ldc * 4);
    };
    auto issueA = [&](int s) {
        const uint32_t base = smb + ((s & 3) * STGU) * 4;
#pragma unroll
        for (int p = 0; p < NPLA; p++)
            cp16(base + (p * 1088 + ldr * 136 + ldc * 4) * 4,
                 Au + p * aPl + (long long)(s * 8 + ldr) * M + m0 + ldc * 4);
    };

    uint4 pre;
    auto ldgA = [&](int s) {     // TRA (NT==1): A fp16-pair rows [m][K/2]
        pre = *reinterpret_cast<const uint4*>(
            Au + (long long)(m0 + ml) * (K >> 1) + s * 8 + half * 4);
    };
    auto stsA = [&](int s) {
        uint32_t* base = sm + (s & 3) * STGU;
        const uint32_t v[4] = {pre.x, pre.y, pre.z, pre.w};
#pragma unroll
        for (int j = 0; j < 4; j++)
            base[(half * 4 + j) * 136 + ml] = v[j];
    };

    float acc[2][8][4];
#pragma unroll
    for (int i = 0; i < 2; i++)
#pragma unroll
        for (int j = 0; j < 8; j++)
#pragma unroll
            for (int q = 0; q < 4; q++) acc[i][j][q] = 0.f;

    const int S = K >> 4;

    // Prologue: 3 stages in flight
    if (TRA) {
        ldgA(0);
        issueB(0); CP_COMMIT();
        issueB(1); CP_COMMIT();
        issueB(2); CP_COMMIT();
        stsA(0); ldgA(1);
    } else {
        issueA(0); issueB(0); CP_COMMIT();
        issueA(1); issueB(1); CP_COMMIT();
        issueA(2); issueB(2); CP_COMMIT();
    }
    cp_wait<2>();
    __syncthreads();

    for (int s = 0; s < S; s++) {
        if (s + 3 < S) {
            if (TRA) { issueB(s + 3); CP_COMMIT(); }
            else     { issueA(s + 3); issueB(s + 3); CP_COMMIT(); }
        }

        // compute stage s (term-major)
        {
            const uint32_t* bs  = sm + (s & 3) * STGU;
            const uint32_t* Bhi = bs + BBASE;
            uint32_t ah[2][4];
#pragma unroll
            for (int i = 0; i < 2; i++) {
                const int mb = wm * 32 + i * 16 + grp;
                ah[i][0] = bs[tig * 136 + mb];
                ah[i][1] = bs[tig * 136 + mb + 8];
                ah[i][2] = bs[(tig + 4) * 136 + mb];
                ah[i][3] = bs[(tig + 4) * 136 + mb + 8];
            }
            uint32_t bh[8][2];
#pragma unroll
            for (int j = 0; j < 8; j++) {      // pass 1: hh
                const int nb = wn * 64 + j * 8 + grp;
                bh[j][0] = Bhi[tig * 136 + nb];
                bh[j][1] = Bhi[(tig + 4) * 136 + nb];
                mma16816(acc[0][j], ah[0], bh[j][0], bh[j][1]);
                mma16816(acc[1][j], ah[1], bh[j][0], bh[j][1]);
            }
            if (NT == 3) {
                const uint32_t* Alo = bs + 1088;
                const uint32_t* Blo = bs + BBASE + 1088;
                uint32_t al[2][4];
#pragma unroll
                for (int i = 0; i < 2; i++) {
                    const int mb = wm * 32 + i * 16 + grp;
                    al[i][0] = Alo[tig * 136 + mb];
                    al[i][1] = Alo[tig * 136 + mb + 8];
                    al[i][2] = Alo[(tig + 4) * 136 + mb];
                    al[i][3] = Alo[(tig + 4) * 136 + mb + 8];
                }
#pragma unroll
                for (int j = 0; j < 8; j++) {  // pass 2: lh
                    mma16816(acc[0][j], al[0], bh[j][0], bh[j][1]);
                    mma16816(acc[1][j], al[1], bh[j][0], bh[j][1]);
                }
#pragma unroll
                for (int j = 0; j < 8; j++) {  // pass 3: hl
                    const int nb = wn * 64 + j * 8 + grp;
                    const uint32_t bl0 = Blo[tig * 136 + nb];
                    const uint32_t bl1 = Blo[(tig + 4) * 136 + nb];
                    mma16816(acc[0][j], ah[0], bl0, bl1);
                    mma16816(acc[1][j], ah[1], bl0, bl1);
                }
            }
        }

        if (s + 1 < S) {
            if (TRA) {
                stsA(s + 1);
                if (s + 2 < S) ldgA(s + 2);
            }
            if (s + 3 < S) cp_wait<2>();
            else if (s + 2 < S) cp_wait<1>();
            else cp_wait<0>();
            __syncthreads();
        }
    }

    // ------------------------- epilogue -------------------------
#pragma unroll
    for (int i = 0; i < 2; i++) {
#pragma unroll
        for (int h = 0; h < 2; h++) {
            const int m = m0 + wm * 32 + i * 16 + grp + h * 8;
            float bm = 0.f;
            if (MODE == 1 || MODE == 3) bm = bias[m];
#pragma unroll
            for (int j = 0; j < 8; j++) {
                const int np = n0 + wn * 64 + j * 8 + tig * 2;
                float v0 = acc[i][j][h * 2];
                float v1 = acc[i][j][h * 2 + 1];
                if (MODE == 0 && bias) { v0 += bias[np]; v1 += bias[np + 1]; }
                if (MODE == 1 || MODE == 3) { v0 += bm; v1 += bm; }
                if (MODE <= 1) {
                    uint32_t* O = scratch_u32(oSel) + (long long)z * oBt
                                + (long long)(np >> 1) * M + m;
                    if (OUTLO) {
                        uint32_t lo;
                        O[0] = packh2(v0, v1, lo);
                        O[oPl] = lo;
                    } else {
                        O[0] = packh1(v0, v1);
                    }
                } else if (MODE == 2) {
                    float2* O = reinterpret_cast<float2*>(
                        g_S + (long long)z * 1048576 + (long long)m * 1024 + np);
                    *O = make_float2(v0, v1);
                } else {
                    const float* R = (rSel ? g_R2 : g_R1)
                                   + (long long)z * 524288 + (long long)m * 1024 + np;
                    const float2 r2 = *reinterpret_cast<const float2*>(R);
                    float2* O = reinterpret_cast<float2*>(
                        outF + (long long)z * 524288 + (long long)m * 1024 + np);
                    *O = make_float2(v0 + r2.x, v1 + r2.y);
                }
            }
        }
    }
}

// ---------------------------------------------------------------------------
// Softmax row -> packed fp16 m-pair rows of u_P (hi only). 16384 rows x 1024.
// ---------------------------------------------------------------------------
__global__ void softmax_pack()
{
    const long long row = blockIdx.x;
    const float4* s4 = reinterpret_cast<const float4*>(g_S + row * NUM);
    const int t = threadIdx.x;

    const float4 a = s4[t * 2], b = s4[t * 2 + 1];
    float v[8] = {a.x, a.y, a.z, a.w, b.x, b.y, b.z, b.w};

    float mx = v[0];
#pragma unroll
    for (int i = 1; i < 8; i++) mx = fmaxf(mx, v[i]);

    __shared__ float red[128];
    red[t] = mx;
    __syncthreads();
#pragma unroll
    for (int st = 64; st > 0; st >>= 1) {
        if (t < st) red[t] = fmaxf(red[t], red[t + st]);
        __syncthreads();
    }
    mx = red[0];
    __syncthreads();

    float sum = 0.f;
#pragma unroll
    for (int i = 0; i < 8; i++) { v[i] = expf(v[i] - mx); sum += v[i]; }
    red[t] = sum;
    __syncthreads();
#pragma unroll
    for (int st = 64; st > 0; st >>= 1) {
        if (t < st) red[t] += red[t + st];
        __syncthreads();
    }
    const float inv = 1.0f / red[0];

    uint32_t H[4];
#pragma unroll
    for (int q = 0; q < 4; q++)
        H[q] = packh1(v[q * 2] * inv, v[q * 2 + 1] * inv);
    *reinterpret_cast<uint4*>(u_P + row * 512 + t * 4) = make_uint4(H[0], H[1], H[2], H[3]);
}

// ---------------------------------------------------------------------------
// Launcher
// ---------------------------------------------------------------------------
extern "C" void kernel_launch(void* const* d_in, const int* in_sizes, int n_in,
                              void* d_out, int out_size)
{
    cudaFuncSetAttribute(tc_gemm<0, false, 3, true >, cudaFuncAttributeMaxDynamicSharedMemorySize, 69632);
    cudaFuncSetAttribute(tc_gemm<2, false, 3, false>, cudaFuncAttributeMaxDynamicSharedMemorySize, 69632);
    cudaFuncSetAttribute(tc_gemm<1, false, 1, false>, cudaFuncAttributeMaxDynamicSharedMemorySize, 34816);
    cudaFuncSetAttribute(tc_gemm<0, true,  1, false>, cudaFuncAttributeMaxDynamicSharedMemorySize, 34816);
    cudaFuncSetAttribute(tc_gemm<3, false, 1, false>, cudaFuncAttributeMaxDynamicSharedMemorySize, 34816);

    bnrelu_pack<<<dim3(256, 16), 256>>>(
        (const float4*)d_in[0], (const float4*)d_in[1],
        (const float*)d_in[2],  (const float*)d_in[3],
        (const float*)d_in[4],  (const float*)d_in[5],
        (const float*)d_in[14], (const float*)d_in[15],
        (const float*)d_in[16], (const float*)d_in[17]);

    prep_w<<<dim3(8, 4), 256>>>((const float*)d_in[6],  0 * 65536LL, 256, 512);
    prep_w<<<dim3(8, 4), 256>>>((const float*)d_in[8],  1 * 65536LL, 256, 512);
    prep_w<<<dim3(8, 4), 256>>>((const float*)d_in[10], 2 * 65536LL, 256, 512);
    prep_w<<<dim3(4, 8), 256>>>((const float*)d_in[12], 3 * 65536LL, 512, 256);
    prep_w<<<dim3(8, 4), 256>>>((const float*)d_in[18], 4 * 65536LL, 256, 512);
    prep_w<<<dim3(8, 4), 256>>>((const float*)d_in[20], 5 * 65536LL, 256, 512);
    prep_w<<<dim3(8, 4), 256>>>((const float*)d_in[22], 6 * 65536LL, 256, 512);
    prep_w<<<dim3(4, 8), 256>>>((const float*)d_in[24], 7 * 65536LL, 512, 256);

    const long long PLX = 4194304, BTX = 262144;   // activations [c2][num]
    const long long PLQ = 2097152, BTQ = 131072;   // projections
    const long long PLW = 524288;                  // weights

    for (int blk = 0; blk < 2; blk++) {
        const int o = blk ? 14 : 2;
        const float* thb = (const float*)d_in[o + 5];
        const float* phb = (const float*)d_in[o + 7];
        const float* gb  = (const float*)d_in[o + 9];
        const float* wb  = (const float*)d_in[o + 11];
        const int Xs = blk ? 2 : 0;
        const int Ps = blk ? 3 : 1;
        const long long mof = (long long)blk * 4 * 65536;

        // theta^T -> u_TH [ci2][num]   (M=1024,N=256,K=512)   3-term
        tc_gemm<0, false, 3, true><<<dim3(2, 8, 16), 256, 69632>>>(
            Xs, 0, PLX, BTX,  8, mof, PLW, 0,
            1024, 256, 512, thb, 4, PLQ, BTQ, nullptr, 0);
        // phi^T -> u_PH                3-term
        tc_gemm<0, false, 3, true><<<dim3(2, 8, 16), 256, 69632>>>(
            Ps, 0, PLX, BTX,  8, mof + 65536, PLW, 0,
            1024, 256, 512, phb, 5, PLQ, BTQ, nullptr, 0);
        // g -> u_G [nk2][ci]           (M=256,N=1024,K=512)   1-term
        tc_gemm<1, false, 1, false><<<dim3(8, 2, 16), 256, 34816>>>(
            8, mof + 131072, PLW, 0,  Xs, 0, PLX, BTX,
            256, 1024, 512, gb, 6, PLQ, BTQ, nullptr, 0);

        // logits S[n_q][m] fp32        (M=1024,N=1024,K=256)  3-term
        tc_gemm<2, false, 3, false><<<dim3(8, 8, 16), 256, 69632>>>(
            4, 0, PLQ, BTQ,  5, 0, PLQ, BTQ,
            1024, 1024, 256, nullptr, 0, 0, 0, nullptr, 0);

        softmax_pack<<<BATCH * NUM, 128>>>();

        // AV -> u_Y [ci2][num]         (M=1024,N=256,K=1024)  1-term, TRA
        tc_gemm<0, true, 1, false><<<dim3(2, 8, 16), 256, 34816>>>(
            9, 0, 0, 524288,  6, 0, PLQ, BTQ,
            1024, 256, 1024, nullptr, 7, PLQ, BTQ, nullptr, 0);

        // final out[c][n_q]            (M=512,N=1024,K=256)   1-term
        float* outp = (float*)d_out + (long long)blk * 8388608;
        tc_gemm<3, false, 1, false><<<dim3(8, 4, 16), 256, 34816>>>(
            8, mof + 196608, PLW, 0,  7, 0, PLQ, BTQ,
            512, 1024, 256, wb, 0, 0, 0, outp, blk);
    }
}

// round 8
// speedup vs baseline: 3.9695x; 1.3916x over previous
#include <cuda_runtime.h>
#include <cuda_fp16.h>
#include <cstdint>

#define BATCH 16
#define CCH   512
#define CIN   256
#define NUM   1024

// ---------------------------------------------------------------------------
// Scratch. Packed fp16-pair (uint32) buffers; hi plane first, lo plane after.
// z-slices: 32 = 2 blocks x 16 batches (blk*16 + batch).
// ---------------------------------------------------------------------------
__device__ uint32_t u_X1[8388608];    // bn1(rgb)  [16][c2 256][1024]  (+4194304 lo)
__device__ uint32_t u_P1[8388608];    // bn1(flow)
__device__ uint32_t u_X2[8388608];    // bn2(flow)
__device__ uint32_t u_P2[8388608];    // bn2(rgb)
__device__ uint32_t u_TH[8388608];    // theta^T [32][ci2 128][1024] (+4194304 lo)
__device__ uint32_t u_PH[8388608];    // phi^T
__device__ uint32_t u_G [4194304];    // g [32][nq2 512][ci 256]   (hi only)
__device__ uint32_t u_Y [4194304];    // y^T [32][ci2 128][1024]   (hi only)
__device__ uint32_t u_W [524288];     // 8 weight mats W^T [k2][dout], hi only
__device__ uint32_t u_P [16777216];   // probs [32][nq 1024][m2 512] (hi only)
__device__ float    g_S [33554432];   // logits fp32 [32][1024][1024]

__device__ __forceinline__ uint32_t* xbuf(int s) {
    switch (s) { case 0: return u_X1; case 1: return u_P1;
                 case 2: return u_X2; default: return u_P2; }
}

// ---------------------------------------------------------------------------
// Helpers
// ---------------------------------------------------------------------------
__device__ __forceinline__ uint32_t smem_u32(const void* p) {
    uint32_t a;
    asm("{ .reg .u64 t; cvta.to.shared.u64 t, %1; cvt.u32.u64 %0, t; }" : "=r"(a) : "l"(p));
    return a;
}
__device__ __forceinline__ void cp16(uint32_t dst, const void* src) {
    asm volatile("cp.async.cg.shared.global [%0], [%1], 16;" :: "r"(dst), "l"(src));
}
#define CP_COMMIT() asm volatile("cp.async.commit_group;")
template <int N>
__device__ __forceinline__ void cp_wait() {
    asm volatile("cp.async.wait_group %0;" :: "n"(N));
}

__device__ __forceinline__ uint32_t packh2(float x, float y, uint32_t& lo) {
    __half hx = __float2half_rn(x), hy = __float2half_rn(y);
    __half lx = __float2half_rn(x - __half2float(hx));
    __half ly = __float2half_rn(y - __half2float(hy));
    __half2 H = __halves2half2(hx, hy);
    __half2 L = __halves2half2(lx, ly);
    lo = *reinterpret_cast<uint32_t*>(&L);
    return *reinterpret_cast<uint32_t*>(&H);
}
__device__ __forceinline__ uint32_t packh1(float x, float y) {
    __half2 H = __halves2half2(__float2half_rn(x), __float2half_rn(y));
    return *reinterpret_cast<uint32_t*>(&H);
}

__device__ __forceinline__ void mma16816(float c[4], const uint32_t a[4],
                                         uint32_t b0, uint32_t b1) {
    asm volatile(
        "mma.sync.aligned.m16n8k16.row.col.f32.f16.f16.f32 "
        "{%0,%1,%2,%3}, {%4,%5,%6,%7}, {%8,%9}, {%0,%1,%2,%3};"
        : "+f"(c[0]), "+f"(c[1]), "+f"(c[2]), "+f"(c[3])
        : "r"(a[0]), "r"(a[1]), "r"(a[2]), "r"(a[3]), "r"(b0), "r"(b1));
}

// ---------------------------------------------------------------------------
// BN+ReLU + channel-pair pack (hi/lo). grid (256 c2, 16 batch), 256 thr.
// ---------------------------------------------------------------------------
__global__ void bnrelu_pack(const float4* __restrict__ rgb, const float4* __restrict__ flow,
                            const float* __restrict__ g1, const float* __restrict__ b1,
                            const float* __restrict__ m1, const float* __restrict__ v1,
                            const float* __restrict__ g2, const float* __restrict__ b2,
                            const float* __restrict__ m2, const float* __restrict__ v2)
{
    const int z = blockIdx.y, c2 = blockIdx.x, t = threadIdx.x;
    const int c0 = 2 * c2, c1 = c0 + 1;

    const float s1a = g1[c0] * rsqrtf(v1[c0] + 1e-5f), h1a = b1[c0] - m1[c0] * s1a;
    const float s1b = g1[c1] * rsqrtf(v1[c1] + 1e-5f), h1b = b1[c1] - m1[c1] * s1b;
    const float s2a = g2[c0] * rsqrtf(v2[c0] + 1e-5f), h2a = b2[c0] - m2[c0] * s2a;
    const float s2b = g2[c1] * rsqrtf(v2[c1] + 1e-5f), h2b = b2[c1] - m2[c1] * s2b;

    const int rbase = (z * CCH + c0) * 256 + t;
    const float4 r0 = rgb[rbase],  r1 = rgb[rbase + 256];
    const float4 f0 = flow[rbase], f1 = flow[rbase + 256];

    auto bnr = [](float x, float s, float h) { return fmaxf(fmaf(x, s, h), 0.f); };
    float a1r[8] = { bnr(r0.x,s1a,h1a), bnr(r0.y,s1a,h1a), bnr(r0.z,s1a,h1a), bnr(r0.w,s1a,h1a),
                     bnr(r1.x,s1b,h1b), bnr(r1.y,s1b,h1b), bnr(r1.z,s1b,h1b), bnr(r1.w,s1b,h1b) };
    float a2r[8] = { bnr(r0.x,s2a,h2a), bnr(r0.y,s2a,h2a), bnr(r0.z,s2a,h2a), bnr(r0.w,s2a,h2a),
                     bnr(r1.x,s2b,h2b), bnr(r1.y,s2b,h2b), bnr(r1.z,s2b,h2b), bnr(r1.w,s2b,h2b) };
    float a1f[8] = { bnr(f0.x,s1a,h1a), bnr(f0.y,s1a,h1a), bnr(f0.z,s1a,h1a), bnr(f0.w,s1a,h1a),
                     bnr(f1.x,s1b,h1b), bnr(f1.y,s1b,h1b), bnr(f1.z,s1b,h1b), bnr(f1.w,s1b,h1b) };
    float a2f[8] = { bnr(f0.x,s2a,h2a), bnr(f0.y,s2a,h2a), bnr(f0.z,s2a,h2a), bnr(f0.w,s2a,h2a),
                     bnr(f1.x,s2b,h2b), bnr(f1.y,s2b,h2b), bnr(f1.z,s2b,h2b), bnr(f1.w,s2b,h2b) };

    const long long ob = (long long)z * 262144 + (long long)c2 * 1024 + t * 4;
    auto emit = [&](uint32_t* buf, const float* a) {
        uint32_t H[4], L[4];
#pragma unroll
        for (int q = 0; q < 4; q++) H[q] = packh2(a[q], a[q + 4], L[q]);
        *reinterpret_cast<uint4*>(buf + ob)           = make_uint4(H[0], H[1], H[2], H[3]);
        *reinterpret_cast<uint4*>(buf + 4194304 + ob) = make_uint4(L[0], L[1], L[2], L[3]);
    };
    emit(u_X1, a1r);
    emit(u_P1, a1f);
    emit(u_X2, a2f);
    emit(u_P2, a2r);
}

// ---------------------------------------------------------------------------
// Weight prep (single launch): 8 mats fp32 [dout][din] -> hi fp16-pair
// [din/2][dout]. mats 3,7 are (512,256); others (256,512). grid (32, 8).
// ---------------------------------------------------------------------------
__global__ void prep_w_all(const float* w0, const float* w1, const float* w2, const float* w3,
                           const float* w4, const float* w5, const float* w6, const float* w7)
{
    __shared__ float s[64][65];
    const int mat = blockIdx.y;
    const bool sw = ((mat & 3) == 3);
    const int dout = sw ? 512 : 256;
    const int din  = sw ? 256 : 512;
    const int gxN  = din / 64;
    const int bx = blockIdx.x % gxN, by = blockIdx.x / gxN;
    const int t = threadIdx.x;
    const float* src;
    switch (mat) {
        case 0: src = w0; break; case 1: src = w1; break;
        case 2: src = w2; break; case 3: src = w3; break;
        case 4: src = w4; break; case 5: src = w5; break;
        case 6: src = w6; break; default: src = w7; break;
    }
    const int r0 = t >> 4, c4 = (t & 15) * 4;
#pragma unroll
    for (int rr = 0; rr < 4; rr++) {
        const int row = r0 + rr * 16;
        const float4 v = *reinterpret_cast<const float4*>(
            src + (long long)(by * 64 + row) * din + bx * 64 + c4);
        s[row][c4] = v.x; s[row][c4 + 1] = v.y; s[row][c4 + 2] = v.z; s[row][c4 + 3] = v.w;
    }
    __syncthreads();
    const int k2l = t >> 3, d0 = (t & 7) * 8;
    uint32_t H[8];
#pragma unroll
    for (int dd = 0; dd < 8; dd++)
        H[dd] = packh1(s[d0 + dd][2 * k2l], s[d0 + dd][2 * k2l + 1]);
    const long long dst = (long long)mat * 65536 + (long long)(bx * 32 + k2l) * dout + by * 64 + d0;
    *reinterpret_cast<uint4*>(u_W + dst)     = make_uint4(H[0], H[1], H[2], H[3]);
    *reinterpret_cast<uint4*>(u_W + dst + 4) = make_uint4(H[4], H[5], H[6], H[7]);
}

// ---------------------------------------------------------------------------
// Unified GEMM, k32 stages. KIND: 0 thph (NT2), 1 g (NT1), 2 logits (NT3),
// 3 AV (NT1,TRA), 4 final (NT1, fp32 out + bias + BN-recomputed residual).
// CTA 128x128; 8 warps (wm 4 x wn 2); term-major fp16 mma.
// ---------------------------------------------------------------------------
template <int KIND>
__global__ __launch_bounds__(256, 2)
void tc_gemm(const float* __restrict__ b0, const float* __restrict__ b1,
             const float* __restrict__ b2, const float* __restrict__ b3,
             const float* __restrict__ i0, const float* __restrict__ i1,
             const float* __restrict__ q0, const float* __restrict__ q1,
             const float* __restrict__ q2, const float* __restrict__ q3,
             const float* __restrict__ q4, const float* __restrict__ q5,
             const float* __restrict__ q6, const float* __restrict__ q7,
             float* outF)
{
    constexpr int  NT   = (KIND == 2) ? 3 : (KIND == 0) ? 2 : 1;
    constexpr bool TRA  = (KIND == 3);
    constexpr int  NPA  = (NT >= 2) ? 2 : 1;
    constexpr int  NPB  = (NT == 3) ? 2 : 1;
    constexpr int  BB   = NPA * 2176;            // B base (u32) within stage
    constexpr int  STGU = (NPA + NPB) * 2176;    // u32 per stage
    constexpr int  NSTG = (NT == 3) ? 3 : 4;
    constexpr int  Kc   = (KIND == 0 || KIND == 1) ? 512 : (KIND == 3) ? 1024 : 256;
    constexpr int  WA   = (KIND == 0 || KIND == 2) ? 1024 : (KIND == 1) ? 256 : 512;
    constexpr int  WB   = (KIND == 0 || KIND == 3) ? 256 : 1024;
    constexpr int  Mtot = (KIND == 1) ? 256 : (KIND == 4) ? 512 : 1024;

    extern __shared__ uint32_t sm[];
    const uint32_t smb = smem_u32(sm);
    const int tid  = threadIdx.x;
    const int lane = tid & 31;
    const int warp = tid >> 5;
    const int grp  = lane >> 2;
    const int tig  = lane & 3;
    const int wm   = warp & 3;
    const int wn   = warp >> 2;
    const int m0   = blockIdx.y * 128;
    const int n0   = blockIdx.x * 128;
    const int zz   = blockIdx.z;

    // ---- KIND-specific operand setup ----
    const uint32_t *Ah = nullptr, *Al = nullptr, *Bh = nullptr, *Bl = nullptr;
    const float* bias = nullptr;
    uint32_t* OU = nullptr;
    float* OF = nullptr;
    int blk = 0, batch = 0;

    if constexpr (KIND == 0) {
        batch = zz & 15; const int sel = zz >> 4; blk = sel >> 1; const int mat = sel & 1;
        Ah = xbuf(sel) + (long long)batch * 262144;  Al = Ah + 4194304;
        Bh = u_W + (blk * 4 + mat) * 65536;
        bias = (sel == 0) ? b0 : (sel == 1) ? b1 : (sel == 2) ? b2 : b3;
        OU = (mat ? u_PH : u_TH) + (long long)(blk * 16 + batch) * 131072;
    } else if constexpr (KIND == 1) {
        blk = zz >> 4; batch = zz & 15;
        Ah = u_W + (blk * 4 + 2) * 65536;
        Bh = xbuf(blk * 2) + (long long)batch * 262144;
        bias = blk ? b1 : b0;
        OU = u_G + (long long)zz * 131072;
    } else if constexpr (KIND == 2) {
        Ah = u_TH + (long long)zz * 131072;  Al = Ah + 4194304;
        Bh = u_PH + (long long)zz * 131072;  Bl = Bh + 4194304;
        OF = g_S + (long long)zz * 1048576;
    } else if constexpr (KIND == 3) {
        Ah = u_P + (long long)zz * 524288;
        Bh = u_G + (long long)zz * 131072;
        OU = u_Y + (long long)zz * 131072;
    } else {
        blk = zz >> 4; batch = zz & 15;
        Ah = u_W + (blk * 4 + 3) * 65536;
        Bh = u_Y + (long long)zz * 131072;
        bias = blk ? b1 : b0;
        OF = outF + (long long)blk * 8388608 + (long long)batch * 524288;
    }

    const int ldr = tid >> 5, ldc = tid & 31;    // cp.async base coords
    const int ml  = tid >> 1, half = tid & 1;    // TRA coords

    auto issueAB = [&](int s, int buf) {
        const uint32_t base = smb + (buf * STGU) * 4;
        if (!TRA) {
#pragma unroll
            for (int p = 0; p < NPA; p++) {
                const uint32_t* src = (p ? Al : Ah);
#pragma unroll
                for (int i = 0; i < 2; i++) {
                    const int q = tid + i * 256, r = q >> 5, c = q & 31;
                    cp16(base + (p * 2176 + r * 136 + c * 4) * 4,
                         src + (long long)(s * 16 + r) * WA + m0 + c * 4);
                }
            }
        }
#pragma unroll
        for (int p = 0; p < NPB; p++) {
            const uint32_t* src = (p ? Bl : Bh);
#pragma unroll
            for (int i = 0; i < 2; i++) {
                const int q = tid + i * 256, r = q >> 5, c = q & 31;
                cp16(base + (BB + p * 2176 + r * 136 + c * 4) * 4,
                     src + (long long)(s * 16 + r) * WB + n0 + c * 4);
            }
        }
        (void)ldr; (void)ldc;
    };

    uint4 pre[2];
    auto ldgA = [&](int s) {
#pragma unroll
        for (int p = 0; p < 2; p++)
            pre[p] = *reinterpret_cast<const uint4*>(
                Ah + (long long)(m0 + ml) * 512 + s * 16 + half * 4 + p * 8);
    };
    auto stsA = [&](int buf) {
        uint32_t* base = sm + buf * STGU;
#pragma unroll
        for (int p = 0; p < 2; p++) {
            const uint32_t v[4] = {pre[p].x, pre[p].y, pre[p].z, pre[p].w};
#pragma unroll
            for (int j = 0; j < 4; j++)
                base[(half * 4 + p * 8 + j) * 136 + ml] = v[j];
        }
    };

    float acc[2][8][4];
#pragma unroll
    for (int i = 0; i < 2; i++)
#pragma unroll
        for (int j = 0; j < 8; j++)
#pragma unroll
            for (int q = 0; q < 4; q++) acc[i][j][q] = 0.f;

    constexpr int S = Kc >> 5;

    // ---- prologue: NSTG-1 stages in flight ----
    if (TRA) {
        ldgA(0);
#pragma unroll
        for (int i = 0; i < NSTG - 1; i++) { issueAB(i, i); CP_COMMIT(); }
        stsA(0); ldgA(1);
    } else {
#pragma unroll
        for (int i = 0; i < NSTG - 1; i++) { issueAB(i, i); CP_COMMIT(); }
    }
    cp_wait<NSTG - 2>();
    __syncthreads();

    int bufC = 0, bufI = NSTG - 1;
    for (int s = 0; s < S; s++) {
        if (s + NSTG - 1 < S) { issueAB(s + NSTG - 1, bufI); CP_COMMIT(); }

        // compute stage s (two k16 halves, term-major)
        {
            const uint32_t* bs = sm + bufC * STGU;
#pragma unroll
            for (int kk = 0; kk < 2; kk++) {
                const int r0 = kk * 8 + tig, r1 = r0 + 4;
                uint32_t ah[2][4];
#pragma unroll
                for (int i = 0; i < 2; i++) {
                    const int mb = wm * 32 + i * 16 + grp;
                    ah[i][0] = bs[r0 * 136 + mb];
                    ah[i][1] = bs[r0 * 136 + mb + 8];
                    ah[i][2] = bs[r1 * 136 + mb];
                    ah[i][3] = bs[r1 * 136 + mb + 8];
                }
                uint32_t bh[8][2];
#pragma unroll
                for (int j = 0; j < 8; j++) {            // pass 1: hh
                    const int nb = wn * 64 + j * 8 + grp;
                    bh[j][0] = bs[BB + r0 * 136 + nb];
                    bh[j][1] = bs[BB + r1 * 136 + nb];
                    mma16816(acc[0][j], ah[0], bh[j][0], bh[j][1]);
                    mma16816(acc[1][j], ah[1], bh[j][0], bh[j][1]);
                }
                if constexpr (NT >= 2) {                  // pass 2: lh
                    uint32_t al[2][4];
#pragma unroll
                    for (int i = 0; i < 2; i++) {
                        const int mb = wm * 32 + i * 16 + grp;
                        al[i][0] = bs[2176 + r0 * 136 + mb];
                        al[i][1] = bs[2176 + r0 * 136 + mb + 8];
                        al[i][2] = bs[2176 + r1 * 136 + mb];
                        al[i][3] = bs[2176 + r1 * 136 + mb + 8];
                    }
#pragma unroll
                    for (int j = 0; j < 8; j++) {
                        mma16816(acc[0][j], al[0], bh[j][0], bh[j][1]);
                        mma16816(acc[1][j], al[1], bh[j][0], bh[j][1]);
                    }
                }
                if constexpr (NT == 3) {                  // pass 3: hl
#pragma unroll
                    for (int j = 0; j < 8; j++) {
                        const int nb = wn * 64 + j * 8 + grp;
                        const uint32_t bl0 = bs[BB + 2176 + r0 * 136 + nb];
                        const uint32_t bl1 = bs[BB + 2176 + r1 * 136 + nb];
                        mma16816(acc[0][j], ah[0], bl0, bl1);
                        mma16816(acc[1][j], ah[1], bl0, bl1);
                    }
                }
            }
        }

        if (s + 1 < S) {
            if (TRA) {
                const int bufN = (bufC + 1 == NSTG) ? 0 : bufC + 1;
                stsA(bufN);
                if (s + 2 < S) ldgA(s + 2);
            }
            const int rem = S - 2 - s;
            if (rem >= NSTG - 2) cp_wait<NSTG - 2>();
            else if constexpr (NSTG == 4) { if (rem == 1) cp_wait<1>(); else cp_wait<0>(); }
            else cp_wait<0>();
            __syncthreads();
        }
        bufC = (bufC + 1 == NSTG) ? 0 : bufC + 1;
        bufI = (bufI + 1 == NSTG) ? 0 : bufI + 1;
    }

    // ---- epilogue ----
#pragma unroll
    for (int i = 0; i < 2; i++) {
#pragma unroll
        for (int h = 0; h < 2; h++) {
            const int m = m0 + wm * 32 + i * 16 + grp + h * 8;
            float bm = 0.f, sc = 0.f, sh = 0.f;
            const float* inp = nullptr;
            if constexpr (KIND == 1) bm = bias[m];
            if constexpr (KIND == 4) {
                bm = bias[m];
                const float* bg = blk ? q4 : q0;
                const float* bb = blk ? q5 : q1;
                const float* bmn = blk ? q6 : q2;
                const float* bv = blk ? q7 : q3;
                sc = bg[m] * rsqrtf(bv[m] + 1e-5f);
                sh = bb[m] - bmn[m] * sc;
                inp = (blk ? i1 : i0) + (long long)batch * 524288 + (long long)m * 1024;
            }
#pragma unroll
            for (int j = 0; j < 8; j++) {
                const int np = n0 + wn * 64 + j * 8 + tig * 2;
                float v0 = acc[i][j][h * 2];
                float v1 = acc[i][j][h * 2 + 1];
                if constexpr (KIND == 0) {
                    v0 += bias[np]; v1 += bias[np + 1];
                    uint32_t lo;
                    const uint32_t hi = packh2(v0, v1, lo);
                    uint32_t* O = OU + (long long)(np >> 1) * Mtot + m;
                    O[0] = hi;
                    O[4194304] = lo;
                } else if constexpr (KIND == 1) {
                    OU[(long long)(np >> 1) * Mtot + m] = packh1(v0 + bm, v1 + bm);
                } else if constexpr (KIND == 2) {
                    *reinterpret_cast<float2*>(OF + (long long)m * 1024 + np) =
                        make_float2(v0, v1);
                } else if constexpr (KIND == 3) {
                    OU[(long long)(np >> 1) * Mtot + m] = packh1(v0, v1);
                } else {
                    const float2 x = *reinterpret_cast<const float2*>(inp + np);
                    const float r0v = fmaxf(fmaf(x.x, sc, sh), 0.f);
                    const float r1v = fmaxf(fmaf(x.y, sc, sh), 0.f);
                    *reinterpret_cast<float2*>(OF + (long long)m * 1024 + np) =
                        make_float2(v0 + bm + r0v, v1 + bm + r1v);
                }
            }
        }
    }
}

// ---------------------------------------------------------------------------
// Softmax row -> packed fp16 m-pair rows of u_P (hi only). 32768 rows x 1024.
// ---------------------------------------------------------------------------
__global__ void softmax_pack()
{
    const long long row = blockIdx.x;
    const float4* s4 = reinterpret_cast<const float4*>(g_S + row * NUM);
    const int t = threadIdx.x;

    const float4 a = s4[t * 2], b = s4[t * 2 + 1];
    float v[8] = {a.x, a.y, a.z, a.w, b.x, b.y, b.z, b.w};

    float mx = v[0];
#pragma unroll
    for (int i = 1; i < 8; i++) mx = fmaxf(mx, v[i]);

    __shared__ float red[128];
    red[t] = mx;
    __syncthreads();
#pragma unroll
    for (int st = 64; st > 0; st >>= 1) {
        if (t < st) red[t] = fmaxf(red[t], red[t + st]);
        __syncthreads();
    }
    mx = red[0];
    __syncthreads();

    float sum = 0.f;
#pragma unroll
    for (int i = 0; i < 8; i++) { v[i] = expf(v[i] - mx); sum += v[i]; }
    red[t] = sum;
    __syncthreads();
#pragma unroll
    for (int st = 64; st > 0; st >>= 1) {
        if (t < st) red[t] += red[t + st];
        __syncthreads();
    }
    const float inv = 1.0f / red[0];

    uint32_t H[4];
#pragma unroll
    for (int q = 0; q < 4; q++)
        H[q] = packh1(v[q * 2] * inv, v[q * 2 + 1] * inv);
    *reinterpret_cast<uint4*>(u_P + row * 512 + t * 4) = make_uint4(H[0], H[1], H[2], H[3]);
}

// ---------------------------------------------------------------------------
// Launcher. 8 launches total.
// ---------------------------------------------------------------------------
extern "C" void kernel_launch(void* const* d_in, const int* in_sizes, int n_in,
                              void* d_out, int out_size)
{
    cudaFuncSetAttribute(tc_gemm<0>, cudaFuncAttributeMaxDynamicSharedMemorySize, 104448);
    cudaFuncSetAttribute(tc_gemm<1>, cudaFuncAttributeMaxDynamicSharedMemorySize, 69632);
    cudaFuncSetAttribute(tc_gemm<2>, cudaFuncAttributeMaxDynamicSharedMemorySize, 104448);
    cudaFuncSetAttribute(tc_gemm<3>, cudaFuncAttributeMaxDynamicSharedMemorySize, 69632);
    cudaFuncSetAttribute(tc_gemm<4>, cudaFuncAttributeMaxDynamicSharedMemorySize, 69632);

    const float* F = nullptr;

    bnrelu_pack<<<dim3(256, 16), 256>>>(
        (const float4*)d_in[0], (const float4*)d_in[1],
        (const float*)d_in[2],  (const float*)d_in[3],
        (const float*)d_in[4],  (const float*)d_in[5],
        (const float*)d_in[14], (const float*)d_in[15],
        (const float*)d_in[16], (const float*)d_in[17]);

    prep_w_all<<<dim3(32, 8), 256>>>(
        (const float*)d_in[6],  (const float*)d_in[8],  (const float*)d_in[10], (const float*)d_in[12],
        (const float*)d_in[18], (const float*)d_in[20], (const float*)d_in[22], (const float*)d_in[24]);

    // theta + phi, both blocks (z = 64)
    tc_gemm<0><<<dim3(2, 8, 64), 256, 104448>>>(
        (const float*)d_in[7], (const float*)d_in[9],
        (const float*)d_in[19], (const float*)d_in[21],
        F, F, F, F, F, F, F, F, F, F, nullptr);

    // g projection, both blocks (z = 32)
    tc_gemm<1><<<dim3(8, 2, 32), 256, 69632>>>(
        (const float*)d_in[11], (const float*)d_in[23], F, F,
        F, F, F, F, F, F, F, F, F, F, nullptr);

    // logits (z = 32)
    tc_gemm<2><<<dim3(8, 8, 32), 256, 104448>>>(
        F, F, F, F, F, F, F, F, F, F, F, F, F, F, nullptr);

    softmax_pack<<<32768, 128>>>();

    // AV (z = 32)
    tc_gemm<3><<<dim3(2, 8, 32), 256, 69632>>>(
        F, F, F, F, F, F, F, F, F, F, F, F, F, F, nullptr);

    // final (z = 32): out = W@Y + wb + bnrelu(input)
    tc_gemm<4><<<dim3(8, 4, 32), 256, 69632>>>(
        (const float*)d_in[13], (const float*)d_in[25], F, F,
        (const float*)d_in[0],  (const float*)d_in[1],
        (const float*)d_in[2],  (const float*)d_in[3],
        (const float*)d_in[4],  (const float*)d_in[5],
        (const float*)d_in[14], (const float*)d_in[15],
        (const float*)d_in[16], (const float*)d_in[17],
        (float*)d_out);
}

// round 9
// speedup vs baseline: 4.1644x; 1.0491x over previous
#include <cuda_runtime.h>
#include <cuda_fp16.h>
#include <cstdint>

#define BATCH 16
#define CCH   512
#define CIN   256
#define NUM   1024

// ---------------------------------------------------------------------------
// Fragment-major global buffers (u32 = fp16 k-pair).
// A-layout: [k16][m16][128]  lane l owns u32 l*4+{0..3} = {a0,a1,a2,a3}
//   reg = ((m&8)>>3) + 2*((kp&4)>>2), lane = (m&7)*4 + (kp&3)
// B-layout: [k16][n8][64]    lane l owns u32 l*2+{0,1}  = {b0,b1}
//   reg = (kp&4)>>2, lane = (n&7)*4 + (kp&3)
// hi plane at 0; lo plane (where present) at +half the array.
// ---------------------------------------------------------------------------
__device__ uint32_t u_XA0[8388608];  // bn1(rgb)  A-layout [16][32][64][128] (+4194304 lo)
__device__ uint32_t u_XA1[8388608];  // bn1(flow)
__device__ uint32_t u_XA2[8388608];  // bn2(flow)
__device__ uint32_t u_XA3[8388608];  // bn2(rgb)
__device__ uint32_t u_XB0[4194304];  // bn1(rgb)  B-layout [16][32][128][64] hi only
__device__ uint32_t u_XB1[4194304];  // bn2(flow) B-layout hi only
__device__ uint32_t u_TH[8388608];   // theta A-layout [32][16][64][128] (+4194304 lo)
__device__ uint32_t u_PH[8388608];   // phi   B-layout [32][16][128][64] (+4194304 lo)
__device__ uint32_t u_G [4194304];   // g     B-layout [32][64][32][64] hi only
__device__ uint32_t u_Y [4194304];   // y     B-layout [32][16][128][64] hi only
__device__ uint32_t u_W [524288];    // 8 mats, 65536 each: th/ph B-layout, g/w A-layout
__device__ uint32_t u_P [16777216];  // probs row-major [32][1024][512 u32]
__device__ float    g_S [33554432];  // logits fp32 [32][1024][1024]

__device__ __forceinline__ uint32_t* xbufA(int s) {
    switch (s) { case 0: return u_XA0; case 1: return u_XA1;
                 case 2: return u_XA2; default: return u_XA3; }
}

// ---------------------------------------------------------------------------
// Helpers
// ---------------------------------------------------------------------------
__device__ __forceinline__ uint32_t smem_u32(const void* p) {
    uint32_t a;
    asm("{ .reg .u64 t; cvta.to.shared.u64 t, %1; cvt.u32.u64 %0, t; }" : "=r"(a) : "l"(p));
    return a;
}
__device__ __forceinline__ void cp16(uint32_t dst, const void* src) {
    asm volatile("cp.async.cg.shared.global [%0], [%1], 16;" :: "r"(dst), "l"(src));
}
#define CP_COMMIT() asm volatile("cp.async.commit_group;")
template <int N>
__device__ __forceinline__ void cp_wait() {
    asm volatile("cp.async.wait_group %0;" :: "n"(N));
}

__device__ __forceinline__ uint32_t packh2(float x, float y, uint32_t& lo) {
    __half hx = __float2half_rn(x), hy = __float2half_rn(y);
    __half lx = __float2half_rn(x - __half2float(hx));
    __half ly = __float2half_rn(y - __half2float(hy));
    __half2 H = __halves2half2(hx, hy);
    __half2 L = __halves2half2(lx, ly);
    lo = *reinterpret_cast<uint32_t*>(&L);
    return *reinterpret_cast<uint32_t*>(&H);
}
__device__ __forceinline__ uint32_t packh1(float x, float y) {
    __half2 H = __halves2half2(__float2half_rn(x), __float2half_rn(y));
    return *reinterpret_cast<uint32_t*>(&H);
}

__device__ __forceinline__ void mma16816(float c[4], const uint32_t a[4],
                                         uint32_t b0, uint32_t b1) {
    asm volatile(
        "mma.sync.aligned.m16n8k16.row.col.f32.f16.f16.f32 "
        "{%0,%1,%2,%3}, {%4,%5,%6,%7}, {%8,%9}, {%0,%1,%2,%3};"
        : "+f"(c[0]), "+f"(c[1]), "+f"(c[2]), "+f"(c[3])
        : "r"(a[0]), "r"(a[1]), "r"(a[2]), "r"(a[3]), "r"(b0), "r"(b1));
}

// ---------------------------------------------------------------------------
// BN+ReLU producing fragment-major tiles. Warp handles one 16c x 16n tile.
// grid (256, 16 batch), 256 thr: tile id = bx*8+warp; t_k = id&31, t_n = id>>5.
// ---------------------------------------------------------------------------
__global__ void bnrelu_pack(const float* __restrict__ rgb, const float* __restrict__ flow,
                            const float* __restrict__ g1, const float* __restrict__ b1,
                            const float* __restrict__ m1, const float* __restrict__ v1,
                            const float* __restrict__ g2, const float* __restrict__ b2,
                            const float* __restrict__ m2, const float* __restrict__ v2)
{
    const int z = blockIdx.y;
    const int warp = threadIdx.x >> 5, lane = threadIdx.x & 31;
    const int grp = lane >> 2, tig = lane & 3;
    const int id = blockIdx.x * 8 + warp;
    const int t_k = id & 31, t_n = id >> 5;
    const int n0 = t_n * 16;

    int c[4];
    c[0] = t_k * 16 + 2 * tig; c[1] = c[0] + 1; c[2] = c[0] + 8; c[3] = c[2] + 1;

    float s1[4], h1[4], s2[4], h2[4];
#pragma unroll
    for (int e = 0; e < 4; e++) {
        s1[e] = g1[c[e]] * rsqrtf(v1[c[e]] + 1e-5f);
        h1[e] = b1[c[e]] - m1[c[e]] * s1[e];
        s2[e] = g2[c[e]] * rsqrtf(v2[c[e]] + 1e-5f);
        h2[e] = b2[c[e]] - m2[c[e]] * s2[e];
    }

    float R[2][4], Fv[2][4];
#pragma unroll
    for (int h = 0; h < 2; h++)
#pragma unroll
        for (int e = 0; e < 4; e++) {
            const long long idx = (long long)(z * CCH + c[e]) * NUM + n0 + grp + h * 8;
            R[h][e] = rgb[idx];
            Fv[h][e] = flow[idx];
        }

    auto bnr = [](float x, float s, float h) { return fmaxf(fmaf(x, s, h), 0.f); };
    const long long aoff = (long long)z * 262144 + (t_k * 64 + t_n) * 128 + lane * 4;
    const long long boff = (long long)z * 262144 + (long long)(t_k * 128 + t_n * 2) * 64 + lane * 2;

    float V[2][4];
    // stream helper: compute vals, emit A-layout hi/lo; optionally B-layout hi.
    auto doStream = [&](const float (*X)[4], const float* sc, const float* sh,
                        uint32_t* bufA, uint32_t* bufB) {
#pragma unroll
        for (int h = 0; h < 2; h++)
#pragma unroll
            for (int e = 0; e < 4; e++) V[h][e] = bnr(X[h][e], sc[e], sh[e]);
        uint32_t L[4];
        uint32_t H0 = packh2(V[0][0], V[0][1], L[0]);   // (h0,q0)
        uint32_t H1 = packh2(V[1][0], V[1][1], L[1]);   // (h1,q0)
        uint32_t H2 = packh2(V[0][2], V[0][3], L[2]);   // (h0,q1)
        uint32_t H3 = packh2(V[1][2], V[1][3], L[3]);   // (h1,q1)
        *reinterpret_cast<uint4*>(bufA + aoff)           = make_uint4(H0, H1, H2, H3);
        *reinterpret_cast<uint4*>(bufA + 4194304 + aoff) = make_uint4(L[0], L[1], L[2], L[3]);
        if (bufB) {
            *reinterpret_cast<uint2*>(bufB + boff)      = make_uint2(H0, H2);   // h=0
            *reinterpret_cast<uint2*>(bufB + boff + 64) = make_uint2(H1, H3);   // h=1
        }
    };
    doStream(R,  s1, h1, u_XA0, u_XB0);   // bn1(rgb)
    doStream(Fv, s1, h1, u_XA1, nullptr); // bn1(flow)
    doStream(Fv, s2, h2, u_XA2, u_XB1);   // bn2(flow)
    doStream(R,  s2, h2, u_XA3, nullptr); // bn2(rgb)
}

// ---------------------------------------------------------------------------
// Weight prep: warp per 16x16 tile. mats 0,1,4,5 (th/ph): B-layout.
// mats 2,3,6,7 (g, w): A-layout. w mats are [512,256]; others [256,512].
// grid (64, 8 mats), 256 thr.
// ---------------------------------------------------------------------------
__global__ void prep_w_all(const float* w0, const float* w1, const float* w2, const float* w3,
                           const float* w4, const float* w5, const float* w6, const float* w7)
{
    const int mat = blockIdx.y;
    const bool isW = ((mat & 3) == 3);
    const int din  = isW ? 256 : 512;
    const int dout = isW ? 512 : 256;
    const bool Asw = ((mat & 3) >= 2);
    const int warp = threadIdx.x >> 5, lane = threadIdx.x & 31;
    const int grp = lane >> 2, tig = lane & 3;
    const int id = blockIdx.x * 8 + warp;
    const int kT = din >> 4;
    const int t_k = id % kT, t_m = id / kT;

    const float* src;
    switch (mat) {
        case 0: src = w0; break; case 1: src = w1; break;
        case 2: src = w2; break; case 3: src = w3; break;
        case 4: src = w4; break; case 5: src = w5; break;
        case 6: src = w6; break; default: src = w7; break;
    }

    uint32_t u[2][2];
#pragma unroll
    for (int h = 0; h < 2; h++)
#pragma unroll
        for (int q = 0; q < 2; q++) {
            const int row = t_m * 16 + grp + h * 8;
            const int col = t_k * 16 + 2 * tig + 8 * q;
            const float2 f = *reinterpret_cast<const float2*>(src + (long long)row * din + col);
            u[h][q] = packh1(f.x, f.y);
        }
    uint32_t* base = u_W + mat * 65536;
    if (Asw) {
        *reinterpret_cast<uint4*>(base + (t_k * (dout >> 4) + t_m) * 128 + lane * 4) =
            make_uint4(u[0][0], u[1][0], u[0][1], u[1][1]);
    } else {
#pragma unroll
        for (int h = 0; h < 2; h++)
            *reinterpret_cast<uint2*>(base + (t_k * (dout >> 3) + t_m * 2 + h) * 64 + lane * 2) =
                make_uint2(u[h][0], u[h][1]);
    }
}

// ---------------------------------------------------------------------------
// Unified GEMM on fragment-major operands, k32 cp.async stages.
// KIND: 0 thph (NT2), 1 g (NT1), 2 logits (NT3), 3 AV (NT1, TRA from u_P rows),
//       4 final (NT1, fp32 out + bias + recomputed BN residual).
// ---------------------------------------------------------------------------
template <int KIND>
__global__ __launch_bounds__(256, 2)
void tc_gemm(const float* __restrict__ b0, const float* __restrict__ b1,
             const float* __restrict__ b2, const float* __restrict__ b3,
             const float* __restrict__ i0, const float* __restrict__ i1,
             const float* __restrict__ q0, const float* __restrict__ q1,
             const float* __restrict__ q2, const float* __restrict__ q3,
             const float* __restrict__ q4, const float* __restrict__ q5,
             const float* __restrict__ q6, const float* __restrict__ q7,
             float* outF)
{
    constexpr int  NT   = (KIND == 2) ? 3 : (KIND == 0) ? 2 : 1;
    constexpr bool TRA  = (KIND == 3);
    constexpr int  NPA  = (NT >= 2) ? 2 : 1;
    constexpr int  NPB  = (NT == 3) ? 2 : 1;
    constexpr int  BBu  = NPA * 2048;
    constexpr int  STGU = (NPA + NPB) * 2048;
    constexpr int  NSTG = (NT == 3) ? 3 : 4;
    constexpr int  Kc   = (KIND == 0 || KIND == 1) ? 512 : (KIND == 3) ? 1024 : 256;
    constexpr int  MT   = (KIND == 1) ? 16 : (KIND == 4) ? 32 : 64;   // m16 tiles in A
    constexpr int  NT8  = (KIND == 0 || KIND == 3) ? 32 : 128;        // n8 tiles in B

    extern __shared__ uint32_t sm[];
    const uint32_t smb = smem_u32(sm);
    const int tid  = threadIdx.x;
    const int lane = tid & 31;
    const int warp = tid >> 5;
    const int grp  = lane >> 2;
    const int tig  = lane & 3;
    const int wm   = warp & 3;
    const int wn   = warp >> 2;
    const int m0   = blockIdx.y * 128;
    const int n0   = blockIdx.x * 128;
    const int zz   = blockIdx.z;

    const uint32_t *Ah = nullptr, *Al = nullptr, *Bh = nullptr, *Bl = nullptr;
    const float* bias = nullptr;
    uint32_t* OU = nullptr;
    float* OF = nullptr;
    int blk = 0, batch = 0, mat = 0;

    if constexpr (KIND == 0) {
        batch = zz & 15; const int sel = zz >> 4; blk = sel >> 1; mat = sel & 1;
        Ah = xbufA(sel) + (long long)batch * 262144;  Al = Ah + 4194304;
        Bh = u_W + (blk * 4 + mat) * 65536;
        bias = (sel == 0) ? b0 : (sel == 1) ? b1 : (sel == 2) ? b2 : b3;
        OU = (mat ? u_PH : u_TH) + (long long)(blk * 16 + batch) * 131072;
    } else if constexpr (KIND == 1) {
        blk = zz >> 4; batch = zz & 15;
        Ah = u_W + (blk * 4 + 2) * 65536;
        Bh = (blk ? u_XB1 : u_XB0) + (long long)batch * 262144;
        bias = blk ? b1 : b0;
        OU = u_G + (long long)zz * 131072;
    } else if constexpr (KIND == 2) {
        Ah = u_TH + (long long)zz * 131072;  Al = Ah + 4194304;
        Bh = u_PH + (long long)zz * 131072;  Bl = Bh + 4194304;
        OF = g_S + (long long)zz * 1048576;
    } else if constexpr (KIND == 3) {
        Ah = u_P + (long long)zz * 524288;          // row-major probs
        Bh = u_G + (long long)zz * 131072;
        OU = u_Y + (long long)zz * 131072;
    } else {
        blk = zz >> 4; batch = zz & 15;
        Ah = u_W + (blk * 4 + 3) * 65536;
        Bh = u_Y + (long long)zz * 131072;
        bias = blk ? b1 : b0;
        OF = outF + (long long)blk * 8388608 + (long long)batch * 524288;
    }

    const int m0t = m0 >> 4, n0t = n0 >> 3;
    const int ml = tid >> 1, half = tid & 1;

    auto issueAB = [&](int s, int buf) {
        const uint32_t base = smb + buf * STGU * 4;
        if (!TRA) {
#pragma unroll
            for (int p = 0; p < NPA; p++) {
                const uint32_t* src = (p ? Al : Ah);
#pragma unroll
                for (int i = 0; i < 2; i++) {
                    const int c = tid + i * 256;
                    const int kk = c >> 8, inner = c & 255;
                    cp16(base + (p * 2048 + c * 4) * 4,
                         src + (long long)((s * 2 + kk) * MT + m0t) * 128 + inner * 4);
                }
            }
        }
#pragma unroll
        for (int p = 0; p < NPB; p++) {
            const uint32_t* src = (p ? Bl : Bh);
#pragma unroll
            for (int i = 0; i < 2; i++) {
                const int c = tid + i * 256;
                const int kk = c >> 8, inner = c & 255;
                cp16(base + (BBu + p * 2048 + c * 4) * 4,
                     src + (long long)((s * 2 + kk) * NT8 + n0t) * 64 + inner * 4);
            }
        }
    };

    uint4 pre[2];
    auto ldgA = [&](int s) {       // TRA: u_P rows [m][512 u32]
#pragma unroll
        for (int p = 0; p < 2; p++)
            pre[p] = *reinterpret_cast<const uint4*>(
                Ah + (long long)(m0 + ml) * 512 + s * 16 + half * 4 + p * 8);
    };
    auto stsA = [&](int buf) {     // scatter into fragment-major A stage
        uint32_t* base = sm + buf * STGU;
        const int tml = ml >> 4, l4 = (ml & 7) * 16, rbase = ((ml >> 3) & 1) + half * 2;
#pragma unroll
        for (int p = 0; p < 2; p++) {
            const uint32_t v[4] = {pre[p].x, pre[p].y, pre[p].z, pre[p].w};
#pragma unroll
            for (int jj = 0; jj < 4; jj++)
                base[((p * 8 + tml) << 7) + l4 + jj * 4 + rbase] = v[jj];
        }
    };

    float acc[2][8][4];
#pragma unroll
    for (int i = 0; i < 2; i++)
#pragma unroll
        for (int j = 0; j < 8; j++)
#pragma unroll
            for (int q = 0; q < 4; q++) acc[i][j][q] = 0.f;

    constexpr int S = Kc >> 5;

    if (TRA) {
        ldgA(0);
#pragma unroll
        for (int i = 0; i < NSTG - 1; i++) { issueAB(i, i); CP_COMMIT(); }
        stsA(0); ldgA(1);
    } else {
#pragma unroll
        for (int i = 0; i < NSTG - 1; i++) { issueAB(i, i); CP_COMMIT(); }
    }
    cp_wait<NSTG - 2>();
    __syncthreads();

    int bufC = 0, bufI = NSTG - 1;
    for (int s = 0; s < S; s++) {
        if (s + NSTG - 1 < S) { issueAB(s + NSTG - 1, bufI); CP_COMMIT(); }

        {
            const uint32_t* st = sm + bufC * STGU;
#pragma unroll
            for (int kk = 0; kk < 2; kk++) {
                uint32_t ah[2][4];
#pragma unroll
                for (int i = 0; i < 2; i++) {
                    const uint4 v = *reinterpret_cast<const uint4*>(
                        st + ((kk * 8 + wm * 2 + i) << 7) + (lane << 2));
                    ah[i][0] = v.x; ah[i][1] = v.y; ah[i][2] = v.z; ah[i][3] = v.w;
                }
                uint2 bh[8];
#pragma unroll
                for (int j = 0; j < 8; j++) {          // pass 1: hh
                    bh[j] = *reinterpret_cast<const uint2*>(
                        st + BBu + ((kk * 16 + wn * 8 + j) << 6) + (lane << 1));
                    mma16816(acc[0][j], ah[0], bh[j].x, bh[j].y);
                    mma16816(acc[1][j], ah[1], bh[j].x, bh[j].y);
                }
                if constexpr (NT >= 2) {                // pass 2: lh
                    uint32_t al[2][4];
#pragma unroll
                    for (int i = 0; i < 2; i++) {
                        const uint4 v = *reinterpret_cast<const uint4*>(
                            st + 2048 + ((kk * 8 + wm * 2 + i) << 7) + (lane << 2));
                        al[i][0] = v.x; al[i][1] = v.y; al[i][2] = v.z; al[i][3] = v.w;
                    }
#pragma unroll
                    for (int j = 0; j < 8; j++) {
                        mma16816(acc[0][j], al[0], bh[j].x, bh[j].y);
                        mma16816(acc[1][j], al[1], bh[j].x, bh[j].y);
                    }
                }
                if constexpr (NT == 3) {                // pass 3: hl
#pragma unroll
                    for (int j = 0; j < 8; j++) {
                        const uint2 bl = *reinterpret_cast<const uint2*>(
                            st + BBu + 2048 + ((kk * 16 + wn * 8 + j) << 6) + (lane << 1));
                        mma16816(acc[0][j], ah[0], bl.x, bl.y);
                        mma16816(acc[1][j], ah[1], bl.x, bl.y);
                    }
                }
            }
        }

        if (s + 1 < S) {
            if (TRA) {
                const int bufN = (bufC + 1 == NSTG) ? 0 : bufC + 1;
                stsA(bufN);
                if (s + 2 < S) ldgA(s + 2);
            }
            const int rem = S - 2 - s;
            if (rem >= NSTG - 2) cp_wait<NSTG - 2>();
            else if constexpr (NSTG == 4) { if (rem == 1) cp_wait<1>(); else cp_wait<0>(); }
            else cp_wait<0>();
            __syncthreads();
        }
        bufC = (bufC + 1 == NSTG) ? 0 : bufC + 1;
        bufI = (bufI + 1 == NSTG) ? 0 : bufI + 1;
    }

    // ------------------------------ epilogue ------------------------------
    const int tkb = (n0 >> 4) + wn * 4;   // consumer k16 tile base (pair dims)

    if constexpr (KIND == 0) {
        if (mat == 0) {   // theta -> A-layout, MT_out = 64
#pragma unroll
            for (int i = 0; i < 2; i++) {
                const int t_m = (m0 + wm * 32 + i * 16) >> 4;
#pragma unroll
                for (int j2 = 0; j2 < 4; j2++) {
                    const int npe = n0 + wn * 64 + j2 * 16 + tig * 2;
                    const float2 bE = *reinterpret_cast<const float2*>(bias + npe);
                    const float2 bO = *reinterpret_cast<const float2*>(bias + npe + 8);
                    uint32_t L0, L1, L2, L3;
                    const uint32_t H0 = packh2(acc[i][2*j2][0]+bE.x, acc[i][2*j2][1]+bE.y, L0);
                    const uint32_t H1 = packh2(acc[i][2*j2][2]+bE.x, acc[i][2*j2][3]+bE.y, L1);
                    const uint32_t H2 = packh2(acc[i][2*j2+1][0]+bO.x, acc[i][2*j2+1][1]+bO.y, L2);
                    const uint32_t H3 = packh2(acc[i][2*j2+1][2]+bO.x, acc[i][2*j2+1][3]+bO.y, L3);
                    const long long off = (long long)((tkb + j2) * 64 + t_m) * 128 + lane * 4;
                    *reinterpret_cast<uint4*>(OU + off)           = make_uint4(H0, H1, H2, H3);
                    *reinterpret_cast<uint4*>(OU + 4194304 + off) = make_uint4(L0, L1, L2, L3);
                }
            }
        } else {          // phi -> B-layout, NT8_out = 128
#pragma unroll
            for (int i = 0; i < 2; i++)
#pragma unroll
                for (int h = 0; h < 2; h++) {
                    const int t_n = (m0 + wm * 32 + i * 16 + h * 8) >> 3;
#pragma unroll
                    for (int j2 = 0; j2 < 4; j2++) {
                        const int npe = n0 + wn * 64 + j2 * 16 + tig * 2;
                        const float2 bE = *reinterpret_cast<const float2*>(bias + npe);
                        const float2 bO = *reinterpret_cast<const float2*>(bias + npe + 8);
                        uint32_t L0, L1;
                        const uint32_t U0 = packh2(acc[i][2*j2][h*2]+bE.x, acc[i][2*j2][h*2+1]+bE.y, L0);
                        const uint32_t U1 = packh2(acc[i][2*j2+1][h*2]+bO.x, acc[i][2*j2+1][h*2+1]+bO.y, L1);
                        const long long off = (long long)((tkb + j2) * 128 + t_n) * 64 + lane * 2;
                        *reinterpret_cast<uint2*>(OU + off)           = make_uint2(U0, U1);
                        *reinterpret_cast<uint2*>(OU + 4194304 + off) = make_uint2(L0, L1);
                    }
                }
        }
    } else if constexpr (KIND == 1 || KIND == 3) {
        constexpr int NTOUT = (KIND == 1) ? 32 : 128;   // n8 tiles in out buffer
#pragma unroll
        for (int i = 0; i < 2; i++)
#pragma unroll
            for (int h = 0; h < 2; h++) {
                const int m = m0 + wm * 32 + i * 16 + grp + h * 8;
                const float bm = (KIND == 1) ? bias[m] : 0.f;
                const int t_n = m >> 3;
#pragma unroll
                for (int j2 = 0; j2 < 4; j2++) {
                    const uint32_t U0 = packh1(acc[i][2*j2][h*2] + bm, acc[i][2*j2][h*2+1] + bm);
                    const uint32_t U1 = packh1(acc[i][2*j2+1][h*2] + bm, acc[i][2*j2+1][h*2+1] + bm);
                    const long long off = (long long)((tkb + j2) * NTOUT + t_n) * 64 + lane * 2;
                    *reinterpret_cast<uint2*>(OU + off) = make_uint2(U0, U1);
                }
            }
    } else {
#pragma unroll
        for (int i = 0; i < 2; i++)
#pragma unroll
            for (int h = 0; h < 2; h++) {
                const int m = m0 + wm * 32 + i * 16 + grp + h * 8;
                float bm = 0.f, sc = 0.f, sh = 0.f;
                const float* inp = nullptr;
                if constexpr (KIND == 4) {
                    bm = bias[m];
                    const float* bg  = blk ? q4 : q0;
                    const float* bb  = blk ? q5 : q1;
                    const float* bmn = blk ? q6 : q2;
                    const float* bv  = blk ? q7 : q3;
                    sc = bg[m] * rsqrtf(bv[m] + 1e-5f);
                    sh = bb[m] - bmn[m] * sc;
                    inp = (blk ? i1 : i0) + (long long)batch * 524288 + (long long)m * 1024;
                }
#pragma unroll
                for (int j = 0; j < 8; j++) {
                    const int np = n0 + wn * 64 + j * 8 + tig * 2;
                    const float v0 = acc[i][j][h * 2];
                    const float v1 = acc[i][j][h * 2 + 1];
                    if constexpr (KIND == 2) {
                        *reinterpret_cast<float2*>(OF + (long long)m * 1024 + np) =
                            make_float2(v0, v1);
                    } else {
                        const float2 x = *reinterpret_cast<const float2*>(inp + np);
                        const float r0v = fmaxf(fmaf(x.x, sc, sh), 0.f);
                        const float r1v = fmaxf(fmaf(x.y, sc, sh), 0.f);
                        *reinterpret_cast<float2*>(OF + (long long)m * 1024 + np) =
                            make_float2(v0 + bm + r0v, v1 + bm + r1v);
                    }
                }
            }
    }
}

// ---------------------------------------------------------------------------
// Softmax rows -> u_P fp16-pair rows. 32768 rows x 1024.
// ---------------------------------------------------------------------------
__global__ void softmax_pack()
{
    const long long row = blockIdx.x;
    const float4* s4 = reinterpret_cast<const float4*>(g_S + row * NUM);
    const int t = threadIdx.x;

    const float4 a = s4[t * 2], b = s4[t * 2 + 1];
    float v[8] = {a.x, a.y, a.z, a.w, b.x, b.y, b.z, b.w};

    float mx = v[0];
#pragma unroll
    for (int i = 1; i < 8; i++) mx = fmaxf(mx, v[i]);

    __shared__ float red[128];
    red[t] = mx;
    __syncthreads();
#pragma unroll
    for (int st = 64; st > 0; st >>= 1) {
        if (t < st) red[t] = fmaxf(red[t], red[t + st]);
        __syncthreads();
    }
    mx = red[0];
    __syncthreads();

    float sum = 0.f;
#pragma unroll
    for (int i = 0; i < 8; i++) { v[i] = expf(v[i] - mx); sum += v[i]; }
    red[t] = sum;
    __syncthreads();
#pragma unroll
    for (int st = 64; st > 0; st >>= 1) {
        if (t < st) red[t] += red[t + st];
        __syncthreads();
    }
    const float inv = 1.0f / red[0];

    uint32_t H[4];
#pragma unroll
    for (int q = 0; q < 4; q++)
        H[q] = packh1(v[q * 2] * inv, v[q * 2 + 1] * inv);
    *reinterpret_cast<uint4*>(u_P + row * 512 + t * 4) = make_uint4(H[0], H[1], H[2], H[3]);
}

// ---------------------------------------------------------------------------
// Launcher
// ---------------------------------------------------------------------------
extern "C" void kernel_launch(void* const* d_in, const int* in_sizes, int n_in,
                              void* d_out, int out_size)
{
    cudaFuncSetAttribute(tc_gemm<0>, cudaFuncAttributeMaxDynamicSharedMemorySize, 98304);
    cudaFuncSetAttribute(tc_gemm<1>, cudaFuncAttributeMaxDynamicSharedMemorySize, 65536);
    cudaFuncSetAttribute(tc_gemm<2>, cudaFuncAttributeMaxDynamicSharedMemorySize, 98304);
    cudaFuncSetAttribute(tc_gemm<3>, cudaFuncAttributeMaxDynamicSharedMemorySize, 65536);
    cudaFuncSetAttribute(tc_gemm<4>, cudaFuncAttributeMaxDynamicSharedMemorySize, 65536);

    const float* F = nullptr;

    bnrelu_pack<<<dim3(256, 16), 256>>>(
        (const float*)d_in[0], (const float*)d_in[1],
        (const float*)d_in[2],  (const float*)d_in[3],
        (const float*)d_in[4],  (const float*)d_in[5],
        (const float*)d_in[14], (const float*)d_in[15],
        (const float*)d_in[16], (const float*)d_in[17]);

    prep_w_all<<<dim3(64, 8), 256>>>(
        (const float*)d_in[6],  (const float*)d_in[8],  (const float*)d_in[10], (const float*)d_in[12],
        (const float*)d_in[18], (const float*)d_in[20], (const float*)d_in[22], (const float*)d_in[24]);

    // theta + phi, both blocks (z = 64)
    tc_gemm<0><<<dim3(2, 8, 64), 256, 98304>>>(
        (const float*)d_in[7], (const float*)d_in[9],
        (const float*)d_in[19], (const float*)d_in[21],
        F, F, F, F, F, F, F, F, F, F, nullptr);

    // g projection, both blocks (z = 32)
    tc_gemm<1><<<dim3(8, 2, 32), 256, 65536>>>(
        (const float*)d_in[11], (const float*)d_in[23], F, F,
        F, F, F, F, F, F, F, F, F, F, nullptr);

    // logits (z = 32)
    tc_gemm<2><<<dim3(8, 8, 32), 256, 98304>>>(
        F, F, F, F, F, F, F, F, F, F, F, F, F, F, nullptr);

    softmax_pack<<<32768, 128>>>();

    // AV (z = 32)
    tc_gemm<3><<<dim3(2, 8, 32), 256, 65536>>>(
        F, F, F, F, F, F, F, F, F, F, F, F, F, F, nullptr);

    // final (z = 32)
    tc_gemm<4><<<dim3(8, 4, 32), 256, 65536>>>(
        (const float*)d_in[13], (const float*)d_in[25], F, F,
        (const float*)d_in[0],  (const float*)d_in[1],
        (const float*)d_in[2],  (const float*)d_in[3],
        (const float*)d_in[4],  (const float*)d_in[5],
        (const float*)d_in[14], (const float*)d_in[15],
        (const float*)d_in[16], (const float*)d_in[17],
        (float*)d_out);
}

// round 10
// speedup vs baseline: 4.5061x; 1.0820x over previous
#include <cuda_runtime.h>
#include <cuda_fp16.h>
#include <cstdint>

#define BATCH 16
#define CCH   512
#define CIN   256
#define NUM   1024

// ---------------------------------------------------------------------------
// Fragment-major global buffers (u32 = fp16 k-pair).
// A-layout: [k16][m16][128]  lane l owns u32 l*4+{0..3} = {a0,a1,a2,a3}
// B-layout: [k16][n8][64]    lane l owns u32 l*2+{0,1}  = {b0,b1}
// hi plane at 0; lo plane (where present) at +half the array.
// ---------------------------------------------------------------------------
__device__ uint32_t u_XA0[8388608];  // bn1(rgb)  A-layout [16][32][64][128] (+4194304 lo)
__device__ uint32_t u_XA1[8388608];  // bn1(flow)
__device__ uint32_t u_XA2[8388608];  // bn2(flow)
__device__ uint32_t u_XA3[8388608];  // bn2(rgb)
__device__ uint32_t u_XB0[4194304];  // bn1(rgb)  B-layout hi only
__device__ uint32_t u_XB1[4194304];  // bn2(flow) B-layout hi only
__device__ uint32_t u_TH[8388608];   // theta A-layout [32][16][64][128] (+4194304 lo)
__device__ uint32_t u_PH[4194304];   // phi   B-layout [32][16][128][64] hi only
__device__ uint32_t u_G [4194304];   // g     B-layout [32][64][32][64] hi only
__device__ uint32_t u_Y [4194304];   // y     B-layout [32][16][128][64] hi only
__device__ uint32_t u_W [524288];    // 8 mats, 65536 each: th/ph B-layout, g/w A-layout
__device__ uint32_t u_P [16777216];  // probs row-major [32][1024][512 u32]
__device__ float    g_S [33554432];  // logits fp32 [32][1024][1024]

__device__ __forceinline__ uint32_t* xbufA(int s) {
    switch (s) { case 0: return u_XA0; case 1: return u_XA1;
                 case 2: return u_XA2; default: return u_XA3; }
}

// ---------------------------------------------------------------------------
// Helpers
// ---------------------------------------------------------------------------
__device__ __forceinline__ uint32_t smem_u32(const void* p) {
    uint32_t a;
    asm("{ .reg .u64 t; cvta.to.shared.u64 t, %1; cvt.u32.u64 %0, t; }" : "=r"(a) : "l"(p));
    return a;
}
__device__ __forceinline__ void cp16(uint32_t dst, const void* src) {
    asm volatile("cp.async.cg.shared.global [%0], [%1], 16;" :: "r"(dst), "l"(src));
}
#define CP_COMMIT() asm volatile("cp.async.commit_group;")
template <int N>
__device__ __forceinline__ void cp_wait() {
    asm volatile("cp.async.wait_group %0;" :: "n"(N));
}

__device__ __forceinline__ uint32_t packh2(float x, float y, uint32_t& lo) {
    __half hx = __float2half_rn(x), hy = __float2half_rn(y);
    __half lx = __float2half_rn(x - __half2float(hx));
    __half ly = __float2half_rn(y - __half2float(hy));
    __half2 H = __halves2half2(hx, hy);
    __half2 L = __halves2half2(lx, ly);
    lo = *reinterpret_cast<uint32_t*>(&L);
    return *reinterpret_cast<uint32_t*>(&H);
}
__device__ __forceinline__ uint32_t packh1(float x, float y) {
    __half2 H = __halves2half2(__float2half_rn(x), __float2half_rn(y));
    return *reinterpret_cast<uint32_t*>(&H);
}

__device__ __forceinline__ void mma16816(float c[4], const uint32_t a[4],
                                         uint32_t b0, uint32_t b1) {
    asm volatile(
        "mma.sync.aligned.m16n8k16.row.col.f32.f16.f16.f32 "
        "{%0,%1,%2,%3}, {%4,%5,%6,%7}, {%8,%9}, {%0,%1,%2,%3};"
        : "+f"(c[0]), "+f"(c[1]), "+f"(c[2]), "+f"(c[3])
        : "r"(a[0]), "r"(a[1]), "r"(a[2]), "r"(a[3]), "r"(b0), "r"(b1));
}

// ---------------------------------------------------------------------------
// BN+ReLU producing fragment-major tiles. Warp handles one 16c x 16n tile.
// ---------------------------------------------------------------------------
__global__ void bnrelu_pack(const float* __restrict__ rgb, const float* __restrict__ flow,
                            const float* __restrict__ g1, const float* __restrict__ b1,
                            const float* __restrict__ m1, const float* __restrict__ v1,
                            const float* __restrict__ g2, const float* __restrict__ b2,
                            const float* __restrict__ m2, const float* __restrict__ v2)
{
    const int z = blockIdx.y;
    const int warp = threadIdx.x >> 5, lane = threadIdx.x & 31;
    const int grp = lane >> 2, tig = lane & 3;
    const int id = blockIdx.x * 8 + warp;
    const int t_k = id & 31, t_n = id >> 5;
    const int n0 = t_n * 16;

    int c[4];
    c[0] = t_k * 16 + 2 * tig; c[1] = c[0] + 1; c[2] = c[0] + 8; c[3] = c[2] + 1;

    float s1[4], h1[4], s2[4], h2[4];
#pragma unroll
    for (int e = 0; e < 4; e++) {
        s1[e] = g1[c[e]] * rsqrtf(v1[c[e]] + 1e-5f);
        h1[e] = b1[c[e]] - m1[c[e]] * s1[e];
        s2[e] = g2[c[e]] * rsqrtf(v2[c[e]] + 1e-5f);
        h2[e] = b2[c[e]] - m2[c[e]] * s2[e];
    }

    float R[2][4], Fv[2][4];
#pragma unroll
    for (int h = 0; h < 2; h++)
#pragma unroll
        for (int e = 0; e < 4; e++) {
            const long long idx = (long long)(z * CCH + c[e]) * NUM + n0 + grp + h * 8;
            R[h][e] = rgb[idx];
            Fv[h][e] = flow[idx];
        }

    auto bnr = [](float x, float s, float h) { return fmaxf(fmaf(x, s, h), 0.f); };
    const long long aoff = (long long)z * 262144 + (t_k * 64 + t_n) * 128 + lane * 4;
    const long long boff = (long long)z * 262144 + (long long)(t_k * 128 + t_n * 2) * 64 + lane * 2;

    float V[2][4];
    auto doStream = [&](const float (*X)[4], const float* sc, const float* sh,
                        uint32_t* bufA, uint32_t* bufB) {
#pragma unroll
        for (int h = 0; h < 2; h++)
#pragma unroll
            for (int e = 0; e < 4; e++) V[h][e] = bnr(X[h][e], sc[e], sh[e]);
        uint32_t L[4];
        uint32_t H0 = packh2(V[0][0], V[0][1], L[0]);
        uint32_t H1 = packh2(V[1][0], V[1][1], L[1]);
        uint32_t H2 = packh2(V[0][2], V[0][3], L[2]);
        uint32_t H3 = packh2(V[1][2], V[1][3], L[3]);
        *reinterpret_cast<uint4*>(bufA + aoff)           = make_uint4(H0, H1, H2, H3);
        *reinterpret_cast<uint4*>(bufA + 4194304 + aoff) = make_uint4(L[0], L[1], L[2], L[3]);
        if (bufB) {
            *reinterpret_cast<uint2*>(bufB + boff)      = make_uint2(H0, H2);
            *reinterpret_cast<uint2*>(bufB + boff + 64) = make_uint2(H1, H3);
        }
    };
    doStream(R,  s1, h1, u_XA0, u_XB0);   // bn1(rgb)
    doStream(Fv, s1, h1, u_XA1, nullptr); // bn1(flow)
    doStream(Fv, s2, h2, u_XA2, u_XB1);   // bn2(flow)
    doStream(R,  s2, h2, u_XA3, nullptr); // bn2(rgb)
}

// ---------------------------------------------------------------------------
// Weight prep: warp per 16x16 tile. mats 0,1,4,5 (th/ph): B-layout.
// mats 2,3,6,7 (g, w): A-layout. w mats are [512,256]; others [256,512].
// ---------------------------------------------------------------------------
__global__ void prep_w_all(const float* w0, const float* w1, const float* w2, const float* w3,
                           const float* w4, const float* w5, const float* w6, const float* w7)
{
    const int mat = blockIdx.y;
    const bool isW = ((mat & 3) == 3);
    const int din  = isW ? 256 : 512;
    const int dout = isW ? 512 : 256;
    const bool Asw = ((mat & 3) >= 2);
    const int warp = threadIdx.x >> 5, lane = threadIdx.x & 31;
    const int grp = lane >> 2, tig = lane & 3;
    const int id = blockIdx.x * 8 + warp;
    const int kT = din >> 4;
    const int t_k = id % kT, t_m = id / kT;

    const float* src;
    switch (mat) {
        case 0: src = w0; break; case 1: src = w1; break;
        case 2: src = w2; break; case 3: src = w3; break;
        case 4: src = w4; break; case 5: src = w5; break;
        case 6: src = w6; break; default: src = w7; break;
    }

    uint32_t u[2][2];
#pragma unroll
    for (int h = 0; h < 2; h++)
#pragma unroll
        for (int q = 0; q < 2; q++) {
            const int row = t_m * 16 + grp + h * 8;
            const int col = t_k * 16 + 2 * tig + 8 * q;
            const float2 f = *reinterpret_cast<const float2*>(src + (long long)row * din + col);
            u[h][q] = packh1(f.x, f.y);
        }
    uint32_t* base = u_W + mat * 65536;
    if (Asw) {
        *reinterpret_cast<uint4*>(base + (t_k * (dout >> 4) + t_m) * 128 + lane * 4) =
            make_uint4(u[0][0], u[1][0], u[0][1], u[1][1]);
    } else {
#pragma unroll
        for (int h = 0; h < 2; h++)
            *reinterpret_cast<uint2*>(base + (t_k * (dout >> 3) + t_m * 2 + h) * 64 + lane * 2) =
                make_uint2(u[h][0], u[h][1]);
    }
}

// ---------------------------------------------------------------------------
// Unified GEMM on fragment-major operands, k32 cp.async stages.
// KIND: 0 thph (NT2), 1 g (NT1), 2 logits (NT2: hh + lh, phi hi-only),
//       3 AV (NT1, TRA from u_P rows), 4 final (NT1, fp32 + BN residual).
// NT1 -> 6-stage pipeline, NT2 -> 4-stage; all 96 KB smem, 2 CTAs/SM.
// ---------------------------------------------------------------------------
template <int KIND>
__global__ __launch_bounds__(256, 2)
void tc_gemm(const float* __restrict__ b0, const float* __restrict__ b1,
             const float* __restrict__ b2, const float* __restrict__ b3,
             const float* __restrict__ i0, const float* __restrict__ i1,
             const float* __restrict__ q0, const float* __restrict__ q1,
             const float* __restrict__ q2, const float* __restrict__ q3,
             const float* __restrict__ q4, const float* __restrict__ q5,
             const float* __restrict__ q6, const float* __restrict__ q7,
             float* outF)
{
    constexpr int  NT   = (KIND == 0 || KIND == 2) ? 2 : 1;
    constexpr bool TRA  = (KIND == 3);
    constexpr int  NPA  = (NT == 2) ? 2 : 1;
    constexpr int  BBu  = NPA * 2048;
    constexpr int  STGU = (NPA + 1) * 2048;
    constexpr int  NSTG = (NT == 2) ? 4 : 6;
    constexpr int  Kc   = (KIND == 0 || KIND == 1) ? 512 : (KIND == 3) ? 1024 : 256;
    constexpr int  MT   = (KIND == 1) ? 16 : (KIND == 4) ? 32 : 64;   // m16 tiles in A
    constexpr int  NT8  = (KIND == 0 || KIND == 3) ? 32 : 128;        // n8 tiles in B

    extern __shared__ uint32_t sm[];
    const uint32_t smb = smem_u32(sm);
    const int tid  = threadIdx.x;
    const int lane = tid & 31;
    const int warp = tid >> 5;
    const int grp  = lane >> 2;
    const int tig  = lane & 3;
    const int wm   = warp & 3;
    const int wn   = warp >> 2;
    const int m0   = blockIdx.y * 128;
    const int n0   = blockIdx.x * 128;
    const int zz   = blockIdx.z;

    const uint32_t *Ah = nullptr, *Al = nullptr, *Bh = nullptr;
    const float* bias = nullptr;
    uint32_t* OU = nullptr;
    float* OF = nullptr;
    int blk = 0, batch = 0, mat = 0;

    if constexpr (KIND == 0) {
        batch = zz & 15; const int sel = zz >> 4; blk = sel >> 1; mat = sel & 1;
        Ah = xbufA(sel) + (long long)batch * 262144;  Al = Ah + 4194304;
        Bh = u_W + (blk * 4 + mat) * 65536;
        bias = (sel == 0) ? b0 : (sel == 1) ? b1 : (sel == 2) ? b2 : b3;
        OU = (mat ? u_PH : u_TH) + (long long)(blk * 16 + batch) * 131072;
    } else if constexpr (KIND == 1) {
        blk = zz >> 4; batch = zz & 15;
        Ah = u_W + (blk * 4 + 2) * 65536;
        Bh = (blk ? u_XB1 : u_XB0) + (long long)batch * 262144;
        bias = blk ? b1 : b0;
        OU = u_G + (long long)zz * 131072;
    } else if constexpr (KIND == 2) {
        Ah = u_TH + (long long)zz * 131072;  Al = Ah + 4194304;
        Bh = u_PH + (long long)zz * 131072;
        OF = g_S + (long long)zz * 1048576;
    } else if constexpr (KIND == 3) {
        Ah = u_P + (long long)zz * 524288;          // row-major probs
        Bh = u_G + (long long)zz * 131072;
        OU = u_Y + (long long)zz * 131072;
    } else {
        blk = zz >> 4; batch = zz & 15;
        Ah = u_W + (blk * 4 + 3) * 65536;
        Bh = u_Y + (long long)zz * 131072;
        bias = blk ? b1 : b0;
        OF = outF + (long long)blk * 8388608 + (long long)batch * 524288;
    }

    const int m0t = m0 >> 4, n0t = n0 >> 3;
    const int ml = tid >> 1, half = tid & 1;

    auto issueAB = [&](int s, int buf) {
        const uint32_t base = smb + buf * STGU * 4;
        if (!TRA) {
#pragma unroll
            for (int p = 0; p < NPA; p++) {
                const uint32_t* src = (p ? Al : Ah);
#pragma unroll
                for (int i = 0; i < 2; i++) {
                    const int c = tid + i * 256;
                    const int kk = c >> 8, inner = c & 255;
                    cp16(base + (p * 2048 + c * 4) * 4,
                         src + (long long)((s * 2 + kk) * MT + m0t) * 128 + inner * 4);
                }
            }
        }
#pragma unroll
        for (int i = 0; i < 2; i++) {
            const int c = tid + i * 256;
            const int kk = c >> 8, inner = c & 255;
            cp16(base + (BBu + c * 4) * 4,
                 Bh + (long long)((s * 2 + kk) * NT8 + n0t) * 64 + inner * 4);
        }
    };

    uint4 pre[2];
    auto ldgA = [&](int s) {       // TRA: u_P rows [m][512 u32]
#pragma unroll
        for (int p = 0; p < 2; p++)
            pre[p] = *reinterpret_cast<const uint4*>(
                Ah + (long long)(m0 + ml) * 512 + s * 16 + half * 4 + p * 8);
    };
    auto stsA = [&](int buf) {     // scatter into fragment-major A stage
        uint32_t* base = sm + buf * STGU;
        const int tml = ml >> 4, l4 = (ml & 7) * 16, rbase = ((ml >> 3) & 1) + half * 2;
#pragma unroll
        for (int p = 0; p < 2; p++) {
            const uint32_t v[4] = {pre[p].x, pre[p].y, pre[p].z, pre[p].w};
#pragma unroll
            for (int jj = 0; jj < 4; jj++)
                base[((p * 8 + tml) << 7) + l4 + jj * 4 + rbase] = v[jj];
        }
    };

    float acc[2][8][4];
#pragma unroll
    for (int i = 0; i < 2; i++)
#pragma unroll
        for (int j = 0; j < 8; j++)
#pragma unroll
            for (int q = 0; q < 4; q++) acc[i][j][q] = 0.f;

    constexpr int S = Kc >> 5;

    if (TRA) {
        ldgA(0);
#pragma unroll
        for (int i = 0; i < NSTG - 1; i++) { issueAB(i, i); CP_COMMIT(); }
        stsA(0); ldgA(1);
    } else {
#pragma unroll
        for (int i = 0; i < NSTG - 1; i++) { issueAB(i, i); CP_COMMIT(); }
    }
    cp_wait<NSTG - 2>();
    __syncthreads();

    int bufC = 0, bufI = NSTG - 1;
    for (int s = 0; s < S; s++) {
        if (s + NSTG - 1 < S) { issueAB(s + NSTG - 1, bufI); CP_COMMIT(); }

        {
            const uint32_t* st = sm + bufC * STGU;
#pragma unroll
            for (int kk = 0; kk < 2; kk++) {
                uint32_t ah[2][4];
#pragma unroll
                for (int i = 0; i < 2; i++) {
                    const uint4 v = *reinterpret_cast<const uint4*>(
                        st + ((kk * 8 + wm * 2 + i) << 7) + (lane << 2));
                    ah[i][0] = v.x; ah[i][1] = v.y; ah[i][2] = v.z; ah[i][3] = v.w;
                }
                uint2 bh[8];
#pragma unroll
                for (int j = 0; j < 8; j++) {          // pass 1: hh
                    bh[j] = *reinterpret_cast<const uint2*>(
                        st + BBu + ((kk * 16 + wn * 8 + j) << 6) + (lane << 1));
                    mma16816(acc[0][j], ah[0], bh[j].x, bh[j].y);
                    mma16816(acc[1][j], ah[1], bh[j].x, bh[j].y);
                }
                if constexpr (NT == 2) {                // pass 2: lh
                    uint32_t al[2][4];
#pragma unroll
                    for (int i = 0; i < 2; i++) {
                        const uint4 v = *reinterpret_cast<const uint4*>(
                            st + 2048 + ((kk * 8 + wm * 2 + i) << 7) + (lane << 2));
                        al[i][0] = v.x; al[i][1] = v.y; al[i][2] = v.z; al[i][3] = v.w;
                    }
#pragma unroll
                    for (int j = 0; j < 8; j++) {
                        mma16816(acc[0][j], al[0], bh[j].x, bh[j].y);
                        mma16816(acc[1][j], al[1], bh[j].x, bh[j].y);
                    }
                }
            }
        }

        if (s + 1 < S) {
            if (TRA) {
                const int bufN = (bufC + 1 == NSTG) ? 0 : bufC + 1;
                stsA(bufN);
                if (s + 2 < S) ldgA(s + 2);
            }
            const int rem = S - s - 2;
            if (rem >= NSTG - 2) cp_wait<NSTG - 2>();
            else if (rem == 3) cp_wait<3>();
            else if (rem == 2) cp_wait<2>();
            else if (rem == 1) cp_wait<1>();
            else cp_wait<0>();
            __syncthreads();
        }
        bufC = (bufC + 1 == NSTG) ? 0 : bufC + 1;
        bufI = (bufI + 1 == NSTG) ? 0 : bufI + 1;
    }

    // ------------------------------ epilogue ------------------------------
    const int tkb = (n0 >> 4) + wn * 4;   // consumer k16 tile base (pair dims)

    if constexpr (KIND == 0) {
        if (mat == 0) {   // theta -> A-layout hi+lo, MT_out = 64
#pragma unroll
            for (int i = 0; i < 2; i++) {
                const int t_m = (m0 + wm * 32 + i * 16) >> 4;
#pragma unroll
                for (int j2 = 0; j2 < 4; j2++) {
                    const int npe = n0 + wn * 64 + j2 * 16 + tig * 2;
                    const float2 bE = *reinterpret_cast<const float2*>(bias + npe);
                    const float2 bO = *reinterpret_cast<const float2*>(bias + npe + 8);
                    uint32_t L0, L1, L2, L3;
                    const uint32_t H0 = packh2(acc[i][2*j2][0]+bE.x, acc[i][2*j2][1]+bE.y, L0);
                    const uint32_t H1 = packh2(acc[i][2*j2][2]+bE.x, acc[i][2*j2][3]+bE.y, L1);
                    const uint32_t H2 = packh2(acc[i][2*j2+1][0]+bO.x, acc[i][2*j2+1][1]+bO.y, L2);
                    const uint32_t H3 = packh2(acc[i][2*j2+1][2]+bO.x, acc[i][2*j2+1][3]+bO.y, L3);
                    const long long off = (long long)((tkb + j2) * 64 + t_m) * 128 + lane * 4;
                    *reinterpret_cast<uint4*>(OU + off)           = make_uint4(H0, H1, H2, H3);
                    *reinterpret_cast<uint4*>(OU + 4194304 + off) = make_uint4(L0, L1, L2, L3);
                }
            }
        } else {          // phi -> B-layout hi only, NT8_out = 128
#pragma unroll
            for (int i = 0; i < 2; i++)
#pragma unroll
                for (int h = 0; h < 2; h++) {
                    const int t_n = (m0 + wm * 32 + i * 16 + h * 8) >> 3;
#pragma unroll
                    for (int j2 = 0; j2 < 4; j2++) {
                        const int npe = n0 + wn * 64 + j2 * 16 + tig * 2;
                        const float2 bE = *reinterpret_cast<const float2*>(bias + npe);
                        const float2 bO = *reinterpret_cast<const float2*>(bias + npe + 8);
                        const uint32_t U0 = packh1(acc[i][2*j2][h*2]+bE.x, acc[i][2*j2][h*2+1]+bE.y);
                        const uint32_t U1 = packh1(acc[i][2*j2+1][h*2]+bO.x, acc[i][2*j2+1][h*2+1]+bO.y);
                        const long long off = (long long)((tkb + j2) * 128 + t_n) * 64 + lane * 2;
                        *reinterpret_cast<uint2*>(OU + off) = make_uint2(U0, U1);
                    }
                }
        }
    } else if constexpr (KIND == 1 || KIND == 3) {
        constexpr int NTOUT = (KIND == 1) ? 32 : 128;   // n8 tiles in out buffer
#pragma unroll
        for (int i = 0; i < 2; i++)
#pragma unroll
            for (int h = 0; h < 2; h++) {
                const int m = m0 + wm * 32 + i * 16 + grp + h * 8;
                const float bm = (KIND == 1) ? bias[m] : 0.f;
                const int t_n = m >> 3;
#pragma unroll
                for (int j2 = 0; j2 < 4; j2++) {
                    const uint32_t U0 = packh1(acc[i][2*j2][h*2] + bm, acc[i][2*j2][h*2+1] + bm);
                    const uint32_t U1 = packh1(acc[i][2*j2+1][h*2] + bm, acc[i][2*j2+1][h*2+1] + bm);
                    const long long off = (long long)((tkb + j2) * NTOUT + t_n) * 64 + lane * 2;
                    *reinterpret_cast<uint2*>(OU + off) = make_uint2(U0, U1);
                }
            }
    } else {
#pragma unroll
        for (int i = 0; i < 2; i++)
#pragma unroll
            for (int h = 0; h < 2; h++) {
                const int m = m0 + wm * 32 + i * 16 + grp + h * 8;
                float bm = 0.f, sc = 0.f, sh = 0.f;
                const float* inp = nullptr;
                if constexpr (KIND == 4) {
                    bm = bias[m];
                    const float* bg  = blk ? q4 : q0;
                    const float* bb  = blk ? q5 : q1;
                    const float* bmn = blk ? q6 : q2;
                    const float* bv  = blk ? q7 : q3;
                    sc = bg[m] * rsqrtf(bv[m] + 1e-5f);
                    sh = bb[m] - bmn[m] * sc;
                    inp = (blk ? i1 : i0) + (long long)batch * 524288 + (long long)m * 1024;
                }
#pragma unroll
                for (int j = 0; j < 8; j++) {
                    const int np = n0 + wn * 64 + j * 8 + tig * 2;
                    const float v0 = acc[i][j][h * 2];
                    const float v1 = acc[i][j][h * 2 + 1];
                    if constexpr (KIND == 2) {
                        *reinterpret_cast<float2*>(OF + (long long)m * 1024 + np) =
                            make_float2(v0, v1);
                    } else {
                        const float2 x = *reinterpret_cast<const float2*>(inp + np);
                        const float r0v = fmaxf(fmaf(x.x, sc, sh), 0.f);
                        const float r1v = fmaxf(fmaf(x.y, sc, sh), 0.f);
                        *reinterpret_cast<float2*>(OF + (long long)m * 1024 + np) =
                            make_float2(v0 + bm + r0v, v1 + bm + r1v);
                    }
                }
            }
    }
}

// ---------------------------------------------------------------------------
// Softmax rows -> u_P fp16-pair rows. 32768 rows x 1024.
// ---------------------------------------------------------------------------
__global__ void softmax_pack()
{
    const long long row = blockIdx.x;
    const float4* s4 = reinterpret_cast<const float4*>(g_S + row * NUM);
    const int t = threadIdx.x;

    const float4 a = s4[t * 2], b = s4[t * 2 + 1];
    float v[8] = {a.x, a.y, a.z, a.w, b.x, b.y, b.z, b.w};

    float mx = v[0];
#pragma unroll
    for (int i = 1; i < 8; i++) mx = fmaxf(mx, v[i]);

    __shared__ float red[128];
    red[t] = mx;
    __syncthreads();
#pragma unroll
    for (int st = 64; st > 0; st >>= 1) {
        if (t < st) red[t] = fmaxf(red[t], red[t + st]);
        __syncthreads();
    }
    mx = red[0];
    __syncthreads();

    float sum = 0.f;
#pragma unroll
    for (int i = 0; i < 8; i++) { v[i] = expf(v[i] - mx); sum += v[i]; }
    red[t] = sum;
    __syncthreads();
#pragma unroll
    for (int st = 64; st > 0; st >>= 1) {
        if (t < st) red[t] += red[t + st];
        __syncthreads();
    }
    const float inv = 1.0f / red[0];

    uint32_t H[4];
#pragma unroll
    for (int q = 0; q < 4; q++)
        H[q] = packh1(v[q * 2] * inv, v[q * 2 + 1] * inv);
    *reinterpret_cast<uint4*>(u_P + row * 512 + t * 4) = make_uint4(H[0], H[1], H[2], H[3]);
}

// ---------------------------------------------------------------------------
// Launcher
// ---------------------------------------------------------------------------
extern "C" void kernel_launch(void* const* d_in, const int* in_sizes, int n_in,
                              void* d_out, int out_size)
{
    cudaFuncSetAttribute(tc_gemm<0>, cudaFuncAttributeMaxDynamicSharedMemorySize, 98304);
    cudaFuncSetAttribute(tc_gemm<1>, cudaFuncAttributeMaxDynamicSharedMemorySize, 98304);
    cudaFuncSetAttribute(tc_gemm<2>, cudaFuncAttributeMaxDynamicSharedMemorySize, 98304);
    cudaFuncSetAttribute(tc_gemm<3>, cudaFuncAttributeMaxDynamicSharedMemorySize, 98304);
    cudaFuncSetAttribute(tc_gemm<4>, cudaFuncAttributeMaxDynamicSharedMemorySize, 98304);

    const float* F = nullptr;

    bnrelu_pack<<<dim3(256, 16), 256>>>(
        (const float*)d_in[0], (const float*)d_in[1],
        (const float*)d_in[2],  (const float*)d_in[3],
        (const float*)d_in[4],  (const float*)d_in[5],
        (const float*)d_in[14], (const float*)d_in[15],
        (const float*)d_in[16], (const float*)d_in[17]);

    prep_w_all<<<dim3(64, 8), 256>>>(
        (const float*)d_in[6],  (const float*)d_in[8],  (const float*)d_in[10], (const float*)d_in[12],
        (const float*)d_in[18], (const float*)d_in[20], (const float*)d_in[22], (const float*)d_in[24]);

    // theta + phi, both blocks (z = 64)
    tc_gemm<0><<<dim3(2, 8, 64), 256, 98304>>>(
        (const float*)d_in[7], (const float*)d_in[9],
        (const float*)d_in[19], (const float*)d_in[21],
        F, F, F, F, F, F, F, F, F, F, nullptr);

    // g projection, both blocks (z = 32)
    tc_gemm<1><<<dim3(8, 2, 32), 256, 98304>>>(
        (const float*)d_in[11], (const float*)d_in[23], F, F,
        F, F, F, F, F, F, F, F, F, F, nullptr);

    // logits (z = 32)
    tc_gemm<2><<<dim3(8, 8, 32), 256, 98304>>>(
        F, F, F, F, F, F, F, F, F, F, F, F, F, F, nullptr);

    softmax_pack<<<32768, 128>>>();

    // AV (z = 32)
    tc_gemm<3><<<dim3(2, 8, 32), 256, 98304>>>(
        F, F, F, F, F, F, F, F, F, F, F, F, F, F, nullptr);

    // final (z = 32)
    tc_gemm<4><<<dim3(8, 4, 32), 256, 98304>>>(
        (const float*)d_in[13], (const float*)d_in[25], F, F,
        (const float*)d_in[0],  (const float*)d_in[1],
        (const float*)d_in[2],  (const float*)d_in[3],
        (const float*)d_in[4],  (const float*)d_in[5],
        (const float*)d_in[14], (const float*)d_in[15],
        (const float*)d_in[16], (const float*)d_in[17],
        (float*)d_out);
}

// round 11
// speedup vs baseline: 5.4234x; 1.2036x over previous
#include <cuda_runtime.h>
#include <cuda_fp16.h>
#include <cstdint>

#define BATCH 16
#define CCH   512
#define CIN   256
#define NUM   1024

// ---------------------------------------------------------------------------
// Fragment-major global buffers (u32 = fp16 k-pair), all hi-precision only.
// A-layout: [k16][m16][128]  lane l owns u32 l*4+{0..3} = {a0,a1,a2,a3}
// B-layout: [k16][n8][64]    lane l owns u32 l*2+{0,1}  = {b0,b1}
// ---------------------------------------------------------------------------
__device__ uint32_t u_XA0[4194304];  // bn1(rgb)  A-layout [16][32][64][128]
__device__ uint32_t u_XA1[4194304];  // bn1(flow)
__device__ uint32_t u_XA2[4194304];  // bn2(flow)
__device__ uint32_t u_XA3[4194304];  // bn2(rgb)
__device__ uint32_t u_XB0[4194304];  // bn1(rgb)  B-layout
__device__ uint32_t u_XB1[4194304];  // bn2(flow) B-layout
__device__ uint32_t u_TH[4194304];   // theta A-layout [32][16][64][128]
__device__ uint32_t u_PH[4194304];   // phi   B-layout [32][16][128][64]
__device__ uint32_t u_G [4194304];   // g     B-layout [32][64][32][64]
__device__ uint32_t u_Y [4194304];   // y     B-layout [32][16][128][64]
__device__ uint32_t u_W [524288];    // 8 mats, 65536 each: th/ph B-layout, g/w A-layout
__device__ uint32_t u_P [16777216];  // probs row-major [32][1024][512 u32]
__device__ float    g_S [33554432];  // logits fp32 [32][1024][1024]

__device__ __forceinline__ uint32_t* xbufA(int s) {
    switch (s) { case 0: return u_XA0; case 1: return u_XA1;
                 case 2: return u_XA2; default: return u_XA3; }
}

// ---------------------------------------------------------------------------
// Helpers
// ---------------------------------------------------------------------------
__device__ __forceinline__ uint32_t smem_u32(const void* p) {
    uint32_t a;
    asm("{ .reg .u64 t; cvta.to.shared.u64 t, %1; cvt.u32.u64 %0, t; }" : "=r"(a) : "l"(p));
    return a;
}
__device__ __forceinline__ void cp16(uint32_t dst, const void* src) {
    asm volatile("cp.async.cg.shared.global [%0], [%1], 16;" :: "r"(dst), "l"(src));
}
#define CP_COMMIT() asm volatile("cp.async.commit_group;")
template <int N>
__device__ __forceinline__ void cp_wait() {
    asm volatile("cp.async.wait_group %0;" :: "n"(N));
}

__device__ __forceinline__ uint32_t packh1(float x, float y) {
    __half2 H = __halves2half2(__float2half_rn(x), __float2half_rn(y));
    return *reinterpret_cast<uint32_t*>(&H);
}

__device__ __forceinline__ void mma16816(float c[4], const uint32_t a[4],
                                         uint32_t b0, uint32_t b1) {
    asm volatile(
        "mma.sync.aligned.m16n8k16.row.col.f32.f16.f16.f32 "
        "{%0,%1,%2,%3}, {%4,%5,%6,%7}, {%8,%9}, {%0,%1,%2,%3};"
        : "+f"(c[0]), "+f"(c[1]), "+f"(c[2]), "+f"(c[3])
        : "r"(a[0]), "r"(a[1]), "r"(a[2]), "r"(a[3]), "r"(b0), "r"(b1));
}

// ---------------------------------------------------------------------------
// BN+ReLU producing fragment-major hi tiles. Warp per 16c x 16n tile.
// ---------------------------------------------------------------------------
__global__ void bnrelu_pack(const float* __restrict__ rgb, const float* __restrict__ flow,
                            const float* __restrict__ g1, const float* __restrict__ b1,
                            const float* __restrict__ m1, const float* __restrict__ v1,
                            const float* __restrict__ g2, const float* __restrict__ b2,
                            const float* __restrict__ m2, const float* __restrict__ v2)
{
    const int z = blockIdx.y;
    const int warp = threadIdx.x >> 5, lane = threadIdx.x & 31;
    const int grp = lane >> 2, tig = lane & 3;
    const int id = blockIdx.x * 8 + warp;
    const int t_k = id & 31, t_n = id >> 5;
    const int n0 = t_n * 16;

    int c[4];
    c[0] = t_k * 16 + 2 * tig; c[1] = c[0] + 1; c[2] = c[0] + 8; c[3] = c[2] + 1;

    float s1[4], h1[4], s2[4], h2[4];
#pragma unroll
    for (int e = 0; e < 4; e++) {
        s1[e] = g1[c[e]] * rsqrtf(v1[c[e]] + 1e-5f);
        h1[e] = b1[c[e]] - m1[c[e]] * s1[e];
        s2[e] = g2[c[e]] * rsqrtf(v2[c[e]] + 1e-5f);
        h2[e] = b2[c[e]] - m2[c[e]] * s2[e];
    }

    float R[2][4], Fv[2][4];
#pragma unroll
    for (int h = 0; h < 2; h++)
#pragma unroll
        for (int e = 0; e < 4; e++) {
            const long long idx = (long long)(z * CCH + c[e]) * NUM + n0 + grp + h * 8;
            R[h][e] = rgb[idx];
            Fv[h][e] = flow[idx];
        }

    auto bnr = [](float x, float s, float h) { return fmaxf(fmaf(x, s, h), 0.f); };
    const long long aoff = (long long)z * 262144 + (t_k * 64 + t_n) * 128 + lane * 4;
    const long long boff = (long long)z * 262144 + (long long)(t_k * 128 + t_n * 2) * 64 + lane * 2;

    float V[2][4];
    auto doStream = [&](const float (*X)[4], const float* sc, const float* sh,
                        uint32_t* bufA, uint32_t* bufB) {
#pragma unroll
        for (int h = 0; h < 2; h++)
#pragma unroll
            for (int e = 0; e < 4; e++) V[h][e] = bnr(X[h][e], sc[e], sh[e]);
        const uint32_t H0 = packh1(V[0][0], V[0][1]);
        const uint32_t H1 = packh1(V[1][0], V[1][1]);
        const uint32_t H2 = packh1(V[0][2], V[0][3]);
        const uint32_t H3 = packh1(V[1][2], V[1][3]);
        *reinterpret_cast<uint4*>(bufA + aoff) = make_uint4(H0, H1, H2, H3);
        if (bufB) {
            *reinterpret_cast<uint2*>(bufB + boff)      = make_uint2(H0, H2);
            *reinterpret_cast<uint2*>(bufB + boff + 64) = make_uint2(H1, H3);
        }
    };
    doStream(R,  s1, h1, u_XA0, u_XB0);   // bn1(rgb)
    doStream(Fv, s1, h1, u_XA1, nullptr); // bn1(flow)
    doStream(Fv, s2, h2, u_XA2, u_XB1);   // bn2(flow)
    doStream(R,  s2, h2, u_XA3, nullptr); // bn2(rgb)
}

// ---------------------------------------------------------------------------
// Weight prep: warp per 16x16 tile. mats 0,1,4,5 (th/ph): B-layout.
// mats 2,3,6,7 (g, w): A-layout. w mats are [512,256]; others [256,512].
// ---------------------------------------------------------------------------
__global__ void prep_w_all(const float* w0, const float* w1, const float* w2, const float* w3,
                           const float* w4, const float* w5, const float* w6, const float* w7)
{
    const int mat = blockIdx.y;
    const bool isW = ((mat & 3) == 3);
    const int din  = isW ? 256 : 512;
    const int dout = isW ? 512 : 256;
    const bool Asw = ((mat & 3) >= 2);
    const int warp = threadIdx.x >> 5, lane = threadIdx.x & 31;
    const int grp = lane >> 2, tig = lane & 3;
    const int id = blockIdx.x * 8 + warp;
    const int kT = din >> 4;
    const int t_k = id % kT, t_m = id / kT;

    const float* src;
    switch (mat) {
        case 0: src = w0; break; case 1: src = w1; break;
        case 2: src = w2; break; case 3: src = w3; break;
        case 4: src = w4; break; case 5: src = w5; break;
        case 6: src = w6; break; default: src = w7; break;
    }

    uint32_t u[2][2];
#pragma unroll
    for (int h = 0; h < 2; h++)
#pragma unroll
        for (int q = 0; q < 2; q++) {
            const int row = t_m * 16 + grp + h * 8;
            const int col = t_k * 16 + 2 * tig + 8 * q;
            const float2 f = *reinterpret_cast<const float2*>(src + (long long)row * din + col);
            u[h][q] = packh1(f.x, f.y);
        }
    uint32_t* base = u_W + mat * 65536;
    if (Asw) {
        *reinterpret_cast<uint4*>(base + (t_k * (dout >> 4) + t_m) * 128 + lane * 4) =
            make_uint4(u[0][0], u[1][0], u[0][1], u[1][1]);
    } else {
#pragma unroll
        for (int h = 0; h < 2; h++)
            *reinterpret_cast<uint2*>(base + (t_k * (dout >> 3) + t_m * 2 + h) * 64 + lane * 2) =
                make_uint2(u[h][0], u[h][1]);
    }
}

// ---------------------------------------------------------------------------
// Unified 1-term GEMM on fragment-major operands, k32 cp.async stages,
// 6-stage x 16 KB pipeline (96 KB smem, 2 CTAs/SM).
// KIND: 0 thph, 1 g, 2 logits, 3 AV (TRA from u_P rows), 4 final (fp32 out
//       + bias + recomputed BN residual).
// ---------------------------------------------------------------------------
template <int KIND>
__global__ __launch_bounds__(256, 2)
void tc_gemm(const float* __restrict__ b0, const float* __restrict__ b1,
             const float* __restrict__ b2, const float* __restrict__ b3,
             const float* __restrict__ i0, const float* __restrict__ i1,
             const float* __restrict__ q0, const float* __restrict__ q1,
             const float* __restrict__ q2, const float* __restrict__ q3,
             const float* __restrict__ q4, const float* __restrict__ q5,
             const float* __restrict__ q6, const float* __restrict__ q7,
             float* outF)
{
    constexpr bool TRA  = (KIND == 3);
    constexpr int  BBu  = 2048;
    constexpr int  STGU = 4096;
    constexpr int  NSTG = 6;
    constexpr int  Kc   = (KIND == 0 || KIND == 1) ? 512 : (KIND == 3) ? 1024 : 256;
    constexpr int  MT   = (KIND == 1) ? 16 : (KIND == 4) ? 32 : 64;   // m16 tiles in A
    constexpr int  NT8  = (KIND == 0 || KIND == 3) ? 32 : 128;        // n8 tiles in B

    extern __shared__ uint32_t sm[];
    const uint32_t smb = smem_u32(sm);
    const int tid  = threadIdx.x;
    const int lane = tid & 31;
    const int warp = tid >> 5;
    const int grp  = lane >> 2;
    const int tig  = lane & 3;
    const int wm   = warp & 3;
    const int wn   = warp >> 2;
    const int m0   = blockIdx.y * 128;
    const int n0   = blockIdx.x * 128;
    const int zz   = blockIdx.z;

    const uint32_t *Ah = nullptr, *Bh = nullptr;
    const float* bias = nullptr;
    uint32_t* OU = nullptr;
    float* OF = nullptr;
    int blk = 0, batch = 0, mat = 0;

    if constexpr (KIND == 0) {
        batch = zz & 15; const int sel = zz >> 4; blk = sel >> 1; mat = sel & 1;
        Ah = xbufA(sel) + (long long)batch * 262144;
        Bh = u_W + (blk * 4 + mat) * 65536;
        bias = (sel == 0) ? b0 : (sel == 1) ? b1 : (sel == 2) ? b2 : b3;
        OU = (mat ? u_PH : u_TH) + (long long)(blk * 16 + batch) * 131072;
    } else if constexpr (KIND == 1) {
        blk = zz >> 4; batch = zz & 15;
        Ah = u_W + (blk * 4 + 2) * 65536;
        Bh = (blk ? u_XB1 : u_XB0) + (long long)batch * 262144;
        bias = blk ? b1 : b0;
        OU = u_G + (long long)zz * 131072;
    } else if constexpr (KIND == 2) {
        Ah = u_TH + (long long)zz * 131072;
        Bh = u_PH + (long long)zz * 131072;
        OF = g_S + (long long)zz * 1048576;
    } else if constexpr (KIND == 3) {
        Ah = u_P + (long long)zz * 524288;          // row-major probs
        Bh = u_G + (long long)zz * 131072;
        OU = u_Y + (long long)zz * 131072;
    } else {
        blk = zz >> 4; batch = zz & 15;
        Ah = u_W + (blk * 4 + 3) * 65536;
        Bh = u_Y + (long long)zz * 131072;
        bias = blk ? b1 : b0;
        OF = outF + (long long)blk * 8388608 + (long long)batch * 524288;
    }

    const int m0t = m0 >> 4, n0t = n0 >> 3;
    const int ml = tid >> 1, half = tid & 1;

    auto issueAB = [&](int s, int buf) {
        const uint32_t base = smb + buf * STGU * 4;
        if (!TRA) {
#pragma unroll
            for (int i = 0; i < 2; i++) {
                const int c = tid + i * 256;
                const int kk = c >> 8, inner = c & 255;
                cp16(base + (c * 4) * 4,
                     Ah + (long long)((s * 2 + kk) * MT + m0t) * 128 + inner * 4);
            }
        }
#pragma unroll
        for (int i = 0; i < 2; i++) {
            const int c = tid + i * 256;
            const int kk = c >> 8, inner = c & 255;
            cp16(base + ((BBu + c * 4)) * 4,
                 Bh + (long long)((s * 2 + kk) * NT8 + n0t) * 64 + inner * 4);
        }
    };

    uint4 pre[2];
    auto ldgA = [&](int s) {       // TRA: u_P rows [m][512 u32]
#pragma unroll
        for (int p = 0; p < 2; p++)
            pre[p] = *reinterpret_cast<const uint4*>(
                Ah + (long long)(m0 + ml) * 512 + s * 16 + half * 4 + p * 8);
    };
    auto stsA = [&](int buf) {     // scatter into fragment-major A stage
        uint32_t* base = sm + buf * STGU;
        const int tml = ml >> 4, l4 = (ml & 7) * 16, rbase = ((ml >> 3) & 1) + half * 2;
#pragma unroll
        for (int p = 0; p < 2; p++) {
            const uint32_t v[4] = {pre[p].x, pre[p].y, pre[p].z, pre[p].w};
#pragma unroll
            for (int jj = 0; jj < 4; jj++)
                base[((p * 8 + tml) << 7) + l4 + jj * 4 + rbase] = v[jj];
        }
    };

    float acc[2][8][4];
#pragma unroll
    for (int i = 0; i < 2; i++)
#pragma unroll
        for (int j = 0; j < 8; j++)
#pragma unroll
            for (int q = 0; q < 4; q++) acc[i][j][q] = 0.f;

    constexpr int S = Kc >> 5;

    if (TRA) {
        ldgA(0);
#pragma unroll
        for (int i = 0; i < NSTG - 1; i++) { issueAB(i, i); CP_COMMIT(); }
        stsA(0); ldgA(1);
    } else {
#pragma unroll
        for (int i = 0; i < NSTG - 1; i++) { issueAB(i, i); CP_COMMIT(); }
    }
    cp_wait<NSTG - 2>();
    __syncthreads();

    int bufC = 0, bufI = NSTG - 1;
    for (int s = 0; s < S; s++) {
        if (s + NSTG - 1 < S) { issueAB(s + NSTG - 1, bufI); CP_COMMIT(); }

        {
            const uint32_t* st = sm + bufC * STGU;
#pragma unroll
            for (int kk = 0; kk < 2; kk++) {
                uint32_t ah[2][4];
#pragma unroll
                for (int i = 0; i < 2; i++) {
                    const uint4 v = *reinterpret_cast<const uint4*>(
                        st + ((kk * 8 + wm * 2 + i) << 7) + (lane << 2));
                    ah[i][0] = v.x; ah[i][1] = v.y; ah[i][2] = v.z; ah[i][3] = v.w;
                }
#pragma unroll
                for (int j = 0; j < 8; j++) {
                    const uint2 bh = *reinterpret_cast<const uint2*>(
                        st + BBu + ((kk * 16 + wn * 8 + j) << 6) + (lane << 1));
                    mma16816(acc[0][j], ah[0], bh.x, bh.y);
                    mma16816(acc[1][j], ah[1], bh.x, bh.y);
                }
            }
        }

        if (s + 1 < S) {
            if (TRA) {
                const int bufN = (bufC + 1 == NSTG) ? 0 : bufC + 1;
                stsA(bufN);
                if (s + 2 < S) ldgA(s + 2);
            }
            const int rem = S - s - 2;
            if (rem >= NSTG - 2) cp_wait<NSTG - 2>();
            else if (rem == 3) cp_wait<3>();
            else if (rem == 2) cp_wait<2>();
            else if (rem == 1) cp_wait<1>();
            else cp_wait<0>();
            __syncthreads();
        }
        bufC = (bufC + 1 == NSTG) ? 0 : bufC + 1;
        bufI = (bufI + 1 == NSTG) ? 0 : bufI + 1;
    }

    // ------------------------------ epilogue ------------------------------
    const int tkb = (n0 >> 4) + wn * 4;   // consumer k16 tile base (pair dims)

    if constexpr (KIND == 0) {
        if (mat == 0) {   // theta -> A-layout hi, MT_out = 64
#pragma unroll
            for (int i = 0; i < 2; i++) {
                const int t_m = (m0 + wm * 32 + i * 16) >> 4;
#pragma unroll
                for (int j2 = 0; j2 < 4; j2++) {
                    const int npe = n0 + wn * 64 + j2 * 16 + tig * 2;
                    const float2 bE = *reinterpret_cast<const float2*>(bias + npe);
                    const float2 bO = *reinterpret_cast<const float2*>(bias + npe + 8);
                    const uint32_t H0 = packh1(acc[i][2*j2][0]+bE.x, acc[i][2*j2][1]+bE.y);
                    const uint32_t H1 = packh1(acc[i][2*j2][2]+bE.x, acc[i][2*j2][3]+bE.y);
                    const uint32_t H2 = packh1(acc[i][2*j2+1][0]+bO.x, acc[i][2*j2+1][1]+bO.y);
                    const uint32_t H3 = packh1(acc[i][2*j2+1][2]+bO.x, acc[i][2*j2+1][3]+bO.y);
                    const long long off = (long long)((tkb + j2) * 64 + t_m) * 128 + lane * 4;
                    *reinterpret_cast<uint4*>(OU + off) = make_uint4(H0, H1, H2, H3);
                }
            }
        } else {          // phi -> B-layout hi, NT8_out = 128
#pragma unroll
            for (int i = 0; i < 2; i++)
#pragma unroll
                for (int h = 0; h < 2; h++) {
                    const int t_n = (m0 + wm * 32 + i * 16 + h * 8) >> 3;
#pragma unroll
                    for (int j2 = 0; j2 < 4; j2++) {
                        const int npe = n0 + wn * 64 + j2 * 16 + tig * 2;
                        const float2 bE = *reinterpret_cast<const float2*>(bias + npe);
                        const float2 bO = *reinterpret_cast<const float2*>(bias + npe + 8);
                        const uint32_t U0 = packh1(acc[i][2*j2][h*2]+bE.x, acc[i][2*j2][h*2+1]+bE.y);
                        const uint32_t U1 = packh1(acc[i][2*j2+1][h*2]+bO.x, acc[i][2*j2+1][h*2+1]+bO.y);
                        const long long off = (long long)((tkb + j2) * 128 + t_n) * 64 + lane * 2;
                        *reinterpret_cast<uint2*>(OU + off) = make_uint2(U0, U1);
                    }
                }
        }
    } else if constexpr (KIND == 1 || KIND == 3) {
        constexpr int NTOUT = (KIND == 1) ? 32 : 128;   // n8 tiles in out buffer
#pragma unroll
        for (int i = 0; i < 2; i++)
#pragma unroll
            for (int h = 0; h < 2; h++) {
                const int m = m0 + wm * 32 + i * 16 + grp + h * 8;
                const float bm = (KIND == 1) ? bias[m] : 0.f;
                const int t_n = m >> 3;
#pragma unroll
                for (int j2 = 0; j2 < 4; j2++) {
                    const uint32_t U0 = packh1(acc[i][2*j2][h*2] + bm, acc[i][2*j2][h*2+1] + bm);
                    const uint32_t U1 = packh1(acc[i][2*j2+1][h*2] + bm, acc[i][2*j2+1][h*2+1] + bm);
                    const long long off = (long long)((tkb + j2) * NTOUT + t_n) * 64 + lane * 2;
                    *reinterpret_cast<uint2*>(OU + off) = make_uint2(U0, U1);
                }
            }
    } else {
#pragma unroll
        for (int i = 0; i < 2; i++)
#pragma unroll
            for (int h = 0; h < 2; h++) {
                const int m = m0 + wm * 32 + i * 16 + grp + h * 8;
                float bm = 0.f, sc = 0.f, sh = 0.f;
                const float* inp = nullptr;
                if constexpr (KIND == 4) {
                    bm = bias[m];
                    const float* bg  = blk ? q4 : q0;
                    const float* bb  = blk ? q5 : q1;
                    const float* bmn = blk ? q6 : q2;
                    const float* bv  = blk ? q7 : q3;
                    sc = bg[m] * rsqrtf(bv[m] + 1e-5f);
                    sh = bb[m] - bmn[m] * sc;
                    inp = (blk ? i1 : i0) + (long long)batch * 524288 + (long long)m * 1024;
                }
#pragma unroll
                for (int j = 0; j < 8; j++) {
                    const int np = n0 + wn * 64 + j * 8 + tig * 2;
                    const float v0 = acc[i][j][h * 2];
                    const float v1 = acc[i][j][h * 2 + 1];
                    if constexpr (KIND == 2) {
                        *reinterpret_cast<float2*>(OF + (long long)m * 1024 + np) =
                            make_float2(v0, v1);
                    } else {
                        const float2 x = *reinterpret_cast<const float2*>(inp + np);
                        const float r0v = fmaxf(fmaf(x.x, sc, sh), 0.f);
                        const float r1v = fmaxf(fmaf(x.y, sc, sh), 0.f);
                        *reinterpret_cast<float2*>(OF + (long long)m * 1024 + np) =
                            make_float2(v0 + bm + r0v, v1 + bm + r1v);
                    }
                }
            }
    }
}

// ---------------------------------------------------------------------------
// Softmax rows -> u_P fp16-pair rows. 32768 rows x 1024.
// ---------------------------------------------------------------------------
__global__ void softmax_pack()
{
    const long long row = blockIdx.x;
    const float4* s4 = reinterpret_cast<const float4*>(g_S + row * NUM);
    const int t = threadIdx.x;

    const float4 a = s4[t * 2], b = s4[t * 2 + 1];
    float v[8] = {a.x, a.y, a.z, a.w, b.x, b.y, b.z, b.w};

    float mx = v[0];
#pragma unroll
    for (int i = 1; i < 8; i++) mx = fmaxf(mx, v[i]);

    __shared__ float red[128];
    red[t] = mx;
    __syncthreads();
#pragma unroll
    for (int st = 64; st > 0; st >>= 1) {
        if (t < st) red[t] = fmaxf(red[t], red[t + st]);
        __syncthreads();
    }
    mx = red[0];
    __syncthreads();

    float sum = 0.f;
#pragma unroll
    for (int i = 0; i < 8; i++) { v[i] = expf(v[i] - mx); sum += v[i]; }
    red[t] = sum;
    __syncthreads();
#pragma unroll
    for (int st = 64; st > 0; st >>= 1) {
        if (t < st) red[t] += red[t + st];
        __syncthreads();
    }
    const float inv = 1.0f / red[0];

    uint32_t H[4];
#pragma unroll
    for (int q = 0; q < 4; q++)
        H[q] = packh1(v[q * 2] * inv, v[q * 2 + 1] * inv);
    *reinterpret_cast<uint4*>(u_P + row * 512 + t * 4) = make_uint4(H[0], H[1], H[2], H[3]);
}

// ---------------------------------------------------------------------------
// Launcher
// ---------------------------------------------------------------------------
extern "C" void kernel_launch(void* const* d_in, const int* in_sizes, int n_in,
                              void* d_out, int out_size)
{
    cudaFuncSetAttribute(tc_gemm<0>, cudaFuncAttributeMaxDynamicSharedMemorySize, 98304);
    cudaFuncSetAttribute(tc_gemm<1>, cudaFuncAttributeMaxDynamicSharedMemorySize, 98304);
    cudaFuncSetAttribute(tc_gemm<2>, cudaFuncAttributeMaxDynamicSharedMemorySize, 98304);
    cudaFuncSetAttribute(tc_gemm<3>, cudaFuncAttributeMaxDynamicSharedMemorySize, 98304);
    cudaFuncSetAttribute(tc_gemm<4>, cudaFuncAttributeMaxDynamicSharedMemorySize, 98304);

    const float* F = nullptr;

    bnrelu_pack<<<dim3(256, 16), 256>>>(
        (const float*)d_in[0], (const float*)d_in[1],
        (const float*)d_in[2],  (const float*)d_in[3],
        (const float*)d_in[4],  (const float*)d_in[5],
        (const float*)d_in[14], (const float*)d_in[15],
        (const float*)d_in[16], (const float*)d_in[17]);

    prep_w_all<<<dim3(64, 8), 256>>>(
        (const float*)d_in[6],  (const float*)d_in[8],  (const float*)d_in[10], (const float*)d_in[12],
        (const float*)d_in[18], (const float*)d_in[20], (const float*)d_in[22], (const float*)d_in[24]);

    // theta + phi, both blocks (z = 64)
    tc_gemm<0><<<dim3(2, 8, 64), 256, 98304>>>(
        (const float*)d_in[7], (const float*)d_in[9],
        (const float*)d_in[19], (const float*)d_in[21],
        F, F, F, F, F, F, F, F, F, F, nullptr);

    // g projection, both blocks (z = 32)
    tc_gemm<1><<<dim3(8, 2, 32), 256, 98304>>>(
        (const float*)d_in[11], (const float*)d_in[23], F, F,
        F, F, F, F, F, F, F, F, F, F, nullptr);

    // logits (z = 32)
    tc_gemm<2><<<dim3(8, 8, 32), 256, 98304>>>(
        F, F, F, F, F, F, F, F, F, F, F, F, F, F, nullptr);

    softmax_pack<<<32768, 128>>>();

    // AV (z = 32)
    tc_gemm<3><<<dim3(2, 8, 32), 256, 98304>>>(
        F, F, F, F, F, F, F, F, F, F, F, F, F, F, nullptr);

    // final (z = 32)
    tc_gemm<4><<<dim3(8, 4, 32), 256, 98304>>>(
        (const float*)d_in[13], (const float*)d_in[25], F, F,
        (const float*)d_in[0],  (const float*)d_in[1],
        (const float*)d_in[2],  (const float*)d_in[3],
        (const float*)d_in[4],  (const float*)d_in[5],
        (const float*)d_in[14], (const float*)d_in[15],
        (const float*)d_in[16], (const float*)d_in[17],
        (float*)d_out);
}